// round 1
// baseline (speedup 1.0000x reference)
#include <cuda_runtime.h>
#include <cstdint>

// Problem constants
#define B 32
#define A 64
#define SLEN 256
#define H 128
#define RLEN 64
#define E 16

// Scratch (device globals — no allocation allowed)
__device__ float g_s1[B * A * H];        // state-encoder output
__device__ float g_pooled[B * A * 2 * H]; // [avr(128) | max(128)]
__device__ float g_ragent[B * A * 2 * H]; // r rows at i == agent_id
__device__ float g_s2[B * A * H];        // post-ra state
__device__ float g_ae[B * A * 2 * H];    // ae rows at i == agent_id

// ---------------------------------------------------------------------------
// Kernel 1: s1 = relu(relu(states @ se_w1 + b1) @ se_w2 + b2)
// 2048 rows of K=256 -> 128 -> 128. 8 rows per block, 128 threads.
// ---------------------------------------------------------------------------
__global__ __launch_bounds__(128) void k_state_enc(
    const float* __restrict__ states,
    const float* __restrict__ w1, const float* __restrict__ b1,
    const float* __restrict__ w2, const float* __restrict__ b2)
{
    __shared__ float X[8 * SLEN];
    __shared__ float HID[8 * H];
    const int row0 = blockIdx.x * 8;
    const int t = threadIdx.x;

    // load 8 input rows
    for (int idx = t; idx < 8 * SLEN; idx += 128)
        X[idx] = states[(size_t)row0 * SLEN + idx];
    __syncthreads();

    const int h = t;
    float acc[8];
    {
        const float bb = b1[h];
#pragma unroll
        for (int jj = 0; jj < 8; jj++) acc[jj] = bb;
        const float4* X4 = reinterpret_cast<const float4*>(X);
        for (int k = 0; k < SLEN; k += 4) {
            const float w0 = w1[(k + 0) * H + h];
            const float wA = w1[(k + 1) * H + h];
            const float wB = w1[(k + 2) * H + h];
            const float wC = w1[(k + 3) * H + h];
#pragma unroll
            for (int jj = 0; jj < 8; jj++) {
                float4 x = X4[jj * (SLEN / 4) + (k >> 2)];
                acc[jj] = fmaf(x.x, w0, acc[jj]);
                acc[jj] = fmaf(x.y, wA, acc[jj]);
                acc[jj] = fmaf(x.z, wB, acc[jj]);
                acc[jj] = fmaf(x.w, wC, acc[jj]);
            }
        }
#pragma unroll
        for (int jj = 0; jj < 8; jj++) HID[jj * H + h] = fmaxf(acc[jj], 0.f);
    }
    __syncthreads();
    {
        const float bb = b2[h];
#pragma unroll
        for (int jj = 0; jj < 8; jj++) acc[jj] = bb;
        const float4* H4 = reinterpret_cast<const float4*>(HID);
        for (int k = 0; k < H; k += 4) {
            const float w0 = w2[(k + 0) * H + h];
            const float wA = w2[(k + 1) * H + h];
            const float wB = w2[(k + 2) * H + h];
            const float wC = w2[(k + 3) * H + h];
#pragma unroll
            for (int jj = 0; jj < 8; jj++) {
                float4 x = H4[jj * (H / 4) + (k >> 2)];
                acc[jj] = fmaf(x.x, w0, acc[jj]);
                acc[jj] = fmaf(x.y, wA, acc[jj]);
                acc[jj] = fmaf(x.z, wB, acc[jj]);
                acc[jj] = fmaf(x.w, wC, acc[jj]);
            }
        }
#pragma unroll
        for (int jj = 0; jj < 8; jj++)
            g_s1[(size_t)(row0 + jj) * H + h] = fmaxf(acc[jj], 0.f);
    }
}

// ---------------------------------------------------------------------------
// Kernel 2 (dominant): fused relation MLP + masked mean/max pooling.
// One block per (b, i). 256 threads. For all j in [0,64):
//   rel_in[j] = [relations[b,i,j,:64] | s1[b,j,:128]]  (K=192)
//   hid = relu(rel_in @ re_w1 + b1)                    (128)
//   out = relu(hid @ re_w2 + b2)                       (256)
// pooled[b,i,c]      = mean_j(out[j,c] * alive[b,j])        c < 128
// pooled[b,i,128+c]  = max_j (out[j,128+c] * alive[b,j])
// if i == agent_id: g_ragent[b,j,:] = out[j,:]
// ---------------------------------------------------------------------------
#define K1 (RLEN + H)   // 192
__global__ __launch_bounds__(256, 2) void k_rel(
    const float* __restrict__ rel,
    const float* __restrict__ alive,
    const float* __restrict__ w1, const float* __restrict__ b1,
    const float* __restrict__ w2, const float* __restrict__ b2,
    const int* __restrict__ agent_id_p)
{
    extern __shared__ float sm[];
    float* X = sm;                 // 64 x 192
    float* HID = sm + 64 * K1;     // 64 x 128
    const int bi = blockIdx.x;
    const int b = bi >> 6;
    const int i = bi & 63;
    const int t = threadIdx.x;

    // fill X: relations part
    const float* relrow = rel + (size_t)bi * (A * RLEN);
    for (int idx = t; idx < A * RLEN; idx += 256) {
        const int j = idx >> 6, k = idx & 63;
        X[j * K1 + k] = relrow[idx];
    }
    // fill X: broadcast s1[b, j]
    const float* srow = g_s1 + (size_t)b * (A * H);
    for (int idx = t; idx < A * H; idx += 256) {
        const int j = idx >> 7, h = idx & 127;
        X[j * K1 + RLEN + h] = srow[idx];
    }
    __syncthreads();

    // ----- layer 1: 256 threads = (h in [0,128)) x (j-half in {0,1}) -----
    {
        const int h = t & 127;
        const int j0 = (t >> 7) * 32;
        float acc[32];
        const float bb = b1[h];
#pragma unroll
        for (int jj = 0; jj < 32; jj++) acc[jj] = bb;
        const float4* X4 = reinterpret_cast<const float4*>(X);
        for (int k = 0; k < K1; k += 4) {
            const float w0 = w1[(k + 0) * H + h];
            const float wA = w1[(k + 1) * H + h];
            const float wB = w1[(k + 2) * H + h];
            const float wC = w1[(k + 3) * H + h];
#pragma unroll
            for (int jj = 0; jj < 32; jj++) {
                float4 x = X4[(j0 + jj) * (K1 / 4) + (k >> 2)];
                acc[jj] = fmaf(x.x, w0, acc[jj]);
                acc[jj] = fmaf(x.y, wA, acc[jj]);
                acc[jj] = fmaf(x.z, wB, acc[jj]);
                acc[jj] = fmaf(x.w, wC, acc[jj]);
            }
        }
#pragma unroll
        for (int jj = 0; jj < 32; jj++)
            HID[(j0 + jj) * H + h] = fmaxf(acc[jj], 0.f);
    }
    __syncthreads();

    // ----- layer 2: thread t owns output column c = t (0..255), all 64 j -----
    {
        const int c = t;
        float acc2[64];
        const float bb = b2[c];
#pragma unroll
        for (int jj = 0; jj < 64; jj++) acc2[jj] = bb;
        const float4* H4 = reinterpret_cast<const float4*>(HID);
        for (int k = 0; k < H; k += 4) {
            const float w0 = w2[(k + 0) * 2 * H + c];
            const float wA = w2[(k + 1) * 2 * H + c];
            const float wB = w2[(k + 2) * 2 * H + c];
            const float wC = w2[(k + 3) * 2 * H + c];
#pragma unroll
            for (int jj = 0; jj < 64; jj++) {
                float4 x = H4[jj * (H / 4) + (k >> 2)];
                acc2[jj] = fmaf(x.x, w0, acc2[jj]);
                acc2[jj] = fmaf(x.y, wA, acc2[jj]);
                acc2[jj] = fmaf(x.z, wB, acc2[jj]);
                acc2[jj] = fmaf(x.w, wC, acc2[jj]);
            }
        }

        const int g = *agent_id_p;
        const bool is_agent = (i == g);
        const float* al = alive + b * A;
        float* rg = g_ragent + (size_t)b * (A * 2 * H);

        if (c < H) {
            float sum = 0.f;
#pragma unroll
            for (int jj = 0; jj < 64; jj++) {
                const float v = fmaxf(acc2[jj], 0.f);
                if (is_agent) rg[jj * (2 * H) + c] = v;
                sum = fmaf(v, al[jj], sum);
            }
            g_pooled[(size_t)bi * (2 * H) + c] = sum * (1.f / 64.f);
        } else {
            float mx = -3.4e38f;
#pragma unroll
            for (int jj = 0; jj < 64; jj++) {
                const float v = fmaxf(acc2[jj], 0.f);
                if (is_agent) rg[jj * (2 * H) + c] = v;
                mx = fmaxf(mx, v * al[jj]);
            }
            g_pooled[(size_t)bi * (2 * H) + c] = mx;
        }
    }
}

// ---------------------------------------------------------------------------
// Kernel 3: s2 = relu([s1 | avr | max] @ ra_w + ra_b)   (K=384 -> 128)
// 8 rows per block, 128 threads.
// ---------------------------------------------------------------------------
#define K3 (3 * H)  // 384
__global__ __launch_bounds__(128) void k_ra(
    const float* __restrict__ w, const float* __restrict__ bias)
{
    __shared__ float X[8 * K3];
    const int row0 = blockIdx.x * 8;
    const int t = threadIdx.x;

    for (int idx = t; idx < 8 * H; idx += 128) {
        const int jj = idx >> 7, h = idx & 127;
        X[jj * K3 + h] = g_s1[(size_t)(row0 + jj) * H + h];
    }
    for (int idx = t; idx < 8 * 2 * H; idx += 128) {
        const int jj = idx >> 8, h = idx & 255;
        X[jj * K3 + H + h] = g_pooled[(size_t)(row0 + jj) * (2 * H) + h];
    }
    __syncthreads();

    const int h = t;
    float acc[8];
    const float bb = bias[h];
#pragma unroll
    for (int jj = 0; jj < 8; jj++) acc[jj] = bb;
    const float4* X4 = reinterpret_cast<const float4*>(X);
    for (int k = 0; k < K3; k += 4) {
        const float w0 = w[(k + 0) * H + h];
        const float wA = w[(k + 1) * H + h];
        const float wB = w[(k + 2) * H + h];
        const float wC = w[(k + 3) * H + h];
#pragma unroll
        for (int jj = 0; jj < 8; jj++) {
            float4 x = X4[jj * (K3 / 4) + (k >> 2)];
            acc[jj] = fmaf(x.x, w0, acc[jj]);
            acc[jj] = fmaf(x.y, wA, acc[jj]);
            acc[jj] = fmaf(x.z, wB, acc[jj]);
            acc[jj] = fmaf(x.w, wC, acc[jj]);
        }
    }
#pragma unroll
    for (int jj = 0; jj < 8; jj++)
        g_s2[(size_t)(row0 + jj) * H + h] = fmaxf(acc[jj], 0.f);
}

// ---------------------------------------------------------------------------
// Kernel 4: ae MLP, ONLY at i == agent_id (64x work reduction vs reference).
// rows (b, j): ae_in = [r_agent[b,j,:256] | s2[b,j] | s2[b,agent_id]]  K=512
// -> 128 -> 256.  8 rows/block, 128 threads (each owns cols h and h+128).
// ---------------------------------------------------------------------------
#define K4 (4 * H)  // 512
__global__ __launch_bounds__(128) void k_ae(
    const float* __restrict__ w1, const float* __restrict__ b1,
    const float* __restrict__ w2, const float* __restrict__ b2,
    const int* __restrict__ agent_id_p)
{
    __shared__ float X[8 * K4];
    __shared__ float HID[8 * H];
    const int row0 = blockIdx.x * 8;   // global (b, j) row
    const int b = row0 >> 6;
    const int t = threadIdx.x;
    const int g = *agent_id_p;

    for (int idx = t; idx < 8 * 2 * H; idx += 128) {
        const int jj = idx >> 8, h = idx & 255;
        X[jj * K4 + h] = g_ragent[(size_t)(row0 + jj) * (2 * H) + h];
    }
    for (int idx = t; idx < 8 * H; idx += 128) {
        const int jj = idx >> 7, h = idx & 127;
        X[jj * K4 + 2 * H + h] = g_s2[(size_t)(row0 + jj) * H + h];
        X[jj * K4 + 3 * H + h] = g_s2[((size_t)b * A + g) * H + h];
    }
    __syncthreads();

    const int h = t;
    float acc[8];
    {
        const float bb = b1[h];
#pragma unroll
        for (int jj = 0; jj < 8; jj++) acc[jj] = bb;
        const float4* X4 = reinterpret_cast<const float4*>(X);
        for (int k = 0; k < K4; k += 4) {
            const float w0 = w1[(k + 0) * H + h];
            const float wA = w1[(k + 1) * H + h];
            const float wB = w1[(k + 2) * H + h];
            const float wC = w1[(k + 3) * H + h];
#pragma unroll
            for (int jj = 0; jj < 8; jj++) {
                float4 x = X4[jj * (K4 / 4) + (k >> 2)];
                acc[jj] = fmaf(x.x, w0, acc[jj]);
                acc[jj] = fmaf(x.y, wA, acc[jj]);
                acc[jj] = fmaf(x.z, wB, acc[jj]);
                acc[jj] = fmaf(x.w, wC, acc[jj]);
            }
        }
#pragma unroll
        for (int jj = 0; jj < 8; jj++) HID[jj * H + h] = fmaxf(acc[jj], 0.f);
    }
    __syncthreads();
    {
        float accA[8], accB[8];
        const float bbA = b2[h];
        const float bbB = b2[h + H];
#pragma unroll
        for (int jj = 0; jj < 8; jj++) { accA[jj] = bbA; accB[jj] = bbB; }
        const float4* H4 = reinterpret_cast<const float4*>(HID);
        for (int k = 0; k < H; k += 4) {
#pragma unroll
            for (int q = 0; q < 4; q++) {
                const float wA = w2[(k + q) * (2 * H) + h];
                const float wB = w2[(k + q) * (2 * H) + h + H];
#pragma unroll
                for (int jj = 0; jj < 8; jj++) {
                    const float x = HID[jj * H + k + q];
                    accA[jj] = fmaf(x, wA, accA[jj]);
                    accB[jj] = fmaf(x, wB, accB[jj]);
                }
            }
        }
        (void)H4;
#pragma unroll
        for (int jj = 0; jj < 8; jj++) {
            g_ae[(size_t)(row0 + jj) * (2 * H) + h] = fmaxf(accA[jj], 0.f);
            g_ae[(size_t)(row0 + jj) * (2 * H) + h + H] = fmaxf(accB[jj], 0.f);
        }
    }
}

// ---------------------------------------------------------------------------
// Kernel 5: action select/scatter + output assembly.
// out = [ state (B,A,H) | sel (B,1,1,H) | passive_sel (B,A,H) ]
// ---------------------------------------------------------------------------
__global__ __launch_bounds__(128) void k_final(
    const float* __restrict__ action_embed,
    const int* __restrict__ action,
    const int* __restrict__ agent_id_p,
    float* __restrict__ out)
{
    const int b = blockIdx.x;
    const int h = threadIdx.x;
    const int a = action[b];
    const int g = *agent_id_p;

    const float sel = (a < E)
        ? action_embed[a * H + h]
        : g_ae[((size_t)b * A + (a - E)) * (2 * H) + h];

    float* out_state = out;
    float* out_sel = out + (size_t)B * A * H;
    float* out_ps = out_sel + (size_t)B * H;

    out_sel[b * H + h] = sel;

    for (int j = 0; j < A; j++) {
        float st = g_s2[((size_t)b * A + j) * H + h];
        float ps = 0.f;
        if (a == E + j) ps = g_ae[((size_t)b * A + j) * (2 * H) + H + h];
        if (j == g) st += sel;
        out_ps[((size_t)b * A + j) * H + h] = ps;
        out_state[((size_t)b * A + j) * H + h] = st + ps;
    }
}

// ---------------------------------------------------------------------------
extern "C" void kernel_launch(void* const* d_in, const int* in_sizes, int n_in,
                              void* d_out, int out_size)
{
    const float* states       = (const float*)d_in[0];
    const float* relations    = (const float*)d_in[1];
    const float* alive_mask   = (const float*)d_in[2];
    const float* se_w1        = (const float*)d_in[3];
    const float* se_b1        = (const float*)d_in[4];
    const float* se_w2        = (const float*)d_in[5];
    const float* se_b2        = (const float*)d_in[6];
    const float* re_w1        = (const float*)d_in[7];
    const float* re_b1        = (const float*)d_in[8];
    const float* re_w2        = (const float*)d_in[9];
    const float* re_b2        = (const float*)d_in[10];
    const float* ra_w         = (const float*)d_in[11];
    const float* ra_b         = (const float*)d_in[12];
    const float* ae_w1        = (const float*)d_in[13];
    const float* ae_b1        = (const float*)d_in[14];
    const float* ae_w2        = (const float*)d_in[15];
    const float* ae_b2        = (const float*)d_in[16];
    const float* action_embed = (const float*)d_in[17];
    /* d_in[18] = action_mask (unused by reference) */
    const int*   action       = (const int*)d_in[19];
    const int*   agent_id     = (const int*)d_in[20];

    float* out = (float*)d_out;

    // k_rel dynamic smem: X(64x192) + HID(64x128) floats = 80 KB
    const int krel_smem = (64 * K1 + 64 * H) * (int)sizeof(float);
    static bool attr_set = false;
    if (!attr_set) {
        cudaFuncSetAttribute(k_rel, cudaFuncAttributeMaxDynamicSharedMemorySize,
                             krel_smem);
        attr_set = true;
    }

    k_state_enc<<<(B * A) / 8, 128>>>(states, se_w1, se_b1, se_w2, se_b2);
    k_rel<<<B * A, 256, krel_smem>>>(relations, alive_mask,
                                     re_w1, re_b1, re_w2, re_b2, agent_id);
    k_ra<<<(B * A) / 8, 128>>>(ra_w, ra_b);
    k_ae<<<(B * A) / 8, 128>>>(ae_w1, ae_b1, ae_w2, ae_b2, agent_id);
    k_final<<<B, 128>>>(action_embed, action, agent_id, out);
}

// round 2
// speedup vs baseline: 1.0016x; 1.0016x over previous
#include <cuda_runtime.h>
#include <cstdint>

// Problem constants
#define B 32
#define A 64
#define SLEN 256
#define H 128
#define RLEN 64
#define E 16

// Scratch (device globals — no allocation allowed)
__device__ float g_s1[B * A * H];        // state-encoder output
__device__ float g_pooled[B * A * 2 * H]; // [avr(128) | max(128)]
__device__ float g_ragent[B * A * 2 * H]; // r rows at i == agent_id
__device__ float g_s2[B * A * H];        // post-ra state
__device__ float g_ae[B * A * 2 * H];    // ae rows at i == agent_id

// ---------------------------------------------------------------------------
// Kernel 1: s1 = relu(relu(states @ se_w1 + b1) @ se_w2 + b2)
// 2048 rows of K=256 -> 128 -> 128. 8 rows per block, 128 threads.
// ---------------------------------------------------------------------------
__global__ __launch_bounds__(128) void k_state_enc(
    const float* __restrict__ states,
    const float* __restrict__ w1, const float* __restrict__ b1,
    const float* __restrict__ w2, const float* __restrict__ b2)
{
    __shared__ float X[8 * SLEN];
    __shared__ float HID[8 * H];
    const int row0 = blockIdx.x * 8;
    const int t = threadIdx.x;

    // load 8 input rows
    for (int idx = t; idx < 8 * SLEN; idx += 128)
        X[idx] = states[(size_t)row0 * SLEN + idx];
    __syncthreads();

    const int h = t;
    float acc[8];
    {
        const float bb = b1[h];
#pragma unroll
        for (int jj = 0; jj < 8; jj++) acc[jj] = bb;
        const float4* X4 = reinterpret_cast<const float4*>(X);
        for (int k = 0; k < SLEN; k += 4) {
            const float w0 = w1[(k + 0) * H + h];
            const float wA = w1[(k + 1) * H + h];
            const float wB = w1[(k + 2) * H + h];
            const float wC = w1[(k + 3) * H + h];
#pragma unroll
            for (int jj = 0; jj < 8; jj++) {
                float4 x = X4[jj * (SLEN / 4) + (k >> 2)];
                acc[jj] = fmaf(x.x, w0, acc[jj]);
                acc[jj] = fmaf(x.y, wA, acc[jj]);
                acc[jj] = fmaf(x.z, wB, acc[jj]);
                acc[jj] = fmaf(x.w, wC, acc[jj]);
            }
        }
#pragma unroll
        for (int jj = 0; jj < 8; jj++) HID[jj * H + h] = fmaxf(acc[jj], 0.f);
    }
    __syncthreads();
    {
        const float bb = b2[h];
#pragma unroll
        for (int jj = 0; jj < 8; jj++) acc[jj] = bb;
        const float4* H4 = reinterpret_cast<const float4*>(HID);
        for (int k = 0; k < H; k += 4) {
            const float w0 = w2[(k + 0) * H + h];
            const float wA = w2[(k + 1) * H + h];
            const float wB = w2[(k + 2) * H + h];
            const float wC = w2[(k + 3) * H + h];
#pragma unroll
            for (int jj = 0; jj < 8; jj++) {
                float4 x = H4[jj * (H / 4) + (k >> 2)];
                acc[jj] = fmaf(x.x, w0, acc[jj]);
                acc[jj] = fmaf(x.y, wA, acc[jj]);
                acc[jj] = fmaf(x.z, wB, acc[jj]);
                acc[jj] = fmaf(x.w, wC, acc[jj]);
            }
        }
#pragma unroll
        for (int jj = 0; jj < 8; jj++)
            g_s1[(size_t)(row0 + jj) * H + h] = fmaxf(acc[jj], 0.f);
    }
}

// ---------------------------------------------------------------------------
// Kernel 2 (dominant): fused relation MLP + masked mean/max pooling.
// One block per (b, i). 256 threads. For all j in [0,64):
//   rel_in[j] = [relations[b,i,j,:64] | s1[b,j,:128]]  (K=192)
//   hid = relu(rel_in @ re_w1 + b1)                    (128)
//   out = relu(hid @ re_w2 + b2)                       (256)
// pooled[b,i,c]      = mean_j(out[j,c] * alive[b,j])        c < 128
// pooled[b,i,128+c]  = max_j (out[j,128+c] * alive[b,j])
// if i == agent_id: g_ragent[b,j,:] = out[j,:]
// ---------------------------------------------------------------------------
#define K1 (RLEN + H)   // 192
__global__ __launch_bounds__(256, 2) void k_rel(
    const float* __restrict__ rel,
    const float* __restrict__ alive,
    const float* __restrict__ w1, const float* __restrict__ b1,
    const float* __restrict__ w2, const float* __restrict__ b2,
    const int* __restrict__ agent_id_p)
{
    extern __shared__ float sm[];
    float* X = sm;                 // 64 x 192
    float* HID = sm + 64 * K1;     // 64 x 128
    const int bi = blockIdx.x;
    const int b = bi >> 6;
    const int i = bi & 63;
    const int t = threadIdx.x;

    // fill X: relations part
    const float* relrow = rel + (size_t)bi * (A * RLEN);
    for (int idx = t; idx < A * RLEN; idx += 256) {
        const int j = idx >> 6, k = idx & 63;
        X[j * K1 + k] = relrow[idx];
    }
    // fill X: broadcast s1[b, j]
    const float* srow = g_s1 + (size_t)b * (A * H);
    for (int idx = t; idx < A * H; idx += 256) {
        const int j = idx >> 7, h = idx & 127;
        X[j * K1 + RLEN + h] = srow[idx];
    }
    __syncthreads();

    // ----- layer 1: 256 threads = (h in [0,128)) x (j-half in {0,1}) -----
    {
        const int h = t & 127;
        const int j0 = (t >> 7) * 32;
        float acc[32];
        const float bb = b1[h];
#pragma unroll
        for (int jj = 0; jj < 32; jj++) acc[jj] = bb;
        const float4* X4 = reinterpret_cast<const float4*>(X);
        for (int k = 0; k < K1; k += 4) {
            const float w0 = w1[(k + 0) * H + h];
            const float wA = w1[(k + 1) * H + h];
            const float wB = w1[(k + 2) * H + h];
            const float wC = w1[(k + 3) * H + h];
#pragma unroll
            for (int jj = 0; jj < 32; jj++) {
                float4 x = X4[(j0 + jj) * (K1 / 4) + (k >> 2)];
                acc[jj] = fmaf(x.x, w0, acc[jj]);
                acc[jj] = fmaf(x.y, wA, acc[jj]);
                acc[jj] = fmaf(x.z, wB, acc[jj]);
                acc[jj] = fmaf(x.w, wC, acc[jj]);
            }
        }
#pragma unroll
        for (int jj = 0; jj < 32; jj++)
            HID[(j0 + jj) * H + h] = fmaxf(acc[jj], 0.f);
    }
    __syncthreads();

    // ----- layer 2: thread t owns output column c = t (0..255), all 64 j -----
    {
        const int c = t;
        float acc2[64];
        const float bb = b2[c];
#pragma unroll
        for (int jj = 0; jj < 64; jj++) acc2[jj] = bb;
        const float4* H4 = reinterpret_cast<const float4*>(HID);
        for (int k = 0; k < H; k += 4) {
            const float w0 = w2[(k + 0) * 2 * H + c];
            const float wA = w2[(k + 1) * 2 * H + c];
            const float wB = w2[(k + 2) * 2 * H + c];
            const float wC = w2[(k + 3) * 2 * H + c];
#pragma unroll
            for (int jj = 0; jj < 64; jj++) {
                float4 x = H4[jj * (H / 4) + (k >> 2)];
                acc2[jj] = fmaf(x.x, w0, acc2[jj]);
                acc2[jj] = fmaf(x.y, wA, acc2[jj]);
                acc2[jj] = fmaf(x.z, wB, acc2[jj]);
                acc2[jj] = fmaf(x.w, wC, acc2[jj]);
            }
        }

        const int g = *agent_id_p;
        const bool is_agent = (i == g);
        const float* al = alive + b * A;
        float* rg = g_ragent + (size_t)b * (A * 2 * H);

        if (c < H) {
            float sum = 0.f;
#pragma unroll
            for (int jj = 0; jj < 64; jj++) {
                const float v = fmaxf(acc2[jj], 0.f);
                if (is_agent) rg[jj * (2 * H) + c] = v;
                sum = fmaf(v, al[jj], sum);
            }
            g_pooled[(size_t)bi * (2 * H) + c] = sum * (1.f / 64.f);
        } else {
            float mx = -3.4e38f;
#pragma unroll
            for (int jj = 0; jj < 64; jj++) {
                const float v = fmaxf(acc2[jj], 0.f);
                if (is_agent) rg[jj * (2 * H) + c] = v;
                mx = fmaxf(mx, v * al[jj]);
            }
            g_pooled[(size_t)bi * (2 * H) + c] = mx;
        }
    }
}

// ---------------------------------------------------------------------------
// Kernel 3: s2 = relu([s1 | avr | max] @ ra_w + ra_b)   (K=384 -> 128)
// 8 rows per block, 128 threads.
// ---------------------------------------------------------------------------
#define K3 (3 * H)  // 384
__global__ __launch_bounds__(128) void k_ra(
    const float* __restrict__ w, const float* __restrict__ bias)
{
    __shared__ float X[8 * K3];
    const int row0 = blockIdx.x * 8;
    const int t = threadIdx.x;

    for (int idx = t; idx < 8 * H; idx += 128) {
        const int jj = idx >> 7, h = idx & 127;
        X[jj * K3 + h] = g_s1[(size_t)(row0 + jj) * H + h];
    }
    for (int idx = t; idx < 8 * 2 * H; idx += 128) {
        const int jj = idx >> 8, h = idx & 255;
        X[jj * K3 + H + h] = g_pooled[(size_t)(row0 + jj) * (2 * H) + h];
    }
    __syncthreads();

    const int h = t;
    float acc[8];
    const float bb = bias[h];
#pragma unroll
    for (int jj = 0; jj < 8; jj++) acc[jj] = bb;
    const float4* X4 = reinterpret_cast<const float4*>(X);
    for (int k = 0; k < K3; k += 4) {
        const float w0 = w[(k + 0) * H + h];
        const float wA = w[(k + 1) * H + h];
        const float wB = w[(k + 2) * H + h];
        const float wC = w[(k + 3) * H + h];
#pragma unroll
        for (int jj = 0; jj < 8; jj++) {
            float4 x = X4[jj * (K3 / 4) + (k >> 2)];
            acc[jj] = fmaf(x.x, w0, acc[jj]);
            acc[jj] = fmaf(x.y, wA, acc[jj]);
            acc[jj] = fmaf(x.z, wB, acc[jj]);
            acc[jj] = fmaf(x.w, wC, acc[jj]);
        }
    }
#pragma unroll
    for (int jj = 0; jj < 8; jj++)
        g_s2[(size_t)(row0 + jj) * H + h] = fmaxf(acc[jj], 0.f);
}

// ---------------------------------------------------------------------------
// Kernel 4: ae MLP, ONLY at i == agent_id (64x work reduction vs reference).
// rows (b, j): ae_in = [r_agent[b,j,:256] | s2[b,j] | s2[b,agent_id]]  K=512
// -> 128 -> 256.  8 rows/block, 128 threads (each owns cols h and h+128).
// ---------------------------------------------------------------------------
#define K4 (4 * H)  // 512
__global__ __launch_bounds__(128) void k_ae(
    const float* __restrict__ w1, const float* __restrict__ b1,
    const float* __restrict__ w2, const float* __restrict__ b2,
    const int* __restrict__ agent_id_p)
{
    __shared__ float X[8 * K4];
    __shared__ float HID[8 * H];
    const int row0 = blockIdx.x * 8;   // global (b, j) row
    const int b = row0 >> 6;
    const int t = threadIdx.x;
    const int g = *agent_id_p;

    for (int idx = t; idx < 8 * 2 * H; idx += 128) {
        const int jj = idx >> 8, h = idx & 255;
        X[jj * K4 + h] = g_ragent[(size_t)(row0 + jj) * (2 * H) + h];
    }
    for (int idx = t; idx < 8 * H; idx += 128) {
        const int jj = idx >> 7, h = idx & 127;
        X[jj * K4 + 2 * H + h] = g_s2[(size_t)(row0 + jj) * H + h];
        X[jj * K4 + 3 * H + h] = g_s2[((size_t)b * A + g) * H + h];
    }
    __syncthreads();

    const int h = t;
    float acc[8];
    {
        const float bb = b1[h];
#pragma unroll
        for (int jj = 0; jj < 8; jj++) acc[jj] = bb;
        const float4* X4 = reinterpret_cast<const float4*>(X);
        for (int k = 0; k < K4; k += 4) {
            const float w0 = w1[(k + 0) * H + h];
            const float wA = w1[(k + 1) * H + h];
            const float wB = w1[(k + 2) * H + h];
            const float wC = w1[(k + 3) * H + h];
#pragma unroll
            for (int jj = 0; jj < 8; jj++) {
                float4 x = X4[jj * (K4 / 4) + (k >> 2)];
                acc[jj] = fmaf(x.x, w0, acc[jj]);
                acc[jj] = fmaf(x.y, wA, acc[jj]);
                acc[jj] = fmaf(x.z, wB, acc[jj]);
                acc[jj] = fmaf(x.w, wC, acc[jj]);
            }
        }
#pragma unroll
        for (int jj = 0; jj < 8; jj++) HID[jj * H + h] = fmaxf(acc[jj], 0.f);
    }
    __syncthreads();
    {
        float accA[8], accB[8];
        const float bbA = b2[h];
        const float bbB = b2[h + H];
#pragma unroll
        for (int jj = 0; jj < 8; jj++) { accA[jj] = bbA; accB[jj] = bbB; }
        const float4* H4 = reinterpret_cast<const float4*>(HID);
        for (int k = 0; k < H; k += 4) {
#pragma unroll
            for (int q = 0; q < 4; q++) {
                const float wA = w2[(k + q) * (2 * H) + h];
                const float wB = w2[(k + q) * (2 * H) + h + H];
#pragma unroll
                for (int jj = 0; jj < 8; jj++) {
                    const float x = HID[jj * H + k + q];
                    accA[jj] = fmaf(x, wA, accA[jj]);
                    accB[jj] = fmaf(x, wB, accB[jj]);
                }
            }
        }
        (void)H4;
#pragma unroll
        for (int jj = 0; jj < 8; jj++) {
            g_ae[(size_t)(row0 + jj) * (2 * H) + h] = fmaxf(accA[jj], 0.f);
            g_ae[(size_t)(row0 + jj) * (2 * H) + h + H] = fmaxf(accB[jj], 0.f);
        }
    }
}

// ---------------------------------------------------------------------------
// Kernel 5: action select/scatter + output assembly.
// out = [ state (B,A,H) | sel (B,1,1,H) | passive_sel (B,A,H) ]
// ---------------------------------------------------------------------------
__global__ __launch_bounds__(128) void k_final(
    const float* __restrict__ action_embed,
    const int* __restrict__ action,
    const int* __restrict__ agent_id_p,
    float* __restrict__ out)
{
    const int b = blockIdx.x;
    const int h = threadIdx.x;
    const int a = action[b];
    const int g = *agent_id_p;

    const float sel = (a < E)
        ? action_embed[a * H + h]
        : g_ae[((size_t)b * A + (a - E)) * (2 * H) + h];

    float* out_state = out;
    float* out_sel = out + (size_t)B * A * H;
    float* out_ps = out_sel + (size_t)B * H;

    out_sel[b * H + h] = sel;

    for (int j = 0; j < A; j++) {
        float st = g_s2[((size_t)b * A + j) * H + h];
        float ps = 0.f;
        if (a == E + j) ps = g_ae[((size_t)b * A + j) * (2 * H) + H + h];
        if (j == g) st += sel;
        out_ps[((size_t)b * A + j) * H + h] = ps;
        out_state[((size_t)b * A + j) * H + h] = st + ps;
    }
}

// ---------------------------------------------------------------------------
extern "C" void kernel_launch(void* const* d_in, const int* in_sizes, int n_in,
                              void* d_out, int out_size)
{
    const float* states       = (const float*)d_in[0];
    const float* relations    = (const float*)d_in[1];
    const float* alive_mask   = (const float*)d_in[2];
    const float* se_w1        = (const float*)d_in[3];
    const float* se_b1        = (const float*)d_in[4];
    const float* se_w2        = (const float*)d_in[5];
    const float* se_b2        = (const float*)d_in[6];
    const float* re_w1        = (const float*)d_in[7];
    const float* re_b1        = (const float*)d_in[8];
    const float* re_w2        = (const float*)d_in[9];
    const float* re_b2        = (const float*)d_in[10];
    const float* ra_w         = (const float*)d_in[11];
    const float* ra_b         = (const float*)d_in[12];
    const float* ae_w1        = (const float*)d_in[13];
    const float* ae_b1        = (const float*)d_in[14];
    const float* ae_w2        = (const float*)d_in[15];
    const float* ae_b2        = (const float*)d_in[16];
    const float* action_embed = (const float*)d_in[17];
    /* d_in[18] = action_mask (unused by reference) */
    const int*   action       = (const int*)d_in[19];
    const int*   agent_id     = (const int*)d_in[20];

    float* out = (float*)d_out;

    // k_rel dynamic smem: X(64x192) + HID(64x128) floats = 80 KB
    const int krel_smem = (64 * K1 + 64 * H) * (int)sizeof(float);
    static bool attr_set = false;
    if (!attr_set) {
        cudaFuncSetAttribute(k_rel, cudaFuncAttributeMaxDynamicSharedMemorySize,
                             krel_smem);
        attr_set = true;
    }

    k_state_enc<<<(B * A) / 8, 128>>>(states, se_w1, se_b1, se_w2, se_b2);
    k_rel<<<B * A, 256, krel_smem>>>(relations, alive_mask,
                                     re_w1, re_b1, re_w2, re_b2, agent_id);
    k_ra<<<(B * A) / 8, 128>>>(ra_w, ra_b);
    k_ae<<<(B * A) / 8, 128>>>(ae_w1, ae_b1, ae_w2, ae_b2, agent_id);
    k_final<<<B, 128>>>(action_embed, action, agent_id, out);
}

// round 4
// speedup vs baseline: 1.7311x; 1.7283x over previous
#include <cuda_runtime.h>
#include <cuda_bf16.h>
#include <cstdint>

#define B 32
#define A 64
#define SLEN 256
#define H 128
#define RLEN 64
#define E 16
#define K3 (3 * H)
#define K4 (4 * H)

// Scratch (device globals — no allocation allowed)
__device__ float g_s1[B * A * H];
__device__ float g_pooled[B * A * 2 * H];
__device__ float g_ragent[B * A * 2 * H];
__device__ float g_s2[B * A * H];
__device__ float g_ae[B * A * 2 * H];
// bf16-split weight images (n-major): w1^T [128][192], w2^T [256][128]
__device__ __align__(16) __nv_bfloat16 g_w1h[128 * 192];
__device__ __align__(16) __nv_bfloat16 g_w1l[128 * 192];
__device__ __align__(16) __nv_bfloat16 g_w2h[256 * 128];
__device__ __align__(16) __nv_bfloat16 g_w2l[256 * 128];

// mma.sync m16n8k16 bf16 (f32 accum): D += A*B
#define MMA4(d, a, b0, b1) asm volatile( \
    "mma.sync.aligned.m16n8k16.row.col.f32.bf16.bf16.f32 " \
    "{%0,%1,%2,%3},{%4,%5,%6,%7},{%8,%9},{%0,%1,%2,%3};" \
    : "+f"((d)[0]), "+f"((d)[1]), "+f"((d)[2]), "+f"((d)[3]) \
    : "r"((a)[0]), "r"((a)[1]), "r"((a)[2]), "r"((a)[3]), "r"(b0), "r"(b1))

__device__ __forceinline__ void split2(float2 v, uint32_t& hi, uint32_t& lo) {
    __nv_bfloat16 h0 = __float2bfloat16(v.x), h1 = __float2bfloat16(v.y);
    float r0 = v.x - __bfloat162float(h0), r1 = v.y - __bfloat162float(h1);
    __nv_bfloat162 Hh = __halves2bfloat162(h0, h1);
    __nv_bfloat162 Ll = __halves2bfloat162(__float2bfloat16(r0), __float2bfloat16(r1));
    hi = *reinterpret_cast<uint32_t*>(&Hh);
    lo = *reinterpret_cast<uint32_t*>(&Ll);
}

// ---------------- k_prep: bf16-split weight images ----------------
__global__ void k_prep(const float* __restrict__ w1, const float* __restrict__ w2)
{
    const int stride = gridDim.x * blockDim.x;
    int tid = blockIdx.x * blockDim.x + threadIdx.x;
    for (int idx = tid; idx < 128 * 192; idx += stride) {
        int n = idx / 192, k = idx % 192;
        float v = w1[k * 128 + n];
        __nv_bfloat16 h = __float2bfloat16(v);
        g_w1h[idx] = h;
        g_w1l[idx] = __float2bfloat16(v - __bfloat162float(h));
    }
    for (int idx = tid; idx < 256 * 128; idx += stride) {
        int n = idx / 128, k = idx % 128;
        float v = w2[k * 256 + n];
        __nv_bfloat16 h = __float2bfloat16(v);
        g_w2h[idx] = h;
        g_w2l[idx] = __float2bfloat16(v - __bfloat162float(h));
    }
}

// ---------------- k_state_enc: 16 rows/block, 256 thr ----------------
__global__ __launch_bounds__(256) void k_state_enc(
    const float* __restrict__ st, const float* __restrict__ w1, const float* __restrict__ b1,
    const float* __restrict__ w2, const float* __restrict__ b2)
{
    __shared__ float X[16 * SLEN];
    __shared__ float HD[16 * H];
    const int row0 = blockIdx.x * 16, t = threadIdx.x;
    for (int i = t; i < 16 * SLEN; i += 256) X[i] = st[(size_t)row0 * SLEN + i];
    __syncthreads();
    const int h = t & 127, rb = (t >> 7) * 8;
    float acc[8];
    {
        const float bb = b1[h];
#pragma unroll
        for (int j = 0; j < 8; j++) acc[j] = bb;
        const float4* X4 = (const float4*)X;
#pragma unroll 2
        for (int k = 0; k < SLEN; k += 4) {
            float w0 = w1[k * H + h], wA = w1[(k + 1) * H + h], wB = w1[(k + 2) * H + h], wC = w1[(k + 3) * H + h];
#pragma unroll
            for (int j = 0; j < 8; j++) {
                float4 x = X4[(rb + j) * (SLEN / 4) + (k >> 2)];
                acc[j] = fmaf(x.x, w0, acc[j]); acc[j] = fmaf(x.y, wA, acc[j]);
                acc[j] = fmaf(x.z, wB, acc[j]); acc[j] = fmaf(x.w, wC, acc[j]);
            }
        }
#pragma unroll
        for (int j = 0; j < 8; j++) HD[(rb + j) * H + h] = fmaxf(acc[j], 0.f);
    }
    __syncthreads();
    {
        const float bb = b2[h];
#pragma unroll
        for (int j = 0; j < 8; j++) acc[j] = bb;
        const float4* H4 = (const float4*)HD;
#pragma unroll 2
        for (int k = 0; k < H; k += 4) {
            float w0 = w2[k * H + h], wA = w2[(k + 1) * H + h], wB = w2[(k + 2) * H + h], wC = w2[(k + 3) * H + h];
#pragma unroll
            for (int j = 0; j < 8; j++) {
                float4 x = H4[(rb + j) * (H / 4) + (k >> 2)];
                acc[j] = fmaf(x.x, w0, acc[j]); acc[j] = fmaf(x.y, wA, acc[j]);
                acc[j] = fmaf(x.z, wB, acc[j]); acc[j] = fmaf(x.w, wC, acc[j]);
            }
        }
#pragma unroll
        for (int j = 0; j < 8; j++) g_s1[(size_t)(row0 + rb + j) * H + h] = fmaxf(acc[j], 0.f);
    }
}

// ---------------- k_rel: mma.sync bf16x3, fused pooling ----------------
// One CTA per (b,i). 8 warps. Layer1: warp w computes HID^T rows c1 in
// [16w,16w+16) over all 64 j (outT = W1 * X^T). Layer2: two passes (mean rows
// c2<128, max rows c2>=128), pooling over j entirely in-warp.
#define HS 136
#define STSP(idx, v) { float _v = (v); __nv_bfloat16 _h = __float2bfloat16(_v); \
    HIh[idx] = _h; HIl[idx] = __float2bfloat16(_v - __bfloat162float(_h)); }

__global__ __launch_bounds__(256, 2) void k_rel(
    const float* __restrict__ rel, const float* __restrict__ alive,
    const float* __restrict__ b1, const float* __restrict__ b2,
    const int* __restrict__ agp)
{
    __shared__ __align__(16) __nv_bfloat16 HIh[64 * HS];
    __shared__ __align__(16) __nv_bfloat16 HIl[64 * HS];
    __shared__ float sal[64];
    const int tid = threadIdx.x, w = tid >> 5, l = tid & 31, g = l >> 2, t4 = l & 3;
    const int bi = blockIdx.x, b = bi >> 6, i = bi & 63;
    if (tid < 64) sal[tid] = alive[b * 64 + tid];

    float ac[8][4];
#pragma unroll
    for (int n = 0; n < 8; n++) { ac[n][0] = 0.f; ac[n][1] = 0.f; ac[n][2] = 0.f; ac[n][3] = 0.f; }
    const int r0 = w * 16 + g;
    const size_t relbase = (size_t)bi * 64 * 64;

    // ---- layer 1: K=192 (12 ksteps). A = W1 frags (LDG), B = X frags (LDG+split)
#pragma unroll 1
    for (int ks = 0; ks < 12; ks++) {
        const int ka = ks * 16 + 2 * t4;
        uint32_t ah[4], alr[4];
        ah[0] = *(const uint32_t*)(g_w1h + r0 * 192 + ka);
        ah[1] = *(const uint32_t*)(g_w1h + (r0 + 8) * 192 + ka);
        ah[2] = *(const uint32_t*)(g_w1h + r0 * 192 + ka + 8);
        ah[3] = *(const uint32_t*)(g_w1h + (r0 + 8) * 192 + ka + 8);
        alr[0] = *(const uint32_t*)(g_w1l + r0 * 192 + ka);
        alr[1] = *(const uint32_t*)(g_w1l + (r0 + 8) * 192 + ka);
        alr[2] = *(const uint32_t*)(g_w1l + r0 * 192 + ka + 8);
        alr[3] = *(const uint32_t*)(g_w1l + (r0 + 8) * 192 + ka + 8);
#pragma unroll
        for (int n = 0; n < 8; n++) {
            const int j = n * 8 + g;
            const float* xb = (ks < 4) ? (rel + relbase + (size_t)j * 64 + ka)
                                       : (g_s1 + (size_t)(b * 64 + j) * 128 + (ka - 64));
            float2 v0 = *(const float2*)xb, v1 = *(const float2*)(xb + 8);
            uint32_t bh0, bl0, bh1, bl1;
            split2(v0, bh0, bl0);
            split2(v1, bh1, bl1);
            MMA4(ac[n], ah, bh0, bh1);
            MMA4(ac[n], ah, bl0, bl1);
            MMA4(ac[n], alr, bh0, bh1);
        }
    }
    // epilogue 1: relu(+b1), split, store HID[j][c1] (transposed scatter)
    {
        const float bA = b1[r0], bB = b1[r0 + 8];
#pragma unroll
        for (int n = 0; n < 8; n++) {
            const int j0 = n * 8 + 2 * t4;
            STSP(j0 * HS + r0,           fmaxf(ac[n][0] + bA, 0.f));
            STSP((j0 + 1) * HS + r0,     fmaxf(ac[n][1] + bA, 0.f));
            STSP(j0 * HS + r0 + 8,       fmaxf(ac[n][2] + bB, 0.f));
            STSP((j0 + 1) * HS + r0 + 8, fmaxf(ac[n][3] + bB, 0.f));
        }
    }
    __syncthreads();

    // ---- layer 2: two half-passes (hf=0: mean cols, hf=1: max cols), K=128
    const int gag = *agp;
    const bool isag = (i == gag);
#pragma unroll 1
    for (int hf = 0; hf < 2; hf++) {
        const int rr = hf * 128 + w * 16 + g;  // absolute output col c2 (and rr+8)
#pragma unroll
        for (int n = 0; n < 8; n++) { ac[n][0] = 0.f; ac[n][1] = 0.f; ac[n][2] = 0.f; ac[n][3] = 0.f; }
#pragma unroll 1
        for (int ks = 0; ks < 8; ks++) {
            const int ka = ks * 16 + 2 * t4;
            uint32_t ah[4], alr[4];
            ah[0] = *(const uint32_t*)(g_w2h + rr * 128 + ka);
            ah[1] = *(const uint32_t*)(g_w2h + (rr + 8) * 128 + ka);
            ah[2] = *(const uint32_t*)(g_w2h + rr * 128 + ka + 8);
            ah[3] = *(const uint32_t*)(g_w2h + (rr + 8) * 128 + ka + 8);
            alr[0] = *(const uint32_t*)(g_w2l + rr * 128 + ka);
            alr[1] = *(const uint32_t*)(g_w2l + (rr + 8) * 128 + ka);
            alr[2] = *(const uint32_t*)(g_w2l + rr * 128 + ka + 8);
            alr[3] = *(const uint32_t*)(g_w2l + (rr + 8) * 128 + ka + 8);
#pragma unroll
            for (int n = 0; n < 8; n++) {
                const int j = n * 8 + g;
                uint32_t bh0 = *(const uint32_t*)&HIh[j * HS + ka];
                uint32_t bh1 = *(const uint32_t*)&HIh[j * HS + ka + 8];
                uint32_t bl0 = *(const uint32_t*)&HIl[j * HS + ka];
                uint32_t bl1 = *(const uint32_t*)&HIl[j * HS + ka + 8];
                MMA4(ac[n], ah, bh0, bh1);
                MMA4(ac[n], ah, bl0, bl1);
                MMA4(ac[n], alr, bh0, bh1);
            }
        }
        // epilogue 2: relu(+b2), agent store, in-warp masked mean/max over j
        const float bA = b2[rr], bB = b2[rr + 8];
        float s0 = 0.f, s1 = 0.f;
#pragma unroll
        for (int n = 0; n < 8; n++) {
            const int j0 = n * 8 + 2 * t4;
            const float al0 = sal[j0], al1 = sal[j0 + 1];
            float v0 = fmaxf(ac[n][0] + bA, 0.f), v1 = fmaxf(ac[n][1] + bA, 0.f);
            float v2 = fmaxf(ac[n][2] + bB, 0.f), v3 = fmaxf(ac[n][3] + bB, 0.f);
            if (isag) {
                float* rg = g_ragent + (size_t)(b * 64) * 256;
                rg[(size_t)j0 * 256 + rr] = v0;
                rg[(size_t)(j0 + 1) * 256 + rr] = v1;
                rg[(size_t)j0 * 256 + rr + 8] = v2;
                rg[(size_t)(j0 + 1) * 256 + rr + 8] = v3;
            }
            if (hf == 0) {
                s0 += v0 * al0 + v1 * al1;
                s1 += v2 * al0 + v3 * al1;
            } else {
                s0 = fmaxf(s0, fmaxf(v0 * al0, v1 * al1));
                s1 = fmaxf(s1, fmaxf(v2 * al0, v3 * al1));
            }
        }
        if (hf == 0) {
            s0 += __shfl_xor_sync(0xffffffffu, s0, 1); s0 += __shfl_xor_sync(0xffffffffu, s0, 2);
            s1 += __shfl_xor_sync(0xffffffffu, s1, 1); s1 += __shfl_xor_sync(0xffffffffu, s1, 2);
            if (t4 == 0) {
                g_pooled[(size_t)bi * 256 + rr] = s0 * (1.f / 64.f);
                g_pooled[(size_t)bi * 256 + rr + 8] = s1 * (1.f / 64.f);
            }
        } else {
            s0 = fmaxf(s0, __shfl_xor_sync(0xffffffffu, s0, 1)); s0 = fmaxf(s0, __shfl_xor_sync(0xffffffffu, s0, 2));
            s1 = fmaxf(s1, __shfl_xor_sync(0xffffffffu, s1, 1)); s1 = fmaxf(s1, __shfl_xor_sync(0xffffffffu, s1, 2));
            if (t4 == 0) {
                g_pooled[(size_t)bi * 256 + rr] = s0;
                g_pooled[(size_t)bi * 256 + rr + 8] = s1;
            }
        }
    }
}

// ---------------- k_ra: 16 rows/block ----------------
__global__ __launch_bounds__(256) void k_ra(const float* __restrict__ w, const float* __restrict__ bias)
{
    __shared__ float X[16 * K3];
    const int row0 = blockIdx.x * 16, t = threadIdx.x;
    for (int i = t; i < 16 * H; i += 256) {
        int j = i >> 7, h = i & 127;
        X[j * K3 + h] = g_s1[(size_t)(row0 + j) * H + h];
    }
    for (int i = t; i < 16 * 2 * H; i += 256) {
        int j = i >> 8, h = i & 255;
        X[j * K3 + H + h] = g_pooled[(size_t)(row0 + j) * (2 * H) + h];
    }
    __syncthreads();
    const int h = t & 127, rb = (t >> 7) * 8;
    float acc[8];
    const float bb = bias[h];
#pragma unroll
    for (int j = 0; j < 8; j++) acc[j] = bb;
    const float4* X4 = (const float4*)X;
#pragma unroll 2
    for (int k = 0; k < K3; k += 4) {
        float w0 = w[k * H + h], wA = w[(k + 1) * H + h], wB = w[(k + 2) * H + h], wC = w[(k + 3) * H + h];
#pragma unroll
        for (int j = 0; j < 8; j++) {
            float4 x = X4[(rb + j) * (K3 / 4) + (k >> 2)];
            acc[j] = fmaf(x.x, w0, acc[j]); acc[j] = fmaf(x.y, wA, acc[j]);
            acc[j] = fmaf(x.z, wB, acc[j]); acc[j] = fmaf(x.w, wC, acc[j]);
        }
    }
#pragma unroll
    for (int j = 0; j < 8; j++) g_s2[(size_t)(row0 + rb + j) * H + h] = fmaxf(acc[j], 0.f);
}

// ---------------- k_ae: 16 rows/block (only i == agent_id rows exist) ----------------
__global__ __launch_bounds__(256) void k_ae(
    const float* __restrict__ w1, const float* __restrict__ b1,
    const float* __restrict__ w2, const float* __restrict__ b2,
    const int* __restrict__ agp)
{
    __shared__ float X[16 * K4];   // 32 KB
    __shared__ float HD[16 * H];   // 8 KB
    const int row0 = blockIdx.x * 16, b = row0 >> 6, t = threadIdx.x;
    const int g = *agp;
    for (int i = t; i < 16 * 2 * H; i += 256) {
        int j = i >> 8, h = i & 255;
        X[j * K4 + h] = g_ragent[(size_t)(row0 + j) * (2 * H) + h];
    }
    for (int i = t; i < 16 * H; i += 256) {
        int j = i >> 7, h = i & 127;
        X[j * K4 + 2 * H + h] = g_s2[(size_t)(row0 + j) * H + h];
        X[j * K4 + 3 * H + h] = g_s2[((size_t)b * A + g) * H + h];
    }
    __syncthreads();
    {
        const int h = t & 127, rb = (t >> 7) * 8;
        float acc[8];
        const float bb = b1[h];
#pragma unroll
        for (int j = 0; j < 8; j++) acc[j] = bb;
        const float4* X4 = (const float4*)X;
#pragma unroll 2
        for (int k = 0; k < K4; k += 4) {
            float w0 = w1[k * H + h], wA = w1[(k + 1) * H + h], wB = w1[(k + 2) * H + h], wC = w1[(k + 3) * H + h];
#pragma unroll
            for (int j = 0; j < 8; j++) {
                float4 x = X4[(rb + j) * (K4 / 4) + (k >> 2)];
                acc[j] = fmaf(x.x, w0, acc[j]); acc[j] = fmaf(x.y, wA, acc[j]);
                acc[j] = fmaf(x.z, wB, acc[j]); acc[j] = fmaf(x.w, wC, acc[j]);
            }
        }
#pragma unroll
        for (int j = 0; j < 8; j++) HD[(rb + j) * H + h] = fmaxf(acc[j], 0.f);
    }
    __syncthreads();
    {
        const int c = t;
        float acc2[16];
        const float bb = b2[c];
#pragma unroll
        for (int j = 0; j < 16; j++) acc2[j] = bb;
        const float4* H4 = (const float4*)HD;
#pragma unroll 2
        for (int k = 0; k < H; k += 4) {
            float w0 = w2[k * 256 + c], wA = w2[(k + 1) * 256 + c], wB = w2[(k + 2) * 256 + c], wC = w2[(k + 3) * 256 + c];
#pragma unroll
            for (int j = 0; j < 16; j++) {
                float4 x = H4[j * (H / 4) + (k >> 2)];
                acc2[j] = fmaf(x.x, w0, acc2[j]); acc2[j] = fmaf(x.y, wA, acc2[j]);
                acc2[j] = fmaf(x.z, wB, acc2[j]); acc2[j] = fmaf(x.w, wC, acc2[j]);
            }
        }
#pragma unroll
        for (int j = 0; j < 16; j++)
            g_ae[(size_t)(row0 + j) * (2 * H) + c] = fmaxf(acc2[j], 0.f);
    }
}

// ---------------- k_final ----------------
__global__ __launch_bounds__(128) void k_final(
    const float* __restrict__ action_embed, const int* __restrict__ action,
    const int* __restrict__ agp, float* __restrict__ out)
{
    const int b = blockIdx.x, h = threadIdx.x;
    const int a = action[b], g = *agp;
    const float sel = (a < E) ? action_embed[a * H + h]
                              : g_ae[((size_t)b * A + (a - E)) * (2 * H) + h];
    float* out_state = out;
    float* out_sel = out + (size_t)B * A * H;
    float* out_ps = out_sel + (size_t)B * H;
    out_sel[b * H + h] = sel;
    for (int j = 0; j < A; j++) {
        float st = g_s2[((size_t)b * A + j) * H + h];
        float ps = 0.f;
        if (a == E + j) ps = g_ae[((size_t)b * A + j) * (2 * H) + H + h];
        if (j == g) st += sel;
        out_ps[((size_t)b * A + j) * H + h] = ps;
        out_state[((size_t)b * A + j) * H + h] = st + ps;
    }
}

// ---------------- launcher ----------------
extern "C" void kernel_launch(void* const* d_in, const int* in_sizes, int n_in,
                              void* d_out, int out_size)
{
    const float* states       = (const float*)d_in[0];
    const float* relations    = (const float*)d_in[1];
    const float* alive_mask   = (const float*)d_in[2];
    const float* se_w1        = (const float*)d_in[3];
    const float* se_b1        = (const float*)d_in[4];
    const float* se_w2        = (const float*)d_in[5];
    const float* se_b2        = (const float*)d_in[6];
    const float* re_w1        = (const float*)d_in[7];
    const float* re_b1        = (const float*)d_in[8];
    const float* re_w2        = (const float*)d_in[9];
    const float* re_b2        = (const float*)d_in[10];
    const float* ra_w         = (const float*)d_in[11];
    const float* ra_b         = (const float*)d_in[12];
    const float* ae_w1        = (const float*)d_in[13];
    const float* ae_b1        = (const float*)d_in[14];
    const float* ae_w2        = (const float*)d_in[15];
    const float* ae_b2        = (const float*)d_in[16];
    const float* action_embed = (const float*)d_in[17];
    const int*   action       = (const int*)d_in[19];
    const int*   agent_id     = (const int*)d_in[20];
    float* out = (float*)d_out;

    k_prep<<<64, 256>>>(re_w1, re_w2);
    k_state_enc<<<(B * A) / 16, 256>>>(states, se_w1, se_b1, se_w2, se_b2);
    k_rel<<<B * A, 256>>>(relations, alive_mask, re_b1, re_b2, agent_id);
    k_ra<<<(B * A) / 16, 256>>>(ra_w, ra_b);
    k_ae<<<(B * A) / 16, 256>>>(ae_w1, ae_b1, ae_w2, ae_b2, agent_id);
    k_final<<<B, 128>>>(action_embed, action, agent_id, out);
}

// round 5
// speedup vs baseline: 2.2168x; 1.2806x over previous
#include <cuda_runtime.h>
#include <cuda_bf16.h>
#include <cstdint>

#define B 32
#define A 64
#define SLEN 256
#define H 128
#define RLEN 64
#define E 16
#define K3 (3 * H)
#define K4 (4 * H)

// Scratch (device globals — no allocation allowed)
__device__ float g_s1[B * A * H];
__device__ float g_pooled[B * A * 2 * H];
__device__ float g_ragent[B * A * 2 * H];
__device__ float g_s2[B * A * H];
__device__ float g_ae[B * A * 2 * H];
// bf16-split weight images (n-major): w1^T [128][192], w2^T [256][128]
__device__ __align__(16) __nv_bfloat16 g_w1h[128 * 192];
__device__ __align__(16) __nv_bfloat16 g_w1l[128 * 192];
__device__ __align__(16) __nv_bfloat16 g_w2h[256 * 128];
__device__ __align__(16) __nv_bfloat16 g_w2l[256 * 128];

// mma.sync m16n8k16 bf16 (f32 accum): D += A*B
#define MMA4(d, a, b0, b1) asm volatile( \
    "mma.sync.aligned.m16n8k16.row.col.f32.bf16.bf16.f32 " \
    "{%0,%1,%2,%3},{%4,%5,%6,%7},{%8,%9},{%0,%1,%2,%3};" \
    : "+f"((d)[0]), "+f"((d)[1]), "+f"((d)[2]), "+f"((d)[3]) \
    : "r"((a)[0]), "r"((a)[1]), "r"((a)[2]), "r"((a)[3]), "r"(b0), "r"(b1))

// ---------------- k_prep: bf16-split weight images ----------------
__global__ void k_prep(const float* __restrict__ w1, const float* __restrict__ w2)
{
    const int stride = gridDim.x * blockDim.x;
    int tid = blockIdx.x * blockDim.x + threadIdx.x;
    for (int idx = tid; idx < 128 * 192; idx += stride) {
        int n = idx / 192, k = idx % 192;
        float v = w1[k * 128 + n];
        __nv_bfloat16 h = __float2bfloat16(v);
        g_w1h[idx] = h;
        g_w1l[idx] = __float2bfloat16(v - __bfloat162float(h));
    }
    for (int idx = tid; idx < 256 * 128; idx += stride) {
        int n = idx / 128, k = idx % 128;
        float v = w2[k * 256 + n];
        __nv_bfloat16 h = __float2bfloat16(v);
        g_w2h[idx] = h;
        g_w2l[idx] = __float2bfloat16(v - __bfloat162float(h));
    }
}

// ---------------- k_state_enc: 8 rows/block, split-K, grid 256 ----------------
__global__ __launch_bounds__(256) void k_state_enc(
    const float* __restrict__ st, const float* __restrict__ w1, const float* __restrict__ b1,
    const float* __restrict__ w2, const float* __restrict__ b2)
{
    __shared__ float X[8 * SLEN];
    __shared__ float HD[8 * H];
    __shared__ float RED[2 * 8 * H];
    const int row0 = blockIdx.x * 8, t = threadIdx.x;
    for (int i = t; i < 8 * SLEN; i += 256) X[i] = st[(size_t)row0 * SLEN + i];
    __syncthreads();
    const int h = t & 127, kh = t >> 7;
    // layer 1: K=256, each half does 128
    {
        float acc[8];
#pragma unroll
        for (int j = 0; j < 8; j++) acc[j] = 0.f;
        const float4* X4 = (const float4*)X;
        const int k0 = kh * 128;
#pragma unroll 4
        for (int k = k0; k < k0 + 128; k += 4) {
            float w0 = w1[k * H + h], wA = w1[(k + 1) * H + h], wB = w1[(k + 2) * H + h], wC = w1[(k + 3) * H + h];
#pragma unroll
            for (int j = 0; j < 8; j++) {
                float4 x = X4[j * (SLEN / 4) + (k >> 2)];
                acc[j] = fmaf(x.x, w0, acc[j]); acc[j] = fmaf(x.y, wA, acc[j]);
                acc[j] = fmaf(x.z, wB, acc[j]); acc[j] = fmaf(x.w, wC, acc[j]);
            }
        }
#pragma unroll
        for (int j = 0; j < 8; j++) RED[(kh * 8 + j) * H + h] = acc[j];
    }
    __syncthreads();
    for (int idx = t; idx < 8 * H; idx += 256)
        HD[idx] = fmaxf(RED[idx] + RED[8 * H + idx] + b1[idx & 127], 0.f);
    __syncthreads();
    // layer 2: K=128, no split: rows split across halves
    {
        const int rb = kh * 4;
        float acc[4];
        const float bb = b2[h];
#pragma unroll
        for (int j = 0; j < 4; j++) acc[j] = bb;
        const float4* H4 = (const float4*)HD;
#pragma unroll 4
        for (int k = 0; k < H; k += 4) {
            float w0 = w2[k * H + h], wA = w2[(k + 1) * H + h], wB = w2[(k + 2) * H + h], wC = w2[(k + 3) * H + h];
#pragma unroll
            for (int j = 0; j < 4; j++) {
                float4 x = H4[(rb + j) * (H / 4) + (k >> 2)];
                acc[j] = fmaf(x.x, w0, acc[j]); acc[j] = fmaf(x.y, wA, acc[j]);
                acc[j] = fmaf(x.z, wB, acc[j]); acc[j] = fmaf(x.w, wC, acc[j]);
            }
        }
#pragma unroll
        for (int j = 0; j < 4; j++) g_s1[(size_t)(row0 + rb + j) * H + h] = fmaxf(acc[j], 0.f);
    }
}

// ---------------- k_rel: mma.sync bf16x3, X staged+split in smem ----------------
// Dynamic smem layout (bytes):
//   XH @0      : 64 x 200 bf16 = 25600
//   XL @25600  : 25600
//   HIH @51200 : 64 x 136 bf16 = 17408
//   HIL @68608 : 17408
//   SAL @86016 : 64 floats = 256   -> total 86272
#define HS 136
#define XS 200
#define SM_REL 86272
#define STSP(idx, v) { float _v = (v); __nv_bfloat16 _h = __float2bfloat16(_v); \
    HIh[idx] = _h; HIl[idx] = __float2bfloat16(_v - __bfloat162float(_h)); }

__global__ __launch_bounds__(256, 2) void k_rel(
    const float* __restrict__ rel, const float* __restrict__ alive,
    const float* __restrict__ b1, const float* __restrict__ b2,
    const int* __restrict__ agp)
{
    extern __shared__ unsigned char smem[];
    __nv_bfloat16* XH = (__nv_bfloat16*)smem;
    __nv_bfloat16* XL = (__nv_bfloat16*)(smem + 25600);
    __nv_bfloat16* HIh = (__nv_bfloat16*)(smem + 51200);
    __nv_bfloat16* HIl = (__nv_bfloat16*)(smem + 68608);
    float* sal = (float*)(smem + 86016);

    const int tid = threadIdx.x, w = tid >> 5, l = tid & 31, g = l >> 2, t4 = l & 3;
    const int bi = blockIdx.x, b = bi >> 6, i = bi & 63;
    if (tid < 64) sal[tid] = alive[b * 64 + tid];

    // stage X (rel | s1) into smem, split to bf16 hi/lo once
    {
        const float* rr = rel + (size_t)bi * 64 * 64;
        for (int idx = tid; idx < 64 * 64; idx += 256) {
            const int j = idx >> 6, k = idx & 63;
            float v = rr[idx];
            __nv_bfloat16 hh = __float2bfloat16(v);
            XH[j * XS + k] = hh;
            XL[j * XS + k] = __float2bfloat16(v - __bfloat162float(hh));
        }
        const float* sr = g_s1 + (size_t)(b * 64) * 128;
        for (int idx = tid; idx < 64 * 128; idx += 256) {
            const int j = idx >> 7, k = idx & 127;
            float v = sr[idx];
            __nv_bfloat16 hh = __float2bfloat16(v);
            XH[j * XS + 64 + k] = hh;
            XL[j * XS + 64 + k] = __float2bfloat16(v - __bfloat162float(hh));
        }
    }
    __syncthreads();

    float ac[8][4];
#pragma unroll
    for (int n = 0; n < 8; n++) { ac[n][0] = 0.f; ac[n][1] = 0.f; ac[n][2] = 0.f; ac[n][3] = 0.f; }
    const int r0 = w * 16 + g;

    // ---- layer 1: K=192 (12 ksteps). A = W1 frags (LDG, L1-hot), B from smem
#pragma unroll 1
    for (int ks = 0; ks < 12; ks++) {
        const int ka = ks * 16 + 2 * t4;
        uint32_t ah[4], alr[4];
        ah[0] = *(const uint32_t*)(g_w1h + r0 * 192 + ka);
        ah[1] = *(const uint32_t*)(g_w1h + (r0 + 8) * 192 + ka);
        ah[2] = *(const uint32_t*)(g_w1h + r0 * 192 + ka + 8);
        ah[3] = *(const uint32_t*)(g_w1h + (r0 + 8) * 192 + ka + 8);
        alr[0] = *(const uint32_t*)(g_w1l + r0 * 192 + ka);
        alr[1] = *(const uint32_t*)(g_w1l + (r0 + 8) * 192 + ka);
        alr[2] = *(const uint32_t*)(g_w1l + r0 * 192 + ka + 8);
        alr[3] = *(const uint32_t*)(g_w1l + (r0 + 8) * 192 + ka + 8);
#pragma unroll
        for (int n = 0; n < 8; n++) {
            const int j = n * 8 + g;
            uint32_t bh0 = *(const uint32_t*)&XH[j * XS + ka];
            uint32_t bh1 = *(const uint32_t*)&XH[j * XS + ka + 8];
            uint32_t bl0 = *(const uint32_t*)&XL[j * XS + ka];
            uint32_t bl1 = *(const uint32_t*)&XL[j * XS + ka + 8];
            MMA4(ac[n], ah, bh0, bh1);
            MMA4(ac[n], ah, bl0, bl1);
            MMA4(ac[n], alr, bh0, bh1);
        }
    }
    // epilogue 1: relu(+b1), split, store HID[j][c1] (transposed scatter)
    {
        const float bA = b1[r0], bB = b1[r0 + 8];
#pragma unroll
        for (int n = 0; n < 8; n++) {
            const int j0 = n * 8 + 2 * t4;
            STSP(j0 * HS + r0,           fmaxf(ac[n][0] + bA, 0.f));
            STSP((j0 + 1) * HS + r0,     fmaxf(ac[n][1] + bA, 0.f));
            STSP(j0 * HS + r0 + 8,       fmaxf(ac[n][2] + bB, 0.f));
            STSP((j0 + 1) * HS + r0 + 8, fmaxf(ac[n][3] + bB, 0.f));
        }
    }
    __syncthreads();

    // ---- layer 2: two half-passes (hf=0: mean cols, hf=1: max cols), K=128
    const int gag = *agp;
    const bool isag = (i == gag);
#pragma unroll 1
    for (int hf = 0; hf < 2; hf++) {
        const int rr = hf * 128 + w * 16 + g;
#pragma unroll
        for (int n = 0; n < 8; n++) { ac[n][0] = 0.f; ac[n][1] = 0.f; ac[n][2] = 0.f; ac[n][3] = 0.f; }
#pragma unroll 1
        for (int ks = 0; ks < 8; ks++) {
            const int ka = ks * 16 + 2 * t4;
            uint32_t ah[4], alr[4];
            ah[0] = *(const uint32_t*)(g_w2h + rr * 128 + ka);
            ah[1] = *(const uint32_t*)(g_w2h + (rr + 8) * 128 + ka);
            ah[2] = *(const uint32_t*)(g_w2h + rr * 128 + ka + 8);
            ah[3] = *(const uint32_t*)(g_w2h + (rr + 8) * 128 + ka + 8);
            alr[0] = *(const uint32_t*)(g_w2l + rr * 128 + ka);
            alr[1] = *(const uint32_t*)(g_w2l + (rr + 8) * 128 + ka);
            alr[2] = *(const uint32_t*)(g_w2l + rr * 128 + ka + 8);
            alr[3] = *(const uint32_t*)(g_w2l + (rr + 8) * 128 + ka + 8);
#pragma unroll
            for (int n = 0; n < 8; n++) {
                const int j = n * 8 + g;
                uint32_t bh0 = *(const uint32_t*)&HIh[j * HS + ka];
                uint32_t bh1 = *(const uint32_t*)&HIh[j * HS + ka + 8];
                uint32_t bl0 = *(const uint32_t*)&HIl[j * HS + ka];
                uint32_t bl1 = *(const uint32_t*)&HIl[j * HS + ka + 8];
                MMA4(ac[n], ah, bh0, bh1);
                MMA4(ac[n], ah, bl0, bl1);
                MMA4(ac[n], alr, bh0, bh1);
            }
        }
        // epilogue 2: relu(+b2), agent store, in-warp masked mean/max over j
        const float bA = b2[rr], bB = b2[rr + 8];
        float s0 = 0.f, s1 = 0.f;
#pragma unroll
        for (int n = 0; n < 8; n++) {
            const int j0 = n * 8 + 2 * t4;
            const float al0 = sal[j0], al1 = sal[j0 + 1];
            float v0 = fmaxf(ac[n][0] + bA, 0.f), v1 = fmaxf(ac[n][1] + bA, 0.f);
            float v2 = fmaxf(ac[n][2] + bB, 0.f), v3 = fmaxf(ac[n][3] + bB, 0.f);
            if (isag) {
                float* rg = g_ragent + (size_t)(b * 64) * 256;
                rg[(size_t)j0 * 256 + rr] = v0;
                rg[(size_t)(j0 + 1) * 256 + rr] = v1;
                rg[(size_t)j0 * 256 + rr + 8] = v2;
                rg[(size_t)(j0 + 1) * 256 + rr + 8] = v3;
            }
            if (hf == 0) {
                s0 += v0 * al0 + v1 * al1;
                s1 += v2 * al0 + v3 * al1;
            } else {
                s0 = fmaxf(s0, fmaxf(v0 * al0, v1 * al1));
                s1 = fmaxf(s1, fmaxf(v2 * al0, v3 * al1));
            }
        }
        if (hf == 0) {
            s0 += __shfl_xor_sync(0xffffffffu, s0, 1); s0 += __shfl_xor_sync(0xffffffffu, s0, 2);
            s1 += __shfl_xor_sync(0xffffffffu, s1, 1); s1 += __shfl_xor_sync(0xffffffffu, s1, 2);
            if (t4 == 0) {
                g_pooled[(size_t)bi * 256 + rr] = s0 * (1.f / 64.f);
                g_pooled[(size_t)bi * 256 + rr + 8] = s1 * (1.f / 64.f);
            }
        } else {
            s0 = fmaxf(s0, __shfl_xor_sync(0xffffffffu, s0, 1)); s0 = fmaxf(s0, __shfl_xor_sync(0xffffffffu, s0, 2));
            s1 = fmaxf(s1, __shfl_xor_sync(0xffffffffu, s1, 1)); s1 = fmaxf(s1, __shfl_xor_sync(0xffffffffu, s1, 2));
            if (t4 == 0) {
                g_pooled[(size_t)bi * 256 + rr] = s0;
                g_pooled[(size_t)bi * 256 + rr + 8] = s1;
            }
        }
    }
}

// ---------------- k_ra: 8 rows/block, split-K, grid 256 ----------------
__global__ __launch_bounds__(256) void k_ra(const float* __restrict__ w, const float* __restrict__ bias)
{
    __shared__ float X[8 * K3];
    __shared__ float RED[2 * 8 * H];
    const int row0 = blockIdx.x * 8, t = threadIdx.x;
    for (int i = t; i < 8 * H; i += 256) {
        int j = i >> 7, h2 = i & 127;
        X[j * K3 + h2] = g_s1[(size_t)(row0 + j) * H + h2];
    }
    for (int i = t; i < 8 * 2 * H; i += 256) {
        int j = i >> 8, h2 = i & 255;
        X[j * K3 + H + h2] = g_pooled[(size_t)(row0 + j) * (2 * H) + h2];
    }
    __syncthreads();
    const int h = t & 127, kh = t >> 7;
    float acc[8];
#pragma unroll
    for (int j = 0; j < 8; j++) acc[j] = 0.f;
    const float4* X4 = (const float4*)X;
    const int k0 = kh * 192;
#pragma unroll 4
    for (int k = k0; k < k0 + 192; k += 4) {
        float w0 = w[k * H + h], wA = w[(k + 1) * H + h], wB = w[(k + 2) * H + h], wC = w[(k + 3) * H + h];
#pragma unroll
        for (int j = 0; j < 8; j++) {
            float4 x = X4[j * (K3 / 4) + (k >> 2)];
            acc[j] = fmaf(x.x, w0, acc[j]); acc[j] = fmaf(x.y, wA, acc[j]);
            acc[j] = fmaf(x.z, wB, acc[j]); acc[j] = fmaf(x.w, wC, acc[j]);
        }
    }
#pragma unroll
    for (int j = 0; j < 8; j++) RED[(kh * 8 + j) * H + h] = acc[j];
    __syncthreads();
    for (int idx = t; idx < 8 * H; idx += 256)
        g_s2[(size_t)(row0 + (idx >> 7)) * H + (idx & 127)] =
            fmaxf(RED[idx] + RED[8 * H + idx] + bias[idx & 127], 0.f);
}

// ---------------- k_ae: 8 rows/block, split-K L1, grid 256 ----------------
__global__ __launch_bounds__(256) void k_ae(
    const float* __restrict__ w1, const float* __restrict__ b1,
    const float* __restrict__ w2, const float* __restrict__ b2,
    const int* __restrict__ agp)
{
    __shared__ float X[8 * K4];
    __shared__ float HD[8 * H];
    __shared__ float RED[2 * 8 * H];
    const int row0 = blockIdx.x * 8, b = row0 >> 6, t = threadIdx.x;
    const int g = *agp;
    for (int i = t; i < 8 * 2 * H; i += 256) {
        int j = i >> 8, h2 = i & 255;
        X[j * K4 + h2] = g_ragent[(size_t)(row0 + j) * (2 * H) + h2];
    }
    for (int i = t; i < 8 * H; i += 256) {
        int j = i >> 7, h2 = i & 127;
        X[j * K4 + 2 * H + h2] = g_s2[(size_t)(row0 + j) * H + h2];
        X[j * K4 + 3 * H + h2] = g_s2[((size_t)b * A + g) * H + h2];
    }
    __syncthreads();
    const int h = t & 127, kh = t >> 7;
    {
        float acc[8];
#pragma unroll
        for (int j = 0; j < 8; j++) acc[j] = 0.f;
        const float4* X4 = (const float4*)X;
        const int k0 = kh * 256;
#pragma unroll 4
        for (int k = k0; k < k0 + 256; k += 4) {
            float w0 = w1[k * H + h], wA = w1[(k + 1) * H + h], wB = w1[(k + 2) * H + h], wC = w1[(k + 3) * H + h];
#pragma unroll
            for (int j = 0; j < 8; j++) {
                float4 x = X4[j * (K4 / 4) + (k >> 2)];
                acc[j] = fmaf(x.x, w0, acc[j]); acc[j] = fmaf(x.y, wA, acc[j]);
                acc[j] = fmaf(x.z, wB, acc[j]); acc[j] = fmaf(x.w, wC, acc[j]);
            }
        }
#pragma unroll
        for (int j = 0; j < 8; j++) RED[(kh * 8 + j) * H + h] = acc[j];
    }
    __syncthreads();
    for (int idx = t; idx < 8 * H; idx += 256)
        HD[idx] = fmaxf(RED[idx] + RED[8 * H + idx] + b1[idx & 127], 0.f);
    __syncthreads();
    {
        const int c = t;  // 0..255 output col
        float acc2[8];
        const float bb = b2[c];
#pragma unroll
        for (int j = 0; j < 8; j++) acc2[j] = bb;
        const float4* H4 = (const float4*)HD;
#pragma unroll 4
        for (int k = 0; k < H; k += 4) {
            float w0 = w2[k * 256 + c], wA = w2[(k + 1) * 256 + c], wB = w2[(k + 2) * 256 + c], wC = w2[(k + 3) * 256 + c];
#pragma unroll
            for (int j = 0; j < 8; j++) {
                float4 x = H4[j * (H / 4) + (k >> 2)];
                acc2[j] = fmaf(x.x, w0, acc2[j]); acc2[j] = fmaf(x.y, wA, acc2[j]);
                acc2[j] = fmaf(x.z, wB, acc2[j]); acc2[j] = fmaf(x.w, wC, acc2[j]);
            }
        }
#pragma unroll
        for (int j = 0; j < 8; j++)
            g_ae[(size_t)(row0 + j) * (2 * H) + c] = fmaxf(acc2[j], 0.f);
    }
}

// ---------------- k_final ----------------
__global__ __launch_bounds__(128) void k_final(
    const float* __restrict__ action_embed, const int* __restrict__ action,
    const int* __restrict__ agp, float* __restrict__ out)
{
    const int b = blockIdx.x, h = threadIdx.x;
    const int a = action[b], g = *agp;
    const float sel = (a < E) ? action_embed[a * H + h]
                              : g_ae[((size_t)b * A + (a - E)) * (2 * H) + h];
    float* out_state = out;
    float* out_sel = out + (size_t)B * A * H;
    float* out_ps = out_sel + (size_t)B * H;
    out_sel[b * H + h] = sel;
    for (int j = 0; j < A; j++) {
        float st = g_s2[((size_t)b * A + j) * H + h];
        float ps = 0.f;
        if (a == E + j) ps = g_ae[((size_t)b * A + j) * (2 * H) + H + h];
        if (j == g) st += sel;
        out_ps[((size_t)b * A + j) * H + h] = ps;
        out_state[((size_t)b * A + j) * H + h] = st + ps;
    }
}

// ---------------- launcher ----------------
extern "C" void kernel_launch(void* const* d_in, const int* in_sizes, int n_in,
                              void* d_out, int out_size)
{
    const float* states       = (const float*)d_in[0];
    const float* relations    = (const float*)d_in[1];
    const float* alive_mask   = (const float*)d_in[2];
    const float* se_w1        = (const float*)d_in[3];
    const float* se_b1        = (const float*)d_in[4];
    const float* se_w2        = (const float*)d_in[5];
    const float* se_b2        = (const float*)d_in[6];
    const float* re_w1        = (const float*)d_in[7];
    const float* re_b1        = (const float*)d_in[8];
    const float* re_w2        = (const float*)d_in[9];
    const float* re_b2        = (const float*)d_in[10];
    const float* ra_w         = (const float*)d_in[11];
    const float* ra_b         = (const float*)d_in[12];
    const float* ae_w1        = (const float*)d_in[13];
    const float* ae_b1        = (const float*)d_in[14];
    const float* ae_w2        = (const float*)d_in[15];
    const float* ae_b2        = (const float*)d_in[16];
    const float* action_embed = (const float*)d_in[17];
    const int*   action       = (const int*)d_in[19];
    const int*   agent_id     = (const int*)d_in[20];
    float* out = (float*)d_out;

    static bool attr = false;
    if (!attr) {
        cudaFuncSetAttribute(k_rel, cudaFuncAttributeMaxDynamicSharedMemorySize, SM_REL);
        attr = true;
    }

    k_prep<<<64, 256>>>(re_w1, re_w2);
    k_state_enc<<<(B * A) / 8, 256>>>(states, se_w1, se_b1, se_w2, se_b2);
    k_rel<<<B * A, 256, SM_REL>>>(relations, alive_mask, re_b1, re_b2, agent_id);
    k_ra<<<(B * A) / 8, 256>>>(ra_w, ra_b);
    k_ae<<<(B * A) / 8, 256>>>(ae_w1, ae_b1, ae_w2, ae_b2, agent_id);
    k_final<<<B, 128>>>(action_embed, action, agent_id, out);
}

// round 6
// speedup vs baseline: 2.5679x; 1.1584x over previous
#include <cuda_runtime.h>
#include <cuda_bf16.h>
#include <cstdint>

#define B 32
#define A 64
#define SLEN 256
#define H 128
#define RLEN 64
#define E 16
#define K3 (3 * H)
#define K4 (4 * H)

__device__ float g_s1[B * A * H];
__device__ float g_Cs[B * H * A];          // [b][c][j] : (s1[b] @ w1[64:])^T
__device__ float g_pooled[B * A * 2 * H];
__device__ float g_ragent[B * A * 2 * H];
__device__ float g_s2[B * A * H];
__device__ float g_ae[B * A * 2 * H];
__device__ __align__(16) __nv_bfloat16 g_w1h[128 * 192];   // w1^T [n][k], only k<64 used by k_rel
__device__ __align__(16) __nv_bfloat16 g_w1l[128 * 192];
__device__ __align__(16) __nv_bfloat16 g_w2h[256 * 128];
__device__ __align__(16) __nv_bfloat16 g_w2l[256 * 128];

#define MMA4(d, a, b0, b1) asm volatile( \
    "mma.sync.aligned.m16n8k16.row.col.f32.bf16.bf16.f32 " \
    "{%0,%1,%2,%3},{%4,%5,%6,%7},{%8,%9},{%0,%1,%2,%3};" \
    : "+f"((d)[0]), "+f"((d)[1]), "+f"((d)[2]), "+f"((d)[3]) \
    : "r"((a)[0]), "r"((a)[1]), "r"((a)[2]), "r"((a)[3]), "r"(b0), "r"(b1))

// ---------------- k_prep ----------------
__global__ void k_prep(const float* __restrict__ w1, const float* __restrict__ w2)
{
    const int stride = gridDim.x * blockDim.x;
    int tid = blockIdx.x * blockDim.x + threadIdx.x;
    for (int idx = tid; idx < 128 * 192; idx += stride) {
        int n = idx / 192, k = idx % 192;
        float v = w1[k * 128 + n];
        __nv_bfloat16 h = __float2bfloat16(v);
        g_w1h[idx] = h;
        g_w1l[idx] = __float2bfloat16(v - __bfloat162float(h));
    }
    for (int idx = tid; idx < 256 * 128; idx += stride) {
        int n = idx / 128, k = idx % 128;
        float v = w2[k * 256 + n];
        __nv_bfloat16 h = __float2bfloat16(v);
        g_w2h[idx] = h;
        g_w2l[idx] = __float2bfloat16(v - __bfloat162float(h));
    }
}

// ---------------- k_state_enc: 4 rows/block, grid 512, split-K ----------------
__global__ __launch_bounds__(256) void k_state_enc(
    const float* __restrict__ st, const float* __restrict__ w1, const float* __restrict__ b1,
    const float* __restrict__ w2, const float* __restrict__ b2)
{
    __shared__ float X[4 * SLEN];
    __shared__ float HD[4 * H];
    __shared__ float RED[2 * 4 * H];
    const int row0 = blockIdx.x * 4, t = threadIdx.x;
    for (int i = t; i < 4 * SLEN; i += 256) X[i] = st[(size_t)row0 * SLEN + i];
    __syncthreads();
    const int h = t & 127, kh = t >> 7;
    {
        float acc[4] = {0.f, 0.f, 0.f, 0.f};
        const float4* X4 = (const float4*)X;
        const int k0 = kh * 128;
#pragma unroll 4
        for (int k = k0; k < k0 + 128; k += 4) {
            float w0 = w1[k * H + h], wA = w1[(k + 1) * H + h], wB = w1[(k + 2) * H + h], wC = w1[(k + 3) * H + h];
#pragma unroll
            for (int j = 0; j < 4; j++) {
                float4 x = X4[j * (SLEN / 4) + (k >> 2)];
                acc[j] = fmaf(x.x, w0, acc[j]); acc[j] = fmaf(x.y, wA, acc[j]);
                acc[j] = fmaf(x.z, wB, acc[j]); acc[j] = fmaf(x.w, wC, acc[j]);
            }
        }
#pragma unroll
        for (int j = 0; j < 4; j++) RED[(kh * 4 + j) * H + h] = acc[j];
    }
    __syncthreads();
    for (int idx = t; idx < 4 * H; idx += 256)
        HD[idx] = fmaxf(RED[idx] + RED[4 * H + idx] + b1[idx & 127], 0.f);
    __syncthreads();
    {
        const int rb = kh * 2;
        float acc[2];
        const float bb = b2[h];
        acc[0] = bb; acc[1] = bb;
        const float4* H4 = (const float4*)HD;
#pragma unroll 4
        for (int k = 0; k < H; k += 4) {
            float w0 = w2[k * H + h], wA = w2[(k + 1) * H + h], wB = w2[(k + 2) * H + h], wC = w2[(k + 3) * H + h];
#pragma unroll
            for (int j = 0; j < 2; j++) {
                float4 x = H4[(rb + j) * (H / 4) + (k >> 2)];
                acc[j] = fmaf(x.x, w0, acc[j]); acc[j] = fmaf(x.y, wA, acc[j]);
                acc[j] = fmaf(x.z, wB, acc[j]); acc[j] = fmaf(x.w, wC, acc[j]);
            }
        }
#pragma unroll
        for (int j = 0; j < 2; j++) g_s1[(size_t)(row0 + rb + j) * H + h] = fmaxf(acc[j], 0.f);
    }
}

// ---------------- k_smm: Cs[b][c][j] = sum_k s1[b,j,k] * w1[64+k][c] ----------------
__global__ __launch_bounds__(512) void k_smm(const float* __restrict__ w1)
{
    __shared__ float S[64 * 128];
    const int b = blockIdx.x, t = threadIdx.x;
    for (int i = t; i < 64 * 128; i += 512) S[i] = g_s1[(size_t)b * 8192 + i];
    __syncthreads();
    const int c = t & 127, jh = t >> 7;  // jh in [0,4): 16 j each
    float acc[16];
#pragma unroll
    for (int j = 0; j < 16; j++) acc[j] = 0.f;
    const float4* S4 = (const float4*)S;
#pragma unroll 2
    for (int k4 = 0; k4 < 32; k4++) {
        const int k = 4 * k4;
        float w0 = w1[(64 + k) * 128 + c], wA = w1[(65 + k) * 128 + c];
        float wB = w1[(66 + k) * 128 + c], wC = w1[(67 + k) * 128 + c];
#pragma unroll
        for (int j = 0; j < 16; j++) {
            float4 s = S4[(jh * 16 + j) * 32 + k4];
            acc[j] = fmaf(s.x, w0, acc[j]); acc[j] = fmaf(s.y, wA, acc[j]);
            acc[j] = fmaf(s.z, wB, acc[j]); acc[j] = fmaf(s.w, wC, acc[j]);
        }
    }
#pragma unroll
    for (int j = 0; j < 16; j++)
        g_Cs[(size_t)b * 8192 + c * 64 + jh * 16 + j] = acc[j];
}

// ---------------- k_rel: rel-only layer1 (K=64) + Cs add, 3 CTA/SM ----------------
// smem: XH @0 (64x72 bf16 = 9216), XL @9216, HIh @18432 (64x136 = 17408),
//       HIl @35840, sal @53248 (256). total 53504.
#define HS 136
#define XS 72
#define SM_REL 53504
#define STSP(idx, v) { float _v = (v); __nv_bfloat16 _h = __float2bfloat16(_v); \
    HIh[idx] = _h; HIl[idx] = __float2bfloat16(_v - __bfloat162float(_h)); }

__global__ __launch_bounds__(256, 3) void k_rel(
    const float* __restrict__ rel, const float* __restrict__ alive,
    const float* __restrict__ b1, const float* __restrict__ b2,
    const int* __restrict__ agp)
{
    extern __shared__ unsigned char smem[];
    __nv_bfloat16* XH = (__nv_bfloat16*)smem;
    __nv_bfloat16* XL = (__nv_bfloat16*)(smem + 9216);
    __nv_bfloat16* HIh = (__nv_bfloat16*)(smem + 18432);
    __nv_bfloat16* HIl = (__nv_bfloat16*)(smem + 35840);
    float* sal = (float*)(smem + 53248);

    const int tid = threadIdx.x, w = tid >> 5, l = tid & 31, g = l >> 2, t4 = l & 3;
    const int bi = blockIdx.x, b = bi >> 6, i = bi & 63;
    if (tid < 64) sal[tid] = alive[b * 64 + tid];

    // stage rel part of X, split bf16 hi/lo
    {
        const float* rr = rel + (size_t)bi * 64 * 64;
        for (int idx = tid; idx < 64 * 64; idx += 256) {
            const int j = idx >> 6, k = idx & 63;
            float v = rr[idx];
            __nv_bfloat16 hh = __float2bfloat16(v);
            XH[j * XS + k] = hh;
            XL[j * XS + k] = __float2bfloat16(v - __bfloat162float(hh));
        }
    }
    __syncthreads();

    float ac[8][4];
#pragma unroll
    for (int n = 0; n < 8; n++) { ac[n][0] = 0.f; ac[n][1] = 0.f; ac[n][2] = 0.f; ac[n][3] = 0.f; }
    const int r0 = w * 16 + g;

    // layer 1 (rel part only): K=64, 4 ksteps
#pragma unroll 1
    for (int ks = 0; ks < 4; ks++) {
        const int ka = ks * 16 + 2 * t4;
        uint32_t ah[4], alr[4];
        ah[0] = *(const uint32_t*)(g_w1h + r0 * 192 + ka);
        ah[1] = *(const uint32_t*)(g_w1h + (r0 + 8) * 192 + ka);
        ah[2] = *(const uint32_t*)(g_w1h + r0 * 192 + ka + 8);
        ah[3] = *(const uint32_t*)(g_w1h + (r0 + 8) * 192 + ka + 8);
        alr[0] = *(const uint32_t*)(g_w1l + r0 * 192 + ka);
        alr[1] = *(const uint32_t*)(g_w1l + (r0 + 8) * 192 + ka);
        alr[2] = *(const uint32_t*)(g_w1l + r0 * 192 + ka + 8);
        alr[3] = *(const uint32_t*)(g_w1l + (r0 + 8) * 192 + ka + 8);
#pragma unroll
        for (int n = 0; n < 8; n++) {
            const int j = n * 8 + g;
            uint32_t bh0 = *(const uint32_t*)&XH[j * XS + ka];
            uint32_t bh1 = *(const uint32_t*)&XH[j * XS + ka + 8];
            uint32_t bl0 = *(const uint32_t*)&XL[j * XS + ka];
            uint32_t bl1 = *(const uint32_t*)&XL[j * XS + ka + 8];
            MMA4(ac[n], ah, bh0, bh1);
            MMA4(ac[n], ah, bl0, bl1);
            MMA4(ac[n], alr, bh0, bh1);
        }
    }
    // epilogue 1: add Cs (s1-part, hoisted per-b) + b1, relu, split-store HID^T
    {
        const float bA = b1[r0], bB = b1[r0 + 8];
        const float* csA = g_Cs + (size_t)b * 8192 + r0 * 64;
        const float* csB = csA + 8 * 64;
#pragma unroll
        for (int n = 0; n < 8; n++) {
            const int j0 = n * 8 + 2 * t4;
            float2 cA = *(const float2*)(csA + j0);
            float2 cB = *(const float2*)(csB + j0);
            STSP(j0 * HS + r0,           fmaxf(ac[n][0] + cA.x + bA, 0.f));
            STSP((j0 + 1) * HS + r0,     fmaxf(ac[n][1] + cA.y + bA, 0.f));
            STSP(j0 * HS + r0 + 8,       fmaxf(ac[n][2] + cB.x + bB, 0.f));
            STSP((j0 + 1) * HS + r0 + 8, fmaxf(ac[n][3] + cB.y + bB, 0.f));
        }
    }
    __syncthreads();

    // layer 2: two half-passes (mean cols / max cols), K=128
    const int gag = *agp;
    const bool isag = (i == gag);
#pragma unroll 1
    for (int hf = 0; hf < 2; hf++) {
        const int rr = hf * 128 + w * 16 + g;
#pragma unroll
        for (int n = 0; n < 8; n++) { ac[n][0] = 0.f; ac[n][1] = 0.f; ac[n][2] = 0.f; ac[n][3] = 0.f; }
#pragma unroll 1
        for (int ks = 0; ks < 8; ks++) {
            const int ka = ks * 16 + 2 * t4;
            uint32_t ah[4], alr[4];
            ah[0] = *(const uint32_t*)(g_w2h + rr * 128 + ka);
            ah[1] = *(const uint32_t*)(g_w2h + (rr + 8) * 128 + ka);
            ah[2] = *(const uint32_t*)(g_w2h + rr * 128 + ka + 8);
            ah[3] = *(const uint32_t*)(g_w2h + (rr + 8) * 128 + ka + 8);
            alr[0] = *(const uint32_t*)(g_w2l + rr * 128 + ka);
            alr[1] = *(const uint32_t*)(g_w2l + (rr + 8) * 128 + ka);
            alr[2] = *(const uint32_t*)(g_w2l + rr * 128 + ka + 8);
            alr[3] = *(const uint32_t*)(g_w2l + (rr + 8) * 128 + ka + 8);
#pragma unroll
            for (int n = 0; n < 8; n++) {
                const int j = n * 8 + g;
                uint32_t bh0 = *(const uint32_t*)&HIh[j * HS + ka];
                uint32_t bh1 = *(const uint32_t*)&HIh[j * HS + ka + 8];
                uint32_t bl0 = *(const uint32_t*)&HIl[j * HS + ka];
                uint32_t bl1 = *(const uint32_t*)&HIl[j * HS + ka + 8];
                MMA4(ac[n], ah, bh0, bh1);
                MMA4(ac[n], ah, bl0, bl1);
                MMA4(ac[n], alr, bh0, bh1);
            }
        }
        const float bA = b2[rr], bB = b2[rr + 8];
        float s0 = 0.f, s1 = 0.f;
#pragma unroll
        for (int n = 0; n < 8; n++) {
            const int j0 = n * 8 + 2 * t4;
            const float al0 = sal[j0], al1 = sal[j0 + 1];
            float v0 = fmaxf(ac[n][0] + bA, 0.f), v1 = fmaxf(ac[n][1] + bA, 0.f);
            float v2 = fmaxf(ac[n][2] + bB, 0.f), v3 = fmaxf(ac[n][3] + bB, 0.f);
            if (isag) {
                float* rg = g_ragent + (size_t)(b * 64) * 256;
                rg[(size_t)j0 * 256 + rr] = v0;
                rg[(size_t)(j0 + 1) * 256 + rr] = v1;
                rg[(size_t)j0 * 256 + rr + 8] = v2;
                rg[(size_t)(j0 + 1) * 256 + rr + 8] = v3;
            }
            if (hf == 0) {
                s0 += v0 * al0 + v1 * al1;
                s1 += v2 * al0 + v3 * al1;
            } else {
                s0 = fmaxf(s0, fmaxf(v0 * al0, v1 * al1));
                s1 = fmaxf(s1, fmaxf(v2 * al0, v3 * al1));
            }
        }
        if (hf == 0) {
            s0 += __shfl_xor_sync(0xffffffffu, s0, 1); s0 += __shfl_xor_sync(0xffffffffu, s0, 2);
            s1 += __shfl_xor_sync(0xffffffffu, s1, 1); s1 += __shfl_xor_sync(0xffffffffu, s1, 2);
            if (t4 == 0) {
                g_pooled[(size_t)bi * 256 + rr] = s0 * (1.f / 64.f);
                g_pooled[(size_t)bi * 256 + rr + 8] = s1 * (1.f / 64.f);
            }
        } else {
            s0 = fmaxf(s0, __shfl_xor_sync(0xffffffffu, s0, 1)); s0 = fmaxf(s0, __shfl_xor_sync(0xffffffffu, s0, 2));
            s1 = fmaxf(s1, __shfl_xor_sync(0xffffffffu, s1, 1)); s1 = fmaxf(s1, __shfl_xor_sync(0xffffffffu, s1, 2));
            if (t4 == 0) {
                g_pooled[(size_t)bi * 256 + rr] = s0;
                g_pooled[(size_t)bi * 256 + rr + 8] = s1;
            }
        }
    }
}

// ---------------- k_ra: 4 rows/block, grid 512, split-K ----------------
__global__ __launch_bounds__(256) void k_ra(const float* __restrict__ w, const float* __restrict__ bias)
{
    __shared__ float X[4 * K3];
    __shared__ float RED[2 * 4 * H];
    const int row0 = blockIdx.x * 4, t = threadIdx.x;
    for (int i = t; i < 4 * H; i += 256) {
        int j = i >> 7, h2 = i & 127;
        X[j * K3 + h2] = g_s1[(size_t)(row0 + j) * H + h2];
    }
    for (int i = t; i < 4 * 2 * H; i += 256) {
        int j = i >> 8, h2 = i & 255;
        X[j * K3 + H + h2] = g_pooled[(size_t)(row0 + j) * (2 * H) + h2];
    }
    __syncthreads();
    const int h = t & 127, kh = t >> 7;
    float acc[4] = {0.f, 0.f, 0.f, 0.f};
    const float4* X4 = (const float4*)X;
    const int k0 = kh * 192;
#pragma unroll 4
    for (int k = k0; k < k0 + 192; k += 4) {
        float w0 = w[k * H + h], wA = w[(k + 1) * H + h], wB = w[(k + 2) * H + h], wC = w[(k + 3) * H + h];
#pragma unroll
        for (int j = 0; j < 4; j++) {
            float4 x = X4[j * (K3 / 4) + (k >> 2)];
            acc[j] = fmaf(x.x, w0, acc[j]); acc[j] = fmaf(x.y, wA, acc[j]);
            acc[j] = fmaf(x.z, wB, acc[j]); acc[j] = fmaf(x.w, wC, acc[j]);
        }
    }
#pragma unroll
    for (int j = 0; j < 4; j++) RED[(kh * 4 + j) * H + h] = acc[j];
    __syncthreads();
    for (int idx = t; idx < 4 * H; idx += 256)
        g_s2[(size_t)(row0 + (idx >> 7)) * H + (idx & 127)] =
            fmaxf(RED[idx] + RED[4 * H + idx] + bias[idx & 127], 0.f);
}

// ---------------- k_ae: 4 rows/block, grid 512, split-K L1 ----------------
__global__ __launch_bounds__(256) void k_ae(
    const float* __restrict__ w1, const float* __restrict__ b1,
    const float* __restrict__ w2, const float* __restrict__ b2,
    const int* __restrict__ agp)
{
    __shared__ float X[4 * K4];
    __shared__ float HD[4 * H];
    __shared__ float RED[2 * 4 * H];
    const int row0 = blockIdx.x * 4, b = row0 >> 6, t = threadIdx.x;
    const int g = *agp;
    for (int i = t; i < 4 * 2 * H; i += 256) {
        int j = i >> 8, h2 = i & 255;
        X[j * K4 + h2] = g_ragent[(size_t)(row0 + j) * (2 * H) + h2];
    }
    for (int i = t; i < 4 * H; i += 256) {
        int j = i >> 7, h2 = i & 127;
        X[j * K4 + 2 * H + h2] = g_s2[(size_t)(row0 + j) * H + h2];
        X[j * K4 + 3 * H + h2] = g_s2[((size_t)b * A + g) * H + h2];
    }
    __syncthreads();
    const int h = t & 127, kh = t >> 7;
    {
        float acc[4] = {0.f, 0.f, 0.f, 0.f};
        const float4* X4 = (const float4*)X;
        const int k0 = kh * 256;
#pragma unroll 4
        for (int k = k0; k < k0 + 256; k += 4) {
            float w0 = w1[k * H + h], wA = w1[(k + 1) * H + h], wB = w1[(k + 2) * H + h], wC = w1[(k + 3) * H + h];
#pragma unroll
            for (int j = 0; j < 4; j++) {
                float4 x = X4[j * (K4 / 4) + (k >> 2)];
                acc[j] = fmaf(x.x, w0, acc[j]); acc[j] = fmaf(x.y, wA, acc[j]);
                acc[j] = fmaf(x.z, wB, acc[j]); acc[j] = fmaf(x.w, wC, acc[j]);
            }
        }
#pragma unroll
        for (int j = 0; j < 4; j++) RED[(kh * 4 + j) * H + h] = acc[j];
    }
    __syncthreads();
    for (int idx = t; idx < 4 * H; idx += 256)
        HD[idx] = fmaxf(RED[idx] + RED[4 * H + idx] + b1[idx & 127], 0.f);
    __syncthreads();
    {
        const int c = t;
        float acc2[4];
        const float bb = b2[c];
#pragma unroll
        for (int j = 0; j < 4; j++) acc2[j] = bb;
        const float4* H4 = (const float4*)HD;
#pragma unroll 4
        for (int k = 0; k < H; k += 4) {
            float w0 = w2[k * 256 + c], wA = w2[(k + 1) * 256 + c], wB = w2[(k + 2) * 256 + c], wC = w2[(k + 3) * 256 + c];
#pragma unroll
            for (int j = 0; j < 4; j++) {
                float4 x = H4[j * (H / 4) + (k >> 2)];
                acc2[j] = fmaf(x.x, w0, acc2[j]); acc2[j] = fmaf(x.y, wA, acc2[j]);
                acc2[j] = fmaf(x.z, wB, acc2[j]); acc2[j] = fmaf(x.w, wC, acc2[j]);
            }
        }
#pragma unroll
        for (int j = 0; j < 4; j++)
            g_ae[(size_t)(row0 + j) * (2 * H) + c] = fmaxf(acc2[j], 0.f);
    }
}

// ---------------- k_final ----------------
__global__ __launch_bounds__(128) void k_final(
    const float* __restrict__ action_embed, const int* __restrict__ action,
    const int* __restrict__ agp, float* __restrict__ out)
{
    const int b = blockIdx.x, h = threadIdx.x;
    const int a = action[b], g = *agp;
    const float sel = (a < E) ? action_embed[a * H + h]
                              : g_ae[((size_t)b * A + (a - E)) * (2 * H) + h];
    float* out_state = out;
    float* out_sel = out + (size_t)B * A * H;
    float* out_ps = out_sel + (size_t)B * H;
    out_sel[b * H + h] = sel;
    for (int j = 0; j < A; j++) {
        float st = g_s2[((size_t)b * A + j) * H + h];
        float ps = 0.f;
        if (a == E + j) ps = g_ae[((size_t)b * A + j) * (2 * H) + H + h];
        if (j == g) st += sel;
        out_ps[((size_t)b * A + j) * H + h] = ps;
        out_state[((size_t)b * A + j) * H + h] = st + ps;
    }
}

// ---------------- launcher ----------------
extern "C" void kernel_launch(void* const* d_in, const int* in_sizes, int n_in,
                              void* d_out, int out_size)
{
    const float* states       = (const float*)d_in[0];
    const float* relations    = (const float*)d_in[1];
    const float* alive_mask   = (const float*)d_in[2];
    const float* se_w1        = (const float*)d_in[3];
    const float* se_b1        = (const float*)d_in[4];
    const float* se_w2        = (const float*)d_in[5];
    const float* se_b2        = (const float*)d_in[6];
    const float* re_w1        = (const float*)d_in[7];
    const float* re_b1        = (const float*)d_in[8];
    const float* re_w2        = (const float*)d_in[9];
    const float* re_b2        = (const float*)d_in[10];
    const float* ra_w         = (const float*)d_in[11];
    const float* ra_b         = (const float*)d_in[12];
    const float* ae_w1        = (const float*)d_in[13];
    const float* ae_b1        = (const float*)d_in[14];
    const float* ae_w2        = (const float*)d_in[15];
    const float* ae_b2        = (const float*)d_in[16];
    const float* action_embed = (const float*)d_in[17];
    const int*   action       = (const int*)d_in[19];
    const int*   agent_id     = (const int*)d_in[20];
    float* out = (float*)d_out;

    static bool attr = false;
    if (!attr) {
        cudaFuncSetAttribute(k_rel, cudaFuncAttributeMaxDynamicSharedMemorySize, SM_REL);
        attr = true;
    }

    k_prep<<<64, 256>>>(re_w1, re_w2);
    k_state_enc<<<(B * A) / 4, 256>>>(states, se_w1, se_b1, se_w2, se_b2);
    k_smm<<<B, 512>>>(re_w1);
    k_rel<<<B * A, 256, SM_REL>>>(relations, alive_mask, re_b1, re_b2, agent_id);
    k_ra<<<(B * A) / 4, 256>>>(ra_w, ra_b);
    k_ae<<<(B * A) / 4, 256>>>(ae_w1, ae_b1, ae_w2, ae_b2, agent_id);
    k_final<<<B, 128>>>(action_embed, action, agent_id, out);
}

// round 7
// speedup vs baseline: 3.4573x; 1.3463x over previous
#include <cuda_runtime.h>
#include <cuda_bf16.h>
#include <cstdint>

#define B 32
#define A 64
#define SLEN 256
#define H 128
#define RLEN 64
#define E 16
#define K3 (3 * H)
#define K4 (4 * H)

__device__ float g_s1[B * A * H];
__device__ float g_Cs[B * H * A];          // [b][c][j] : (s1[b] @ w1[64:])^T
__device__ float g_pooled[B * A * 2 * H];
__device__ float g_ragent[B * A * 2 * H];
__device__ float g_s2[B * A * H];
__device__ float g_ae[B * A * 2 * H];
// Fragment-ordered weight images: thread's 4 regs = one uint4.
// w1 (layer1, K=64): [slot=warp(8)][ks(4)][lane(32)]
__device__ __align__(16) uint4 g_w1fh[8 * 4 * 32];
__device__ __align__(16) uint4 g_w1fl[8 * 4 * 32];
// w2 (layer2, K=128, 256 out rows = 16 slots): [slot(16)][ks(8)][lane(32)]
__device__ __align__(16) uint4 g_w2fh[16 * 8 * 32];
__device__ __align__(16) uint4 g_w2fl[16 * 8 * 32];

#define MMA4(d, a, b0, b1) asm volatile( \
    "mma.sync.aligned.m16n8k16.row.col.f32.bf16.bf16.f32 " \
    "{%0,%1,%2,%3},{%4,%5,%6,%7},{%8,%9},{%0,%1,%2,%3};" \
    : "+f"((d)[0]), "+f"((d)[1]), "+f"((d)[2]), "+f"((d)[3]) \
    : "r"((a)[0]), "r"((a)[1]), "r"((a)[2]), "r"((a)[3]), "r"(b0), "r"(b1))

#define LDSM4(r, a) asm volatile( \
    "ldmatrix.sync.aligned.m8n8.x4.shared.b16 {%0,%1,%2,%3}, [%4];" \
    : "=r"((r)[0]), "=r"((r)[1]), "=r"((r)[2]), "=r"((r)[3]) : "r"(a))

__device__ __forceinline__ uint32_t s2u(const void* p) {
    uint32_t a;
    asm("{ .reg .u64 t; cvta.to.shared.u64 t, %1; cvt.u32.u64 %0, t; }" : "=r"(a) : "l"(p));
    return a;
}
__device__ __forceinline__ uint32_t pkhi(float a, float b) {
    __nv_bfloat162 t = __halves2bfloat162(__float2bfloat16(a), __float2bfloat16(b));
    return *reinterpret_cast<uint32_t*>(&t);
}
__device__ __forceinline__ uint32_t pklo(float a, float b) {
    float ra = a - __bfloat162float(__float2bfloat16(a));
    float rb = b - __bfloat162float(__float2bfloat16(b));
    __nv_bfloat162 t = __halves2bfloat162(__float2bfloat16(ra), __float2bfloat16(rb));
    return *reinterpret_cast<uint32_t*>(&t);
}

// ---------------- k_prep: fragment-ordered bf16-split weight images ----------------
__global__ void k_prep(const float* __restrict__ w1, const float* __restrict__ w2)
{
    const int stride = gridDim.x * blockDim.x;
    for (int tid = blockIdx.x * blockDim.x + threadIdx.x; tid < 1024 + 4096; tid += stride) {
        if (tid < 1024) {
            // w1 frag: i = (slot*4 + ks)*32 + lane
            const int i = tid, lane = i & 31, ks = (i >> 5) & 3, slot = i >> 7;
            const int r0 = slot * 16 + (lane >> 2), ka = ks * 16 + 2 * (lane & 3);
            float v00 = w1[ka * 128 + r0],       v01 = w1[(ka + 1) * 128 + r0];
            float v10 = w1[ka * 128 + r0 + 8],   v11 = w1[(ka + 1) * 128 + r0 + 8];
            float v20 = w1[(ka + 8) * 128 + r0], v21 = w1[(ka + 9) * 128 + r0];
            float v30 = w1[(ka + 8) * 128 + r0 + 8], v31 = w1[(ka + 9) * 128 + r0 + 8];
            g_w1fh[i] = make_uint4(pkhi(v00, v01), pkhi(v10, v11), pkhi(v20, v21), pkhi(v30, v31));
            g_w1fl[i] = make_uint4(pklo(v00, v01), pklo(v10, v11), pklo(v20, v21), pklo(v30, v31));
        } else {
            // w2 frag: i = (slot*8 + ks)*32 + lane
            const int i = tid - 1024, lane = i & 31, ks = (i >> 5) & 7, slot = i >> 8;
            const int rr = slot * 16 + (lane >> 2), ka = ks * 16 + 2 * (lane & 3);
            float v00 = w2[ka * 256 + rr],       v01 = w2[(ka + 1) * 256 + rr];
            float v10 = w2[ka * 256 + rr + 8],   v11 = w2[(ka + 1) * 256 + rr + 8];
            float v20 = w2[(ka + 8) * 256 + rr], v21 = w2[(ka + 9) * 256 + rr];
            float v30 = w2[(ka + 8) * 256 + rr + 8], v31 = w2[(ka + 9) * 256 + rr + 8];
            g_w2fh[i] = make_uint4(pkhi(v00, v01), pkhi(v10, v11), pkhi(v20, v21), pkhi(v30, v31));
            g_w2fl[i] = make_uint4(pklo(v00, v01), pklo(v10, v11), pklo(v20, v21), pklo(v30, v31));
        }
    }
}

// ---------------- k_state_enc: 4 rows/block, grid 512, split-K ----------------
__global__ __launch_bounds__(256) void k_state_enc(
    const float* __restrict__ st, const float* __restrict__ w1, const float* __restrict__ b1,
    const float* __restrict__ w2, const float* __restrict__ b2)
{
    __shared__ float X[4 * SLEN];
    __shared__ float HD[4 * H];
    __shared__ float RED[2 * 4 * H];
    const int row0 = blockIdx.x * 4, t = threadIdx.x;
    for (int i = t; i < 4 * SLEN; i += 256) X[i] = st[(size_t)row0 * SLEN + i];
    __syncthreads();
    const int h = t & 127, kh = t >> 7;
    {
        float acc[4] = {0.f, 0.f, 0.f, 0.f};
        const float4* X4 = (const float4*)X;
        const int k0 = kh * 128;
#pragma unroll 4
        for (int k = k0; k < k0 + 128; k += 4) {
            float w0 = w1[k * H + h], wA = w1[(k + 1) * H + h], wB = w1[(k + 2) * H + h], wC = w1[(k + 3) * H + h];
#pragma unroll
            for (int j = 0; j < 4; j++) {
                float4 x = X4[j * (SLEN / 4) + (k >> 2)];
                acc[j] = fmaf(x.x, w0, acc[j]); acc[j] = fmaf(x.y, wA, acc[j]);
                acc[j] = fmaf(x.z, wB, acc[j]); acc[j] = fmaf(x.w, wC, acc[j]);
            }
        }
#pragma unroll
        for (int j = 0; j < 4; j++) RED[(kh * 4 + j) * H + h] = acc[j];
    }
    __syncthreads();
    for (int idx = t; idx < 4 * H; idx += 256)
        HD[idx] = fmaxf(RED[idx] + RED[4 * H + idx] + b1[idx & 127], 0.f);
    __syncthreads();
    {
        const int rb = kh * 2;
        float acc[2];
        const float bb = b2[h];
        acc[0] = bb; acc[1] = bb;
        const float4* H4 = (const float4*)HD;
#pragma unroll 4
        for (int k = 0; k < H; k += 4) {
            float w0 = w2[k * H + h], wA = w2[(k + 1) * H + h], wB = w2[(k + 2) * H + h], wC = w2[(k + 3) * H + h];
#pragma unroll
            for (int j = 0; j < 2; j++) {
                float4 x = H4[(rb + j) * (H / 4) + (k >> 2)];
                acc[j] = fmaf(x.x, w0, acc[j]); acc[j] = fmaf(x.y, wA, acc[j]);
                acc[j] = fmaf(x.z, wB, acc[j]); acc[j] = fmaf(x.w, wC, acc[j]);
            }
        }
#pragma unroll
        for (int j = 0; j < 2; j++) g_s1[(size_t)(row0 + rb + j) * H + h] = fmaxf(acc[j], 0.f);
    }
}

// ---------------- k_smm: Cs[b][c][j] = sum_k s1[b,j,k] * w1[64+k][c] ----------------
__global__ __launch_bounds__(512) void k_smm(const float* __restrict__ w1)
{
    __shared__ float S[64 * 128];
    const int b = blockIdx.x, t = threadIdx.x;
    for (int i = t; i < 64 * 128; i += 512) S[i] = g_s1[(size_t)b * 8192 + i];
    __syncthreads();
    const int c = t & 127, jh = t >> 7;
    float acc[16];
#pragma unroll
    for (int j = 0; j < 16; j++) acc[j] = 0.f;
    const float4* S4 = (const float4*)S;
#pragma unroll 2
    for (int k4 = 0; k4 < 32; k4++) {
        const int k = 4 * k4;
        float w0 = w1[(64 + k) * 128 + c], wA = w1[(65 + k) * 128 + c];
        float wB = w1[(66 + k) * 128 + c], wC = w1[(67 + k) * 128 + c];
#pragma unroll
        for (int j = 0; j < 16; j++) {
            float4 s = S4[(jh * 16 + j) * 32 + k4];
            acc[j] = fmaf(s.x, w0, acc[j]); acc[j] = fmaf(s.y, wA, acc[j]);
            acc[j] = fmaf(s.z, wB, acc[j]); acc[j] = fmaf(s.w, wC, acc[j]);
        }
    }
#pragma unroll
    for (int j = 0; j < 16; j++)
        g_Cs[(size_t)b * 8192 + c * 64 + jh * 16 + j] = acc[j];
}

// ---------------- k_rel: LDSM B-frags + LDG.128 weight frags ----------------
// smem: XH @0 (64x72 bf16 = 9216), XL @9216, HIh @18432 (64x136 = 17408),
//       HIl @35840, sal @53248 (256). total 53504.
#define HS 136
#define XS 72
#define SM_REL 53504
#define STSP(idx, v) { float _v = (v); __nv_bfloat16 _h = __float2bfloat16(_v); \
    HIh[idx] = _h; HIl[idx] = __float2bfloat16(_v - __bfloat162float(_h)); }

__global__ __launch_bounds__(256, 3) void k_rel(
    const float* __restrict__ rel, const float* __restrict__ alive,
    const float* __restrict__ b1, const float* __restrict__ b2,
    const int* __restrict__ agp)
{
    extern __shared__ unsigned char smem[];
    __nv_bfloat16* XH = (__nv_bfloat16*)smem;
    __nv_bfloat16* XL = (__nv_bfloat16*)(smem + 9216);
    __nv_bfloat16* HIh = (__nv_bfloat16*)(smem + 18432);
    __nv_bfloat16* HIl = (__nv_bfloat16*)(smem + 35840);
    float* sal = (float*)(smem + 53248);

    const int tid = threadIdx.x, w = tid >> 5, l = tid & 31, g = l >> 2, t4 = l & 3;
    const int bi = blockIdx.x, b = bi >> 6, i = bi & 63;
    if (tid < 64) sal[tid] = alive[b * 64 + tid];

    // ldmatrix per-lane row offsets: sel 0/1 -> tile q rows, 2/3 -> tile q+1 rows;
    // sel odd -> col +8.
    const int sel = l >> 3, lr = l & 7;
    const int jofs = lr + ((sel >> 1) << 3);
    const int cofs = (sel & 1) << 3;
    const uint32_t xrow = (uint32_t)((jofs * XS + cofs) * 2);
    const uint32_t hrow = (uint32_t)((jofs * HS + cofs) * 2);
    const uint32_t xh_b = s2u(XH), xl_b = s2u(XL), hh_b = s2u(HIh), hl_b = s2u(HIl);

    // stage rel part of X, split bf16 hi/lo
    {
        const float* rr = rel + (size_t)bi * 64 * 64;
        for (int idx = tid; idx < 64 * 64; idx += 256) {
            const int j = idx >> 6, k = idx & 63;
            float v = rr[idx];
            __nv_bfloat16 hh = __float2bfloat16(v);
            XH[j * XS + k] = hh;
            XL[j * XS + k] = __float2bfloat16(v - __bfloat162float(hh));
        }
    }
    __syncthreads();

    float ac[8][4];
#pragma unroll
    for (int n = 0; n < 8; n++) { ac[n][0] = 0.f; ac[n][1] = 0.f; ac[n][2] = 0.f; ac[n][3] = 0.f; }
    const int r0 = w * 16 + g;

    // layer 1 (rel part only): K=64, 4 ksteps
#pragma unroll
    for (int ks = 0; ks < 4; ks++) {
        const uint4 AH = g_w1fh[(w * 4 + ks) * 32 + l];
        const uint4 AL = g_w1fl[(w * 4 + ks) * 32 + l];
        const uint32_t ah[4] = {AH.x, AH.y, AH.z, AH.w};
        const uint32_t alr[4] = {AL.x, AL.y, AL.z, AL.w};
        const uint32_t kb = (uint32_t)(ks * 32);
#pragma unroll
        for (int q = 0; q < 8; q += 2) {
            uint32_t bh[4], bl[4];
            const uint32_t off = (uint32_t)(q * 8 * XS * 2) + kb;
            LDSM4(bh, xh_b + off + xrow);
            LDSM4(bl, xl_b + off + xrow);
            MMA4(ac[q], ah, bh[0], bh[1]);
            MMA4(ac[q], ah, bl[0], bl[1]);
            MMA4(ac[q], alr, bh[0], bh[1]);
            MMA4(ac[q + 1], ah, bh[2], bh[3]);
            MMA4(ac[q + 1], ah, bl[2], bl[3]);
            MMA4(ac[q + 1], alr, bh[2], bh[3]);
        }
    }
    // epilogue 1: add hoisted Cs + b1, relu, split-store HID^T
    {
        const float bA = b1[r0], bB = b1[r0 + 8];
        const float* csA = g_Cs + (size_t)b * 8192 + r0 * 64;
        const float* csB = csA + 8 * 64;
#pragma unroll
        for (int n = 0; n < 8; n++) {
            const int j0 = n * 8 + 2 * t4;
            float2 cA = *(const float2*)(csA + j0);
            float2 cB = *(const float2*)(csB + j0);
            STSP(j0 * HS + r0,           fmaxf(ac[n][0] + cA.x + bA, 0.f));
            STSP((j0 + 1) * HS + r0,     fmaxf(ac[n][1] + cA.y + bA, 0.f));
            STSP(j0 * HS + r0 + 8,       fmaxf(ac[n][2] + cB.x + bB, 0.f));
            STSP((j0 + 1) * HS + r0 + 8, fmaxf(ac[n][3] + cB.y + bB, 0.f));
        }
    }
    __syncthreads();

    // layer 2: two half-passes (mean cols / max cols), K=128
    const int gag = *agp;
    const bool isag = (i == gag);
#pragma unroll 1
    for (int hf = 0; hf < 2; hf++) {
        const int rr = hf * 128 + w * 16 + g;
        const int slot = hf * 8 + w;
#pragma unroll
        for (int n = 0; n < 8; n++) { ac[n][0] = 0.f; ac[n][1] = 0.f; ac[n][2] = 0.f; ac[n][3] = 0.f; }
#pragma unroll 1
        for (int ks = 0; ks < 8; ks++) {
            const uint4 AH = g_w2fh[(slot * 8 + ks) * 32 + l];
            const uint4 AL = g_w2fl[(slot * 8 + ks) * 32 + l];
            const uint32_t ah[4] = {AH.x, AH.y, AH.z, AH.w};
            const uint32_t alr[4] = {AL.x, AL.y, AL.z, AL.w};
            const uint32_t kb = (uint32_t)(ks * 32);
#pragma unroll
            for (int q = 0; q < 8; q += 2) {
                uint32_t bh[4], bl[4];
                const uint32_t off = (uint32_t)(q * 8 * HS * 2) + kb;
                LDSM4(bh, hh_b + off + hrow);
                LDSM4(bl, hl_b + off + hrow);
                MMA4(ac[q], ah, bh[0], bh[1]);
                MMA4(ac[q], ah, bl[0], bl[1]);
                MMA4(ac[q], alr, bh[0], bh[1]);
                MMA4(ac[q + 1], ah, bh[2], bh[3]);
                MMA4(ac[q + 1], ah, bl[2], bl[3]);
                MMA4(ac[q + 1], alr, bh[2], bh[3]);
            }
        }
        const float bA = b2[rr], bB = b2[rr + 8];
        float s0 = 0.f, s1 = 0.f;
#pragma unroll
        for (int n = 0; n < 8; n++) {
            const int j0 = n * 8 + 2 * t4;
            const float al0 = sal[j0], al1 = sal[j0 + 1];
            float v0 = fmaxf(ac[n][0] + bA, 0.f), v1 = fmaxf(ac[n][1] + bA, 0.f);
            float v2 = fmaxf(ac[n][2] + bB, 0.f), v3 = fmaxf(ac[n][3] + bB, 0.f);
            if (isag) {
                float* rg = g_ragent + (size_t)(b * 64) * 256;
                rg[(size_t)j0 * 256 + rr] = v0;
                rg[(size_t)(j0 + 1) * 256 + rr] = v1;
                rg[(size_t)j0 * 256 + rr + 8] = v2;
                rg[(size_t)(j0 + 1) * 256 + rr + 8] = v3;
            }
            if (hf == 0) {
                s0 += v0 * al0 + v1 * al1;
                s1 += v2 * al0 + v3 * al1;
            } else {
                s0 = fmaxf(s0, fmaxf(v0 * al0, v1 * al1));
                s1 = fmaxf(s1, fmaxf(v2 * al0, v3 * al1));
            }
        }
        if (hf == 0) {
            s0 += __shfl_xor_sync(0xffffffffu, s0, 1); s0 += __shfl_xor_sync(0xffffffffu, s0, 2);
            s1 += __shfl_xor_sync(0xffffffffu, s1, 1); s1 += __shfl_xor_sync(0xffffffffu, s1, 2);
            if (t4 == 0) {
                g_pooled[(size_t)bi * 256 + rr] = s0 * (1.f / 64.f);
                g_pooled[(size_t)bi * 256 + rr + 8] = s1 * (1.f / 64.f);
            }
        } else {
            s0 = fmaxf(s0, __shfl_xor_sync(0xffffffffu, s0, 1)); s0 = fmaxf(s0, __shfl_xor_sync(0xffffffffu, s0, 2));
            s1 = fmaxf(s1, __shfl_xor_sync(0xffffffffu, s1, 1)); s1 = fmaxf(s1, __shfl_xor_sync(0xffffffffu, s1, 2));
            if (t4 == 0) {
                g_pooled[(size_t)bi * 256 + rr] = s0;
                g_pooled[(size_t)bi * 256 + rr + 8] = s1;
            }
        }
    }
}

// ---------------- k_ra: 4 rows/block, grid 512, split-K ----------------
__global__ __launch_bounds__(256) void k_ra(const float* __restrict__ w, const float* __restrict__ bias)
{
    __shared__ float X[4 * K3];
    __shared__ float RED[2 * 4 * H];
    const int row0 = blockIdx.x * 4, t = threadIdx.x;
    for (int i = t; i < 4 * H; i += 256) {
        int j = i >> 7, h2 = i & 127;
        X[j * K3 + h2] = g_s1[(size_t)(row0 + j) * H + h2];
    }
    for (int i = t; i < 4 * 2 * H; i += 256) {
        int j = i >> 8, h2 = i & 255;
        X[j * K3 + H + h2] = g_pooled[(size_t)(row0 + j) * (2 * H) + h2];
    }
    __syncthreads();
    const int h = t & 127, kh = t >> 7;
    float acc[4] = {0.f, 0.f, 0.f, 0.f};
    const float4* X4 = (const float4*)X;
    const int k0 = kh * 192;
#pragma unroll 4
    for (int k = k0; k < k0 + 192; k += 4) {
        float w0 = w[k * H + h], wA = w[(k + 1) * H + h], wB = w[(k + 2) * H + h], wC = w[(k + 3) * H + h];
#pragma unroll
        for (int j = 0; j < 4; j++) {
            float4 x = X4[j * (K3 / 4) + (k >> 2)];
            acc[j] = fmaf(x.x, w0, acc[j]); acc[j] = fmaf(x.y, wA, acc[j]);
            acc[j] = fmaf(x.z, wB, acc[j]); acc[j] = fmaf(x.w, wC, acc[j]);
        }
    }
#pragma unroll
    for (int j = 0; j < 4; j++) RED[(kh * 4 + j) * H + h] = acc[j];
    __syncthreads();
    for (int idx = t; idx < 4 * H; idx += 256)
        g_s2[(size_t)(row0 + (idx >> 7)) * H + (idx & 127)] =
            fmaxf(RED[idx] + RED[4 * H + idx] + bias[idx & 127], 0.f);
}

// ---------------- k_ae: 4 rows/block, grid 512, split-K L1 ----------------
__global__ __launch_bounds__(256) void k_ae(
    const float* __restrict__ w1, const float* __restrict__ b1,
    const float* __restrict__ w2, const float* __restrict__ b2,
    const int* __restrict__ agp)
{
    __shared__ float X[4 * K4];
    __shared__ float HD[4 * H];
    __shared__ float RED[2 * 4 * H];
    const int row0 = blockIdx.x * 4, b = row0 >> 6, t = threadIdx.x;
    const int g = *agp;
    for (int i = t; i < 4 * 2 * H; i += 256) {
        int j = i >> 8, h2 = i & 255;
        X[j * K4 + h2] = g_ragent[(size_t)(row0 + j) * (2 * H) + h2];
    }
    for (int i = t; i < 4 * H; i += 256) {
        int j = i >> 7, h2 = i & 127;
        X[j * K4 + 2 * H + h2] = g_s2[(size_t)(row0 + j) * H + h2];
        X[j * K4 + 3 * H + h2] = g_s2[((size_t)b * A + g) * H + h2];
    }
    __syncthreads();
    const int h = t & 127, kh = t >> 7;
    {
        float acc[4] = {0.f, 0.f, 0.f, 0.f};
        const float4* X4 = (const float4*)X;
        const int k0 = kh * 256;
#pragma unroll 4
        for (int k = k0; k < k0 + 256; k += 4) {
            float w0 = w1[k * H + h], wA = w1[(k + 1) * H + h], wB = w1[(k + 2) * H + h], wC = w1[(k + 3) * H + h];
#pragma unroll
            for (int j = 0; j < 4; j++) {
                float4 x = X4[j * (K4 / 4) + (k >> 2)];
                acc[j] = fmaf(x.x, w0, acc[j]); acc[j] = fmaf(x.y, wA, acc[j]);
                acc[j] = fmaf(x.z, wB, acc[j]); acc[j] = fmaf(x.w, wC, acc[j]);
            }
        }
#pragma unroll
        for (int j = 0; j < 4; j++) RED[(kh * 4 + j) * H + h] = acc[j];
    }
    __syncthreads();
    for (int idx = t; idx < 4 * H; idx += 256)
        HD[idx] = fmaxf(RED[idx] + RED[4 * H + idx] + b1[idx & 127], 0.f);
    __syncthreads();
    {
        const int c = t;
        float acc2[4];
        const float bb = b2[c];
#pragma unroll
        for (int j = 0; j < 4; j++) acc2[j] = bb;
        const float4* H4 = (const float4*)HD;
#pragma unroll 4
        for (int k = 0; k < H; k += 4) {
            float w0 = w2[k * 256 + c], wA = w2[(k + 1) * 256 + c], wB = w2[(k + 2) * 256 + c], wC = w2[(k + 3) * 256 + c];
#pragma unroll
            for (int j = 0; j < 4; j++) {
                float4 x = H4[j * (H / 4) + (k >> 2)];
                acc2[j] = fmaf(x.x, w0, acc2[j]); acc2[j] = fmaf(x.y, wA, acc2[j]);
                acc2[j] = fmaf(x.z, wB, acc2[j]); acc2[j] = fmaf(x.w, wC, acc2[j]);
            }
        }
#pragma unroll
        for (int j = 0; j < 4; j++)
            g_ae[(size_t)(row0 + j) * (2 * H) + c] = fmaxf(acc2[j], 0.f);
    }
}

// ---------------- k_final ----------------
__global__ __launch_bounds__(128) void k_final(
    const float* __restrict__ action_embed, const int* __restrict__ action,
    const int* __restrict__ agp, float* __restrict__ out)
{
    const int b = blockIdx.x, h = threadIdx.x;
    const int a = action[b], g = *agp;
    const float sel = (a < E) ? action_embed[a * H + h]
                              : g_ae[((size_t)b * A + (a - E)) * (2 * H) + h];
    float* out_state = out;
    float* out_sel = out + (size_t)B * A * H;
    float* out_ps = out_sel + (size_t)B * H;
    out_sel[b * H + h] = sel;
    for (int j = 0; j < A; j++) {
        float st = g_s2[((size_t)b * A + j) * H + h];
        float ps = 0.f;
        if (a == E + j) ps = g_ae[((size_t)b * A + j) * (2 * H) + H + h];
        if (j == g) st += sel;
        out_ps[((size_t)b * A + j) * H + h] = ps;
        out_state[((size_t)b * A + j) * H + h] = st + ps;
    }
}

// ---------------- launcher ----------------
extern "C" void kernel_launch(void* const* d_in, const int* in_sizes, int n_in,
                              void* d_out, int out_size)
{
    const float* states       = (const float*)d_in[0];
    const float* relations    = (const float*)d_in[1];
    const float* alive_mask   = (const float*)d_in[2];
    const float* se_w1        = (const float*)d_in[3];
    const float* se_b1        = (const float*)d_in[4];
    const float* se_w2        = (const float*)d_in[5];
    const float* se_b2        = (const float*)d_in[6];
    const float* re_w1        = (const float*)d_in[7];
    const float* re_b1        = (const float*)d_in[8];
    const float* re_w2        = (const float*)d_in[9];
    const float* re_b2        = (const float*)d_in[10];
    const float* ra_w         = (const float*)d_in[11];
    const float* ra_b         = (const float*)d_in[12];
    const float* ae_w1        = (const float*)d_in[13];
    const float* ae_b1        = (const float*)d_in[14];
    const float* ae_w2        = (const float*)d_in[15];
    const float* ae_b2        = (const float*)d_in[16];
    const float* action_embed = (const float*)d_in[17];
    const int*   action       = (const int*)d_in[19];
    const int*   agent_id     = (const int*)d_in[20];
    float* out = (float*)d_out;

    static bool attr = false;
    if (!attr) {
        cudaFuncSetAttribute(k_rel, cudaFuncAttributeMaxDynamicSharedMemorySize, SM_REL);
        attr = true;
    }

    k_prep<<<20, 256>>>(re_w1, re_w2);
    k_state_enc<<<(B * A) / 4, 256>>>(states, se_w1, se_b1, se_w2, se_b2);
    k_smm<<<B, 512>>>(re_w1);
    k_rel<<<B * A, 256, SM_REL>>>(relations, alive_mask, re_b1, re_b2, agent_id);
    k_ra<<<(B * A) / 4, 256>>>(ra_w, ra_b);
    k_ae<<<(B * A) / 4, 256>>>(ae_w1, ae_b1, ae_w2, ae_b2, agent_id);
    k_final<<<B, 128>>>(action_embed, action, agent_id, out);
}

// round 8
// speedup vs baseline: 3.5863x; 1.0373x over previous
#include <cuda_runtime.h>
#include <cuda_bf16.h>
#include <cstdint>

#define B 32
#define A 64
#define SLEN 256
#define H 128
#define RLEN 64
#define E 16
#define K3 (3 * H)
#define K4 (4 * H)

__device__ float g_s1[B * A * H];
__device__ float g_Cs[B * H * A];          // [b][c][j] : (s1[b] @ w1[64:])^T
__device__ float g_pooled[B * A * 2 * H];
__device__ float g_ragent[B * A * 2 * H];
__device__ float g_s2[B * A * H];
__device__ float g_ae[B * A * 2 * H];
// Fragment-ordered weight images: thread's 4 regs = one uint4.
__device__ __align__(16) uint4 g_w1fh[8 * 4 * 32];
__device__ __align__(16) uint4 g_w1fl[8 * 4 * 32];
__device__ __align__(16) uint4 g_w2fh[16 * 8 * 32];
__device__ __align__(16) uint4 g_w2fl[16 * 8 * 32];

#define MMA4(d, a, b0, b1) asm volatile( \
    "mma.sync.aligned.m16n8k16.row.col.f32.bf16.bf16.f32 " \
    "{%0,%1,%2,%3},{%4,%5,%6,%7},{%8,%9},{%0,%1,%2,%3};" \
    : "+f"((d)[0]), "+f"((d)[1]), "+f"((d)[2]), "+f"((d)[3]) \
    : "r"((a)[0]), "r"((a)[1]), "r"((a)[2]), "r"((a)[3]), "r"(b0), "r"(b1))

#define LDSM4(r, a) asm volatile( \
    "ldmatrix.sync.aligned.m8n8.x4.shared.b16 {%0,%1,%2,%3}, [%4];" \
    : "=r"((r)[0]), "=r"((r)[1]), "=r"((r)[2]), "=r"((r)[3]) : "r"(a))
#define LDSM4T(r, a) asm volatile( \
    "ldmatrix.sync.aligned.m8n8.x4.trans.shared.b16 {%0,%1,%2,%3}, [%4];" \
    : "=r"((r)[0]), "=r"((r)[1]), "=r"((r)[2]), "=r"((r)[3]) : "r"(a))

__device__ __forceinline__ uint32_t s2u(const void* p) {
    uint32_t a;
    asm("{ .reg .u64 t; cvta.to.shared.u64 t, %1; cvt.u32.u64 %0, t; }" : "=r"(a) : "l"(p));
    return a;
}
__device__ __forceinline__ uint32_t pkhi(float a, float b) {
    __nv_bfloat162 t = __halves2bfloat162(__float2bfloat16(a), __float2bfloat16(b));
    return *reinterpret_cast<uint32_t*>(&t);
}
__device__ __forceinline__ uint32_t pklo(float a, float b) {
    float ra = a - __bfloat162float(__float2bfloat16(a));
    float rb = b - __bfloat162float(__float2bfloat16(b));
    __nv_bfloat162 t = __halves2bfloat162(__float2bfloat16(ra), __float2bfloat16(rb));
    return *reinterpret_cast<uint32_t*>(&t);
}

// ---------------- k_prep: fragment-ordered bf16-split weight images ----------------
__global__ void k_prep(const float* __restrict__ w1, const float* __restrict__ w2)
{
    const int stride = gridDim.x * blockDim.x;
    for (int tid = blockIdx.x * blockDim.x + threadIdx.x; tid < 1024 + 4096; tid += stride) {
        if (tid < 1024) {
            const int i = tid, lane = i & 31, ks = (i >> 5) & 3, slot = i >> 7;
            const int r0 = slot * 16 + (lane >> 2), ka = ks * 16 + 2 * (lane & 3);
            float v00 = w1[ka * 128 + r0],       v01 = w1[(ka + 1) * 128 + r0];
            float v10 = w1[ka * 128 + r0 + 8],   v11 = w1[(ka + 1) * 128 + r0 + 8];
            float v20 = w1[(ka + 8) * 128 + r0], v21 = w1[(ka + 9) * 128 + r0];
            float v30 = w1[(ka + 8) * 128 + r0 + 8], v31 = w1[(ka + 9) * 128 + r0 + 8];
            g_w1fh[i] = make_uint4(pkhi(v00, v01), pkhi(v10, v11), pkhi(v20, v21), pkhi(v30, v31));
            g_w1fl[i] = make_uint4(pklo(v00, v01), pklo(v10, v11), pklo(v20, v21), pklo(v30, v31));
        } else {
            const int i = tid - 1024, lane = i & 31, ks = (i >> 5) & 7, slot = i >> 8;
            const int rr = slot * 16 + (lane >> 2), ka = ks * 16 + 2 * (lane & 3);
            float v00 = w2[ka * 256 + rr],       v01 = w2[(ka + 1) * 256 + rr];
            float v10 = w2[ka * 256 + rr + 8],   v11 = w2[(ka + 1) * 256 + rr + 8];
            float v20 = w2[(ka + 8) * 256 + rr], v21 = w2[(ka + 9) * 256 + rr];
            float v30 = w2[(ka + 8) * 256 + rr + 8], v31 = w2[(ka + 9) * 256 + rr + 8];
            g_w2fh[i] = make_uint4(pkhi(v00, v01), pkhi(v10, v11), pkhi(v20, v21), pkhi(v30, v31));
            g_w2fl[i] = make_uint4(pklo(v00, v01), pklo(v10, v11), pklo(v20, v21), pklo(v30, v31));
        }
    }
}

// ---------------- k_state_enc: 4 rows/block, grid 512, split-K ----------------
__global__ __launch_bounds__(256) void k_state_enc(
    const float* __restrict__ st, const float* __restrict__ w1, const float* __restrict__ b1,
    const float* __restrict__ w2, const float* __restrict__ b2)
{
    __shared__ float X[4 * SLEN];
    __shared__ float HD[4 * H];
    __shared__ float RED[2 * 4 * H];
    const int row0 = blockIdx.x * 4, t = threadIdx.x;
    for (int i = t; i < 4 * SLEN; i += 256) X[i] = st[(size_t)row0 * SLEN + i];
    __syncthreads();
    const int h = t & 127, kh = t >> 7;
    {
        float acc[4] = {0.f, 0.f, 0.f, 0.f};
        const float4* X4 = (const float4*)X;
        const int k0 = kh * 128;
#pragma unroll 4
        for (int k = k0; k < k0 + 128; k += 4) {
            float w0 = w1[k * H + h], wA = w1[(k + 1) * H + h], wB = w1[(k + 2) * H + h], wC = w1[(k + 3) * H + h];
#pragma unroll
            for (int j = 0; j < 4; j++) {
                float4 x = X4[j * (SLEN / 4) + (k >> 2)];
                acc[j] = fmaf(x.x, w0, acc[j]); acc[j] = fmaf(x.y, wA, acc[j]);
                acc[j] = fmaf(x.z, wB, acc[j]); acc[j] = fmaf(x.w, wC, acc[j]);
            }
        }
#pragma unroll
        for (int j = 0; j < 4; j++) RED[(kh * 4 + j) * H + h] = acc[j];
    }
    __syncthreads();
    for (int idx = t; idx < 4 * H; idx += 256)
        HD[idx] = fmaxf(RED[idx] + RED[4 * H + idx] + b1[idx & 127], 0.f);
    __syncthreads();
    {
        const int rb = kh * 2;
        float acc[2];
        const float bb = b2[h];
        acc[0] = bb; acc[1] = bb;
        const float4* H4 = (const float4*)HD;
#pragma unroll 4
        for (int k = 0; k < H; k += 4) {
            float w0 = w2[k * H + h], wA = w2[(k + 1) * H + h], wB = w2[(k + 2) * H + h], wC = w2[(k + 3) * H + h];
#pragma unroll
            for (int j = 0; j < 2; j++) {
                float4 x = H4[(rb + j) * (H / 4) + (k >> 2)];
                acc[j] = fmaf(x.x, w0, acc[j]); acc[j] = fmaf(x.y, wA, acc[j]);
                acc[j] = fmaf(x.z, wB, acc[j]); acc[j] = fmaf(x.w, wC, acc[j]);
            }
        }
#pragma unroll
        for (int j = 0; j < 2; j++) g_s1[(size_t)(row0 + rb + j) * H + h] = fmaxf(acc[j], 0.f);
    }
}

// ---------------- k_smm: Cs[b][c][j] = sum_k s1[b,j,k] * w1[64+k][c] ----------------
__global__ __launch_bounds__(512) void k_smm(const float* __restrict__ w1)
{
    __shared__ float S[64 * 128];
    const int b = blockIdx.x, t = threadIdx.x;
    for (int i = t; i < 64 * 128; i += 512) S[i] = g_s1[(size_t)b * 8192 + i];
    __syncthreads();
    const int c = t & 127, jh = t >> 7;
    float acc[16];
#pragma unroll
    for (int j = 0; j < 16; j++) acc[j] = 0.f;
    const float4* S4 = (const float4*)S;
#pragma unroll 2
    for (int k4 = 0; k4 < 32; k4++) {
        const int k = 4 * k4;
        float w0 = w1[(64 + k) * 128 + c], wA = w1[(65 + k) * 128 + c];
        float wB = w1[(66 + k) * 128 + c], wC = w1[(67 + k) * 128 + c];
#pragma unroll
        for (int j = 0; j < 16; j++) {
            float4 s = S4[(jh * 16 + j) * 32 + k4];
            acc[j] = fmaf(s.x, w0, acc[j]); acc[j] = fmaf(s.y, wA, acc[j]);
            acc[j] = fmaf(s.z, wB, acc[j]); acc[j] = fmaf(s.w, wC, acc[j]);
        }
    }
#pragma unroll
    for (int j = 0; j < 16; j++)
        g_Cs[(size_t)b * 8192 + c * 64 + jh * 16 + j] = acc[j];
}

// ---------------- k_rel: wide warps (32 cols), trans HID, single-pass L2 ----------------
// smem: XH @0 (64x72 bf16 = 9216), XL @9216,
//       HTh @18432 (128 k-rows x 72 j, 18432 B), HTl @36864,
//       sal @55296 (256). total 55552.
#define XS 72
#define HTS 72
#define SM_REL 55552

__global__ __launch_bounds__(256, 2) void k_rel(
    const float* __restrict__ rel, const float* __restrict__ alive,
    const float* __restrict__ b1, const float* __restrict__ b2,
    const int* __restrict__ agp)
{
    extern __shared__ unsigned char smem[];
    __nv_bfloat16* XH = (__nv_bfloat16*)smem;
    __nv_bfloat16* XL = (__nv_bfloat16*)(smem + 9216);
    __nv_bfloat16* HTh = (__nv_bfloat16*)(smem + 18432);
    __nv_bfloat16* HTl = (__nv_bfloat16*)(smem + 36864);
    float* sal = (float*)(smem + 55296);

    const int tid = threadIdx.x, w = tid >> 5, l = tid & 31, g = l >> 2, t4 = l & 3;
    const int bi = blockIdx.x, b = bi >> 6, i = bi & 63;
    if (tid < 64) sal[tid] = alive[b * 64 + tid];

    const int sel = l >> 3, lr = l & 7;
    // layer-1 (non-trans, X[j][k]): tiles (jq, k / k+8)
    const uint32_t xrow = (uint32_t)(((lr + ((sel >> 1) << 3)) * XS + ((sel & 1) << 3)) * 2);
    // layer-2 (trans, HT[k][j]): tiles (k / k+8, jq)
    const uint32_t hrow = (uint32_t)(((lr + ((sel & 1) << 3)) * HTS + ((sel >> 1) << 3)) * 2);
    const uint32_t xh_b = s2u(XH), xl_b = s2u(XL), hh_b = s2u(HTh), hl_b = s2u(HTl);

    // stage rel part of X (vectorized), split bf16 hi/lo
    {
        const float4* rr4 = (const float4*)(rel + (size_t)bi * 4096);
        for (int idx = tid; idx < 1024; idx += 256) {
            const int j = idx >> 4, k4 = idx & 15;
            float4 v = rr4[idx];
            *(uint2*)(XH + j * XS + k4 * 4) = make_uint2(pkhi(v.x, v.y), pkhi(v.z, v.w));
            *(uint2*)(XL + j * XS + k4 * 4) = make_uint2(pklo(v.x, v.y), pklo(v.z, v.w));
        }
    }

    const int r0 = w * 16 + g;
    // prefetch hoisted Cs rows (hide GMEM latency behind layer-1 MMAs)
    float2 csA[8], csB[8];
    {
        const float* pA = g_Cs + (size_t)b * 8192 + r0 * 64;
        const float* pB = pA + 8 * 64;
#pragma unroll
        for (int n = 0; n < 8; n++) {
            csA[n] = *(const float2*)(pA + n * 8 + 2 * t4);
            csB[n] = *(const float2*)(pB + n * 8 + 2 * t4);
        }
    }
    __syncthreads();

    float ac[8][4];
#pragma unroll
    for (int n = 0; n < 8; n++) { ac[n][0] = 0.f; ac[n][1] = 0.f; ac[n][2] = 0.f; ac[n][3] = 0.f; }

    // layer 1 (rel part only): K=64, 4 ksteps, warp = 16 cols
#pragma unroll
    for (int ks = 0; ks < 4; ks++) {
        const uint4 AH = g_w1fh[(w * 4 + ks) * 32 + l];
        const uint4 AL = g_w1fl[(w * 4 + ks) * 32 + l];
        const uint32_t ah[4] = {AH.x, AH.y, AH.z, AH.w};
        const uint32_t alr[4] = {AL.x, AL.y, AL.z, AL.w};
        const uint32_t kb = (uint32_t)(ks * 32);
#pragma unroll
        for (int q = 0; q < 8; q += 2) {
            uint32_t bh[4], bl[4];
            const uint32_t off = (uint32_t)(q * 8 * XS * 2) + kb;
            LDSM4(bh, xh_b + off + xrow);
            LDSM4(bl, xl_b + off + xrow);
            MMA4(ac[q], ah, bh[0], bh[1]);
            MMA4(ac[q], ah, bl[0], bl[1]);
            MMA4(ac[q], alr, bh[0], bh[1]);
            MMA4(ac[q + 1], ah, bh[2], bh[3]);
            MMA4(ac[q + 1], ah, bl[2], bl[3]);
            MMA4(ac[q + 1], alr, bh[2], bh[3]);
        }
    }
    // epilogue 1: add Cs + b1, relu, pack-store HID transposed [k][j]
    {
        const float bA = b1[r0], bB = b1[r0 + 8];
#pragma unroll
        for (int n = 0; n < 8; n++) {
            const int j0 = n * 8 + 2 * t4;
            float v0 = fmaxf(ac[n][0] + csA[n].x + bA, 0.f);
            float v1 = fmaxf(ac[n][1] + csA[n].y + bA, 0.f);
            float v2 = fmaxf(ac[n][2] + csB[n].x + bB, 0.f);
            float v3 = fmaxf(ac[n][3] + csB[n].y + bB, 0.f);
            *(uint32_t*)(HTh + r0 * HTS + j0) = pkhi(v0, v1);
            *(uint32_t*)(HTl + r0 * HTS + j0) = pklo(v0, v1);
            *(uint32_t*)(HTh + (r0 + 8) * HTS + j0) = pkhi(v2, v3);
            *(uint32_t*)(HTl + (r0 + 8) * HTS + j0) = pklo(v2, v3);
        }
    }
    __syncthreads();

    // layer 2: SINGLE pass, warp w owns mean cols [16w,16w+16) and max cols [128+16w,...)
    float acM[8][4], acX[8][4];
#pragma unroll
    for (int n = 0; n < 8; n++) {
        acM[n][0] = 0.f; acM[n][1] = 0.f; acM[n][2] = 0.f; acM[n][3] = 0.f;
        acX[n][0] = 0.f; acX[n][1] = 0.f; acX[n][2] = 0.f; acX[n][3] = 0.f;
    }
#pragma unroll 1
    for (int ks = 0; ks < 8; ks++) {
        const uint4 AHa = g_w2fh[(w * 8 + ks) * 32 + l];
        const uint4 ALa = g_w2fl[(w * 8 + ks) * 32 + l];
        const uint4 AHb = g_w2fh[((8 + w) * 8 + ks) * 32 + l];
        const uint4 ALb = g_w2fl[((8 + w) * 8 + ks) * 32 + l];
        const uint32_t aha[4] = {AHa.x, AHa.y, AHa.z, AHa.w};
        const uint32_t ala[4] = {ALa.x, ALa.y, ALa.z, ALa.w};
        const uint32_t ahb[4] = {AHb.x, AHb.y, AHb.z, AHb.w};
        const uint32_t alb[4] = {ALb.x, ALb.y, ALb.z, ALb.w};
        const uint32_t kb = (uint32_t)(ks * 16 * HTS * 2);
#pragma unroll
        for (int q = 0; q < 8; q += 2) {
            uint32_t bh[4], bl[4];
            const uint32_t off = kb + (uint32_t)(q * 8 * 2);
            LDSM4T(bh, hh_b + off + hrow);
            LDSM4T(bl, hl_b + off + hrow);
            MMA4(acM[q], aha, bh[0], bh[1]);
            MMA4(acM[q], aha, bl[0], bl[1]);
            MMA4(acM[q], ala, bh[0], bh[1]);
            MMA4(acX[q], ahb, bh[0], bh[1]);
            MMA4(acX[q], ahb, bl[0], bl[1]);
            MMA4(acX[q], alb, bh[0], bh[1]);
            MMA4(acM[q + 1], aha, bh[2], bh[3]);
            MMA4(acM[q + 1], aha, bl[2], bl[3]);
            MMA4(acM[q + 1], ala, bh[2], bh[3]);
            MMA4(acX[q + 1], ahb, bh[2], bh[3]);
            MMA4(acX[q + 1], ahb, bl[2], bl[3]);
            MMA4(acX[q + 1], alb, bh[2], bh[3]);
        }
    }
    // epilogue 2: relu(+b2), agent store, in-warp masked mean AND max over j
    {
        const int rrA = w * 16 + g;          // mean cols
        const int rrB = 128 + w * 16 + g;    // max cols
        const int gag = *agp;
        const bool isag = (i == gag);
        const float bMA = b2[rrA], bMB = b2[rrA + 8];
        const float bXA = b2[rrB], bXB = b2[rrB + 8];
        float s0 = 0.f, s1 = 0.f, t0 = 0.f, t1 = 0.f;
        float* rg = g_ragent + (size_t)(b * 64) * 256;
#pragma unroll
        for (int n = 0; n < 8; n++) {
            const int j0 = n * 8 + 2 * t4;
            const float al0 = sal[j0], al1 = sal[j0 + 1];
            float m0 = fmaxf(acM[n][0] + bMA, 0.f), m1 = fmaxf(acM[n][1] + bMA, 0.f);
            float m2 = fmaxf(acM[n][2] + bMB, 0.f), m3 = fmaxf(acM[n][3] + bMB, 0.f);
            float x0 = fmaxf(acX[n][0] + bXA, 0.f), x1 = fmaxf(acX[n][1] + bXA, 0.f);
            float x2 = fmaxf(acX[n][2] + bXB, 0.f), x3 = fmaxf(acX[n][3] + bXB, 0.f);
            if (isag) {
                rg[(size_t)j0 * 256 + rrA] = m0;
                rg[(size_t)(j0 + 1) * 256 + rrA] = m1;
                rg[(size_t)j0 * 256 + rrA + 8] = m2;
                rg[(size_t)(j0 + 1) * 256 + rrA + 8] = m3;
                rg[(size_t)j0 * 256 + rrB] = x0;
                rg[(size_t)(j0 + 1) * 256 + rrB] = x1;
                rg[(size_t)j0 * 256 + rrB + 8] = x2;
                rg[(size_t)(j0 + 1) * 256 + rrB + 8] = x3;
            }
            s0 += m0 * al0 + m1 * al1;
            s1 += m2 * al0 + m3 * al1;
            t0 = fmaxf(t0, fmaxf(x0 * al0, x1 * al1));
            t1 = fmaxf(t1, fmaxf(x2 * al0, x3 * al1));
        }
        s0 += __shfl_xor_sync(0xffffffffu, s0, 1); s0 += __shfl_xor_sync(0xffffffffu, s0, 2);
        s1 += __shfl_xor_sync(0xffffffffu, s1, 1); s1 += __shfl_xor_sync(0xffffffffu, s1, 2);
        t0 = fmaxf(t0, __shfl_xor_sync(0xffffffffu, t0, 1)); t0 = fmaxf(t0, __shfl_xor_sync(0xffffffffu, t0, 2));
        t1 = fmaxf(t1, __shfl_xor_sync(0xffffffffu, t1, 1)); t1 = fmaxf(t1, __shfl_xor_sync(0xffffffffu, t1, 2));
        if (t4 == 0) {
            g_pooled[(size_t)bi * 256 + rrA] = s0 * (1.f / 64.f);
            g_pooled[(size_t)bi * 256 + rrA + 8] = s1 * (1.f / 64.f);
            g_pooled[(size_t)bi * 256 + rrB] = t0;
            g_pooled[(size_t)bi * 256 + rrB + 8] = t1;
        }
    }
}

// ---------------- k_ra: 4 rows/block, grid 512, split-K ----------------
__global__ __launch_bounds__(256) void k_ra(const float* __restrict__ w, const float* __restrict__ bias)
{
    __shared__ float X[4 * K3];
    __shared__ float RED[2 * 4 * H];
    const int row0 = blockIdx.x * 4, t = threadIdx.x;
    for (int i = t; i < 4 * H; i += 256) {
        int j = i >> 7, h2 = i & 127;
        X[j * K3 + h2] = g_s1[(size_t)(row0 + j) * H + h2];
    }
    for (int i = t; i < 4 * 2 * H; i += 256) {
        int j = i >> 8, h2 = i & 255;
        X[j * K3 + H + h2] = g_pooled[(size_t)(row0 + j) * (2 * H) + h2];
    }
    __syncthreads();
    const int h = t & 127, kh = t >> 7;
    float acc[4] = {0.f, 0.f, 0.f, 0.f};
    const float4* X4 = (const float4*)X;
    const int k0 = kh * 192;
#pragma unroll 4
    for (int k = k0; k < k0 + 192; k += 4) {
        float w0 = w[k * H + h], wA = w[(k + 1) * H + h], wB = w[(k + 2) * H + h], wC = w[(k + 3) * H + h];
#pragma unroll
        for (int j = 0; j < 4; j++) {
            float4 x = X4[j * (K3 / 4) + (k >> 2)];
            acc[j] = fmaf(x.x, w0, acc[j]); acc[j] = fmaf(x.y, wA, acc[j]);
            acc[j] = fmaf(x.z, wB, acc[j]); acc[j] = fmaf(x.w, wC, acc[j]);
        }
    }
#pragma unroll
    for (int j = 0; j < 4; j++) RED[(kh * 4 + j) * H + h] = acc[j];
    __syncthreads();
    for (int idx = t; idx < 4 * H; idx += 256)
        g_s2[(size_t)(row0 + (idx >> 7)) * H + (idx & 127)] =
            fmaxf(RED[idx] + RED[4 * H + idx] + bias[idx & 127], 0.f);
}

// ---------------- k_ae: 4 rows/block, grid 512, split-K L1 ----------------
__global__ __launch_bounds__(256) void k_ae(
    const float* __restrict__ w1, const float* __restrict__ b1,
    const float* __restrict__ w2, const float* __restrict__ b2,
    const int* __restrict__ agp)
{
    __shared__ float X[4 * K4];
    __shared__ float HD[4 * H];
    __shared__ float RED[2 * 4 * H];
    const int row0 = blockIdx.x * 4, b = row0 >> 6, t = threadIdx.x;
    const int g = *agp;
    for (int i = t; i < 4 * 2 * H; i += 256) {
        int j = i >> 8, h2 = i & 255;
        X[j * K4 + h2] = g_ragent[(size_t)(row0 + j) * (2 * H) + h2];
    }
    for (int i = t; i < 4 * H; i += 256) {
        int j = i >> 7, h2 = i & 127;
        X[j * K4 + 2 * H + h2] = g_s2[(size_t)(row0 + j) * H + h2];
        X[j * K4 + 3 * H + h2] = g_s2[((size_t)b * A + g) * H + h2];
    }
    __syncthreads();
    const int h = t & 127, kh = t >> 7;
    {
        float acc[4] = {0.f, 0.f, 0.f, 0.f};
        const float4* X4 = (const float4*)X;
        const int k0 = kh * 256;
#pragma unroll 4
        for (int k = k0; k < k0 + 256; k += 4) {
            float w0 = w1[k * H + h], wA = w1[(k + 1) * H + h], wB = w1[(k + 2) * H + h], wC = w1[(k + 3) * H + h];
#pragma unroll
            for (int j = 0; j < 4; j++) {
                float4 x = X4[j * (K4 / 4) + (k >> 2)];
                acc[j] = fmaf(x.x, w0, acc[j]); acc[j] = fmaf(x.y, wA, acc[j]);
                acc[j] = fmaf(x.z, wB, acc[j]); acc[j] = fmaf(x.w, wC, acc[j]);
            }
        }
#pragma unroll
        for (int j = 0; j < 4; j++) RED[(kh * 4 + j) * H + h] = acc[j];
    }
    __syncthreads();
    for (int idx = t; idx < 4 * H; idx += 256)
        HD[idx] = fmaxf(RED[idx] + RED[4 * H + idx] + b1[idx & 127], 0.f);
    __syncthreads();
    {
        const int c = t;
        float acc2[4];
        const float bb = b2[c];
#pragma unroll
        for (int j = 0; j < 4; j++) acc2[j] = bb;
        const float4* H4 = (const float4*)HD;
#pragma unroll 4
        for (int k = 0; k < H; k += 4) {
            float w0 = w2[k * 256 + c], wA = w2[(k + 1) * 256 + c], wB = w2[(k + 2) * 256 + c], wC = w2[(k + 3) * 256 + c];
#pragma unroll
            for (int j = 0; j < 4; j++) {
                float4 x = H4[j * (H / 4) + (k >> 2)];
                acc2[j] = fmaf(x.x, w0, acc2[j]); acc2[j] = fmaf(x.y, wA, acc2[j]);
                acc2[j] = fmaf(x.z, wB, acc2[j]); acc2[j] = fmaf(x.w, wC, acc2[j]);
            }
        }
#pragma unroll
        for (int j = 0; j < 4; j++)
            g_ae[(size_t)(row0 + j) * (2 * H) + c] = fmaxf(acc2[j], 0.f);
    }
}

// ---------------- k_final ----------------
__global__ __launch_bounds__(128) void k_final(
    const float* __restrict__ action_embed, const int* __restrict__ action,
    const int* __restrict__ agp, float* __restrict__ out)
{
    const int b = blockIdx.x, h = threadIdx.x;
    const int a = action[b], g = *agp;
    const float sel = (a < E) ? action_embed[a * H + h]
                              : g_ae[((size_t)b * A + (a - E)) * (2 * H) + h];
    float* out_state = out;
    float* out_sel = out + (size_t)B * A * H;
    float* out_ps = out_sel + (size_t)B * H;
    out_sel[b * H + h] = sel;
    for (int j = 0; j < A; j++) {
        float st = g_s2[((size_t)b * A + j) * H + h];
        float ps = 0.f;
        if (a == E + j) ps = g_ae[((size_t)b * A + j) * (2 * H) + H + h];
        if (j == g) st += sel;
        out_ps[((size_t)b * A + j) * H + h] = ps;
        out_state[((size_t)b * A + j) * H + h] = st + ps;
    }
}

// ---------------- launcher ----------------
extern "C" void kernel_launch(void* const* d_in, const int* in_sizes, int n_in,
                              void* d_out, int out_size)
{
    const float* states       = (const float*)d_in[0];
    const float* relations    = (const float*)d_in[1];
    const float* alive_mask   = (const float*)d_in[2];
    const float* se_w1        = (const float*)d_in[3];
    const float* se_b1        = (const float*)d_in[4];
    const float* se_w2        = (const float*)d_in[5];
    const float* se_b2        = (const float*)d_in[6];
    const float* re_w1        = (const float*)d_in[7];
    const float* re_b1        = (const float*)d_in[8];
    const float* re_w2        = (const float*)d_in[9];
    const float* re_b2        = (const float*)d_in[10];
    const float* ra_w         = (const float*)d_in[11];
    const float* ra_b         = (const float*)d_in[12];
    const float* ae_w1        = (const float*)d_in[13];
    const float* ae_b1        = (const float*)d_in[14];
    const float* ae_w2        = (const float*)d_in[15];
    const float* ae_b2        = (const float*)d_in[16];
    const float* action_embed = (const float*)d_in[17];
    const int*   action       = (const int*)d_in[19];
    const int*   agent_id     = (const int*)d_in[20];
    float* out = (float*)d_out;

    static bool attr = false;
    if (!attr) {
        cudaFuncSetAttribute(k_rel, cudaFuncAttributeMaxDynamicSharedMemorySize, SM_REL);
        attr = true;
    }

    k_prep<<<20, 256>>>(re_w1, re_w2);
    k_state_enc<<<(B * A) / 4, 256>>>(states, se_w1, se_b1, se_w2, se_b2);
    k_smm<<<B, 512>>>(re_w1);
    k_rel<<<B * A, 256, SM_REL>>>(relations, alive_mask, re_b1, re_b2, agent_id);
    k_ra<<<(B * A) / 4, 256>>>(ra_w, ra_b);
    k_ae<<<(B * A) / 4, 256>>>(ae_w1, ae_b1, ae_w2, ae_b2, agent_id);
    k_final<<<B, 128>>>(action_embed, action, agent_id, out);
}

// round 9
// speedup vs baseline: 3.8822x; 1.0825x over previous
#include <cuda_runtime.h>
#include <cuda_bf16.h>
#include <cstdint>

#define B 32
#define A 64
#define SLEN 256
#define H 128
#define RLEN 64
#define E 16
#define K3 (3 * H)
#define K4 (4 * H)

__device__ float g_s1[B * A * H];
__device__ float g_Cs[B * H * A];          // [b][c][j]
__device__ float g_pooled[B * A * 2 * H];
__device__ float g_ragent[B * A * 2 * H];
__device__ float g_s2[B * A * H];
__device__ float g_ae[B * A * 2 * H];
__device__ __align__(16) uint4 g_w1fh[8 * 4 * 32];
__device__ __align__(16) uint4 g_w1fl[8 * 4 * 32];
__device__ __align__(16) uint4 g_w2fh[16 * 8 * 32];
__device__ __align__(16) uint4 g_w2fl[16 * 8 * 32];

#define MMA4(d, a, b0, b1) asm volatile( \
    "mma.sync.aligned.m16n8k16.row.col.f32.bf16.bf16.f32 " \
    "{%0,%1,%2,%3},{%4,%5,%6,%7},{%8,%9},{%0,%1,%2,%3};" \
    : "+f"((d)[0]), "+f"((d)[1]), "+f"((d)[2]), "+f"((d)[3]) \
    : "r"((a)[0]), "r"((a)[1]), "r"((a)[2]), "r"((a)[3]), "r"(b0), "r"(b1))

#define LDSM4(r, a) asm volatile( \
    "ldmatrix.sync.aligned.m8n8.x4.shared.b16 {%0,%1,%2,%3}, [%4];" \
    : "=r"((r)[0]), "=r"((r)[1]), "=r"((r)[2]), "=r"((r)[3]) : "r"(a))
#define LDSM4T(r, a) asm volatile( \
    "ldmatrix.sync.aligned.m8n8.x4.trans.shared.b16 {%0,%1,%2,%3}, [%4];" \
    : "=r"((r)[0]), "=r"((r)[1]), "=r"((r)[2]), "=r"((r)[3]) : "r"(a))

__device__ __forceinline__ uint32_t s2u(const void* p) {
    uint32_t a;
    asm("{ .reg .u64 t; cvta.to.shared.u64 t, %1; cvt.u32.u64 %0, t; }" : "=r"(a) : "l"(p));
    return a;
}
__device__ __forceinline__ uint32_t pkhi(float a, float b) {
    __nv_bfloat162 t = __halves2bfloat162(__float2bfloat16(a), __float2bfloat16(b));
    return *reinterpret_cast<uint32_t*>(&t);
}
__device__ __forceinline__ uint32_t pklo(float a, float b) {
    float ra = a - __bfloat162float(__float2bfloat16(a));
    float rb = b - __bfloat162float(__float2bfloat16(b));
    __nv_bfloat162 t = __halves2bfloat162(__float2bfloat16(ra), __float2bfloat16(rb));
    return *reinterpret_cast<uint32_t*>(&t);
}

// ---------------- k_enc_prep: state encoder (blocks <512) + weight prep (>=512) ----------------
__global__ __launch_bounds__(256) void k_enc_prep(
    const float* __restrict__ st, const float* __restrict__ w1, const float* __restrict__ b1,
    const float* __restrict__ w2, const float* __restrict__ b2,
    const float* __restrict__ rw1, const float* __restrict__ rw2)
{
    __shared__ float X[4 * SLEN];
    __shared__ float HD[4 * H];
    __shared__ float RED[2 * 4 * H];
    const int t = threadIdx.x;

    if (blockIdx.x >= 512) {
        // weight prep: 5120 items, one per thread
        const int it = (blockIdx.x - 512) * 256 + t;
        if (it < 1024) {
            const int i = it, lane = i & 31, ks = (i >> 5) & 3, slot = i >> 7;
            const int r0 = slot * 16 + (lane >> 2), ka = ks * 16 + 2 * (lane & 3);
            float v00 = rw1[ka * 128 + r0],       v01 = rw1[(ka + 1) * 128 + r0];
            float v10 = rw1[ka * 128 + r0 + 8],   v11 = rw1[(ka + 1) * 128 + r0 + 8];
            float v20 = rw1[(ka + 8) * 128 + r0], v21 = rw1[(ka + 9) * 128 + r0];
            float v30 = rw1[(ka + 8) * 128 + r0 + 8], v31 = rw1[(ka + 9) * 128 + r0 + 8];
            g_w1fh[i] = make_uint4(pkhi(v00, v01), pkhi(v10, v11), pkhi(v20, v21), pkhi(v30, v31));
            g_w1fl[i] = make_uint4(pklo(v00, v01), pklo(v10, v11), pklo(v20, v21), pklo(v30, v31));
        } else {
            const int i = it - 1024, lane = i & 31, ks = (i >> 5) & 7, slot = i >> 8;
            const int rr = slot * 16 + (lane >> 2), ka = ks * 16 + 2 * (lane & 3);
            float v00 = rw2[ka * 256 + rr],       v01 = rw2[(ka + 1) * 256 + rr];
            float v10 = rw2[ka * 256 + rr + 8],   v11 = rw2[(ka + 1) * 256 + rr + 8];
            float v20 = rw2[(ka + 8) * 256 + rr], v21 = rw2[(ka + 9) * 256 + rr];
            float v30 = rw2[(ka + 8) * 256 + rr + 8], v31 = rw2[(ka + 9) * 256 + rr + 8];
            g_w2fh[i] = make_uint4(pkhi(v00, v01), pkhi(v10, v11), pkhi(v20, v21), pkhi(v30, v31));
            g_w2fl[i] = make_uint4(pklo(v00, v01), pklo(v10, v11), pklo(v20, v21), pklo(v30, v31));
        }
        return;
    }

    const int row0 = blockIdx.x * 4;
    for (int i = t; i < 4 * SLEN; i += 256) X[i] = st[(size_t)row0 * SLEN + i];
    __syncthreads();
    const int h = t & 127, kh = t >> 7;
    {
        float acc[4] = {0.f, 0.f, 0.f, 0.f};
        const float4* X4 = (const float4*)X;
        const int k0 = kh * 128;
#pragma unroll 4
        for (int k = k0; k < k0 + 128; k += 4) {
            float w0 = w1[k * H + h], wA = w1[(k + 1) * H + h], wB = w1[(k + 2) * H + h], wC = w1[(k + 3) * H + h];
#pragma unroll
            for (int j = 0; j < 4; j++) {
                float4 x = X4[j * (SLEN / 4) + (k >> 2)];
                acc[j] = fmaf(x.x, w0, acc[j]); acc[j] = fmaf(x.y, wA, acc[j]);
                acc[j] = fmaf(x.z, wB, acc[j]); acc[j] = fmaf(x.w, wC, acc[j]);
            }
        }
#pragma unroll
        for (int j = 0; j < 4; j++) RED[(kh * 4 + j) * H + h] = acc[j];
    }
    __syncthreads();
    for (int idx = t; idx < 4 * H; idx += 256)
        HD[idx] = fmaxf(RED[idx] + RED[4 * H + idx] + b1[idx & 127], 0.f);
    __syncthreads();
    {
        const int rb = kh * 2;
        float acc[2];
        const float bb = b2[h];
        acc[0] = bb; acc[1] = bb;
        const float4* H4 = (const float4*)HD;
#pragma unroll 4
        for (int k = 0; k < H; k += 4) {
            float w0 = w2[k * H + h], wA = w2[(k + 1) * H + h], wB = w2[(k + 2) * H + h], wC = w2[(k + 3) * H + h];
#pragma unroll
            for (int j = 0; j < 2; j++) {
                float4 x = H4[(rb + j) * (H / 4) + (k >> 2)];
                acc[j] = fmaf(x.x, w0, acc[j]); acc[j] = fmaf(x.y, wA, acc[j]);
                acc[j] = fmaf(x.z, wB, acc[j]); acc[j] = fmaf(x.w, wC, acc[j]);
            }
        }
#pragma unroll
        for (int j = 0; j < 2; j++) g_s1[(size_t)(row0 + rb + j) * H + h] = fmaxf(acc[j], 0.f);
    }
}

// ---------------- k_smm: grid 128 (4 j-chunks per b) ----------------
__global__ __launch_bounds__(256) void k_smm(const float* __restrict__ w1)
{
    __shared__ float S[16 * 128];
    const int b = blockIdx.x >> 2, j0 = (blockIdx.x & 3) * 16, t = threadIdx.x;
    for (int i = t; i < 16 * 128; i += 256)
        S[i] = g_s1[(size_t)b * 8192 + (size_t)j0 * 128 + i];
    __syncthreads();
    const int c = t & 127, jh = t >> 7;
    float acc[8];
#pragma unroll
    for (int j = 0; j < 8; j++) acc[j] = 0.f;
    const float4* S4 = (const float4*)S;
#pragma unroll 2
    for (int k4 = 0; k4 < 32; k4++) {
        const int k = 4 * k4;
        float w0 = w1[(64 + k) * 128 + c], wA = w1[(65 + k) * 128 + c];
        float wB = w1[(66 + k) * 128 + c], wC = w1[(67 + k) * 128 + c];
#pragma unroll
        for (int j = 0; j < 8; j++) {
            float4 s = S4[(jh * 8 + j) * 32 + k4];
            acc[j] = fmaf(s.x, w0, acc[j]); acc[j] = fmaf(s.y, wA, acc[j]);
            acc[j] = fmaf(s.z, wB, acc[j]); acc[j] = fmaf(s.w, wC, acc[j]);
        }
    }
#pragma unroll
    for (int j = 0; j < 8; j++)
        g_Cs[(size_t)b * 8192 + c * 64 + j0 + jh * 8 + j] = acc[j];
}

// ---------------- k_rel ----------------
#define XS 72
#define HTS 72
#define SM_REL 55552

#define DO6(q, BH, BL) \
    MMA4(ac[q], ah, BH[0], BH[1]); MMA4(ac[q], ah, BL[0], BL[1]); MMA4(ac[q], alr, BH[0], BH[1]); \
    MMA4(ac[q + 1], ah, BH[2], BH[3]); MMA4(ac[q + 1], ah, BL[2], BL[3]); MMA4(ac[q + 1], alr, BH[2], BH[3]);

#define DO12(q, BH, BL) \
    MMA4(acM[q], aha, BH[0], BH[1]); MMA4(acM[q], aha, BL[0], BL[1]); MMA4(acM[q], ala, BH[0], BH[1]); \
    MMA4(acX[q], ahb, BH[0], BH[1]); MMA4(acX[q], ahb, BL[0], BL[1]); MMA4(acX[q], alb, BH[0], BH[1]); \
    MMA4(acM[q + 1], aha, BH[2], BH[3]); MMA4(acM[q + 1], aha, BL[2], BL[3]); MMA4(acM[q + 1], ala, BH[2], BH[3]); \
    MMA4(acX[q + 1], ahb, BH[2], BH[3]); MMA4(acX[q + 1], ahb, BL[2], BL[3]); MMA4(acX[q + 1], alb, BH[2], BH[3]);

__global__ __launch_bounds__(256, 2) void k_rel(
    const float* __restrict__ rel, const float* __restrict__ alive,
    const float* __restrict__ b1, const float* __restrict__ b2,
    const int* __restrict__ agp)
{
    extern __shared__ unsigned char smem[];
    __nv_bfloat16* XH = (__nv_bfloat16*)smem;
    __nv_bfloat16* XL = (__nv_bfloat16*)(smem + 9216);
    __nv_bfloat16* HTh = (__nv_bfloat16*)(smem + 18432);
    __nv_bfloat16* HTl = (__nv_bfloat16*)(smem + 36864);
    float* sal = (float*)(smem + 55296);

    const int tid = threadIdx.x, w = tid >> 5, l = tid & 31, g = l >> 2, t4 = l & 3;
    const int bi = blockIdx.x, b = bi >> 6, i = bi & 63;
    if (tid < 64) sal[tid] = alive[b * 64 + tid];

    const int sel = l >> 3, lr = l & 7;
    const uint32_t xrow = (uint32_t)(((lr + ((sel >> 1) << 3)) * XS + ((sel & 1) << 3)) * 2);
    const uint32_t hrow = (uint32_t)(((lr + ((sel & 1) << 3)) * HTS + ((sel >> 1) << 3)) * 2);
    const uint32_t xh_b = s2u(XH), xl_b = s2u(XL), hh_b = s2u(HTh), hl_b = s2u(HTl);

    // stage rel part of X, split bf16 hi/lo
    {
        const float4* rr4 = (const float4*)(rel + (size_t)bi * 4096);
        for (int idx = tid; idx < 1024; idx += 256) {
            const int j = idx >> 4, k4 = idx & 15;
            float4 v = rr4[idx];
            *(uint2*)(XH + j * XS + k4 * 4) = make_uint2(pkhi(v.x, v.y), pkhi(v.z, v.w));
            *(uint2*)(XL + j * XS + k4 * 4) = make_uint2(pklo(v.x, v.y), pklo(v.z, v.w));
        }
    }

    const int r0 = w * 16 + g;
    float2 csA[8], csB[8];
    {
        const float* pA = g_Cs + (size_t)b * 8192 + r0 * 64;
        const float* pB = pA + 8 * 64;
#pragma unroll
        for (int n = 0; n < 8; n++) {
            csA[n] = *(const float2*)(pA + n * 8 + 2 * t4);
            csB[n] = *(const float2*)(pB + n * 8 + 2 * t4);
        }
    }
    __syncthreads();

    float ac[8][4];
#pragma unroll
    for (int n = 0; n < 8; n++) { ac[n][0] = 0.f; ac[n][1] = 0.f; ac[n][2] = 0.f; ac[n][3] = 0.f; }

    // layer 1: K=64, 4 ksteps, batched LDSM
#pragma unroll
    for (int ks = 0; ks < 4; ks++) {
        const uint4 AH = g_w1fh[(w * 4 + ks) * 32 + l];
        const uint4 AL = g_w1fl[(w * 4 + ks) * 32 + l];
        const uint32_t ah[4] = {AH.x, AH.y, AH.z, AH.w};
        const uint32_t alr[4] = {AL.x, AL.y, AL.z, AL.w};
        const uint32_t kb = (uint32_t)(ks * 32);
        uint32_t bh0[4], bl0[4], bh1[4], bl1[4];
        LDSM4(bh0, xh_b + kb + xrow);
        LDSM4(bl0, xl_b + kb + xrow);
        LDSM4(bh1, xh_b + (uint32_t)(16 * XS * 2) + kb + xrow);
        LDSM4(bl1, xl_b + (uint32_t)(16 * XS * 2) + kb + xrow);
        DO6(0, bh0, bl0)
        DO6(2, bh1, bl1)
        LDSM4(bh0, xh_b + (uint32_t)(32 * XS * 2) + kb + xrow);
        LDSM4(bl0, xl_b + (uint32_t)(32 * XS * 2) + kb + xrow);
        LDSM4(bh1, xh_b + (uint32_t)(48 * XS * 2) + kb + xrow);
        LDSM4(bl1, xl_b + (uint32_t)(48 * XS * 2) + kb + xrow);
        DO6(4, bh0, bl0)
        DO6(6, bh1, bl1)
    }
    // epilogue 1: add Cs + b1, relu, store HID transposed [k][j]
    {
        const float bA = b1[r0], bB = b1[r0 + 8];
#pragma unroll
        for (int n = 0; n < 8; n++) {
            const int j0 = n * 8 + 2 * t4;
            float v0 = fmaxf(ac[n][0] + csA[n].x + bA, 0.f);
            float v1 = fmaxf(ac[n][1] + csA[n].y + bA, 0.f);
            float v2 = fmaxf(ac[n][2] + csB[n].x + bB, 0.f);
            float v3 = fmaxf(ac[n][3] + csB[n].y + bB, 0.f);
            *(uint32_t*)(HTh + r0 * HTS + j0) = pkhi(v0, v1);
            *(uint32_t*)(HTl + r0 * HTS + j0) = pklo(v0, v1);
            *(uint32_t*)(HTh + (r0 + 8) * HTS + j0) = pkhi(v2, v3);
            *(uint32_t*)(HTl + (r0 + 8) * HTS + j0) = pklo(v2, v3);
        }
    }
    __syncthreads();

    // layer 2: single pass, warp = 16 mean cols + 16 max cols, batched LDSM
    float acM[8][4], acX[8][4];
#pragma unroll
    for (int n = 0; n < 8; n++) {
        acM[n][0] = 0.f; acM[n][1] = 0.f; acM[n][2] = 0.f; acM[n][3] = 0.f;
        acX[n][0] = 0.f; acX[n][1] = 0.f; acX[n][2] = 0.f; acX[n][3] = 0.f;
    }
#pragma unroll 1
    for (int ks = 0; ks < 8; ks++) {
        const uint4 AHa = g_w2fh[(w * 8 + ks) * 32 + l];
        const uint4 ALa = g_w2fl[(w * 8 + ks) * 32 + l];
        const uint4 AHb = g_w2fh[((8 + w) * 8 + ks) * 32 + l];
        const uint4 ALb = g_w2fl[((8 + w) * 8 + ks) * 32 + l];
        const uint32_t aha[4] = {AHa.x, AHa.y, AHa.z, AHa.w};
        const uint32_t ala[4] = {ALa.x, ALa.y, ALa.z, ALa.w};
        const uint32_t ahb[4] = {AHb.x, AHb.y, AHb.z, AHb.w};
        const uint32_t alb[4] = {ALb.x, ALb.y, ALb.z, ALb.w};
        const uint32_t kb = (uint32_t)(ks * 16 * HTS * 2);
        uint32_t bh0[4], bl0[4], bh1[4], bl1[4];
        LDSM4T(bh0, hh_b + kb + hrow);
        LDSM4T(bl0, hl_b + kb + hrow);
        LDSM4T(bh1, hh_b + kb + 32 + hrow);
        LDSM4T(bl1, hl_b + kb + 32 + hrow);
        DO12(0, bh0, bl0)
        DO12(2, bh1, bl1)
        LDSM4T(bh0, hh_b + kb + 64 + hrow);
        LDSM4T(bl0, hl_b + kb + 64 + hrow);
        LDSM4T(bh1, hh_b + kb + 96 + hrow);
        LDSM4T(bl1, hl_b + kb + 96 + hrow);
        DO12(4, bh0, bl0)
        DO12(6, bh1, bl1)
    }
    // epilogue 2
    {
        const int rrA = w * 16 + g;
        const int rrB = 128 + w * 16 + g;
        const int gag = *agp;
        const bool isag = (i == gag);
        const float bMA = b2[rrA], bMB = b2[rrA + 8];
        const float bXA = b2[rrB], bXB = b2[rrB + 8];
        float s0 = 0.f, s1 = 0.f, t0 = 0.f, t1 = 0.f;
        float* rg = g_ragent + (size_t)(b * 64) * 256;
#pragma unroll
        for (int n = 0; n < 8; n++) {
            const int j0 = n * 8 + 2 * t4;
            const float al0 = sal[j0], al1 = sal[j0 + 1];
            float m0 = fmaxf(acM[n][0] + bMA, 0.f), m1 = fmaxf(acM[n][1] + bMA, 0.f);
            float m2 = fmaxf(acM[n][2] + bMB, 0.f), m3 = fmaxf(acM[n][3] + bMB, 0.f);
            float x0 = fmaxf(acX[n][0] + bXA, 0.f), x1 = fmaxf(acX[n][1] + bXA, 0.f);
            float x2 = fmaxf(acX[n][2] + bXB, 0.f), x3 = fmaxf(acX[n][3] + bXB, 0.f);
            if (isag) {
                rg[(size_t)j0 * 256 + rrA] = m0;
                rg[(size_t)(j0 + 1) * 256 + rrA] = m1;
                rg[(size_t)j0 * 256 + rrA + 8] = m2;
                rg[(size_t)(j0 + 1) * 256 + rrA + 8] = m3;
                rg[(size_t)j0 * 256 + rrB] = x0;
                rg[(size_t)(j0 + 1) * 256 + rrB] = x1;
                rg[(size_t)j0 * 256 + rrB + 8] = x2;
                rg[(size_t)(j0 + 1) * 256 + rrB + 8] = x3;
            }
            s0 += m0 * al0 + m1 * al1;
            s1 += m2 * al0 + m3 * al1;
            t0 = fmaxf(t0, fmaxf(x0 * al0, x1 * al1));
            t1 = fmaxf(t1, fmaxf(x2 * al0, x3 * al1));
        }
        s0 += __shfl_xor_sync(0xffffffffu, s0, 1); s0 += __shfl_xor_sync(0xffffffffu, s0, 2);
        s1 += __shfl_xor_sync(0xffffffffu, s1, 1); s1 += __shfl_xor_sync(0xffffffffu, s1, 2);
        t0 = fmaxf(t0, __shfl_xor_sync(0xffffffffu, t0, 1)); t0 = fmaxf(t0, __shfl_xor_sync(0xffffffffu, t0, 2));
        t1 = fmaxf(t1, __shfl_xor_sync(0xffffffffu, t1, 1)); t1 = fmaxf(t1, __shfl_xor_sync(0xffffffffu, t1, 2));
        if (t4 == 0) {
            g_pooled[(size_t)bi * 256 + rrA] = s0 * (1.f / 64.f);
            g_pooled[(size_t)bi * 256 + rrA + 8] = s1 * (1.f / 64.f);
            g_pooled[(size_t)bi * 256 + rrB] = t0;
            g_pooled[(size_t)bi * 256 + rrB + 8] = t1;
        }
    }
}

// ---------------- k_ra ----------------
__global__ __launch_bounds__(256) void k_ra(const float* __restrict__ w, const float* __restrict__ bias)
{
    __shared__ float X[4 * K3];
    __shared__ float RED[2 * 4 * H];
    const int row0 = blockIdx.x * 4, t = threadIdx.x;
    for (int i = t; i < 4 * H; i += 256) {
        int j = i >> 7, h2 = i & 127;
        X[j * K3 + h2] = g_s1[(size_t)(row0 + j) * H + h2];
    }
    for (int i = t; i < 4 * 2 * H; i += 256) {
        int j = i >> 8, h2 = i & 255;
        X[j * K3 + H + h2] = g_pooled[(size_t)(row0 + j) * (2 * H) + h2];
    }
    __syncthreads();
    const int h = t & 127, kh = t >> 7;
    float acc[4] = {0.f, 0.f, 0.f, 0.f};
    const float4* X4 = (const float4*)X;
    const int k0 = kh * 192;
#pragma unroll 4
    for (int k = k0; k < k0 + 192; k += 4) {
        float w0 = w[k * H + h], wA = w[(k + 1) * H + h], wB = w[(k + 2) * H + h], wC = w[(k + 3) * H + h];
#pragma unroll
        for (int j = 0; j < 4; j++) {
            float4 x = X4[j * (K3 / 4) + (k >> 2)];
            acc[j] = fmaf(x.x, w0, acc[j]); acc[j] = fmaf(x.y, wA, acc[j]);
            acc[j] = fmaf(x.z, wB, acc[j]); acc[j] = fmaf(x.w, wC, acc[j]);
        }
    }
#pragma unroll
    for (int j = 0; j < 4; j++) RED[(kh * 4 + j) * H + h] = acc[j];
    __syncthreads();
    for (int idx = t; idx < 4 * H; idx += 256)
        g_s2[(size_t)(row0 + (idx >> 7)) * H + (idx & 127)] =
            fmaxf(RED[idx] + RED[4 * H + idx] + bias[idx & 127], 0.f);
}

// ---------------- k_ae ----------------
__global__ __launch_bounds__(256) void k_ae(
    const float* __restrict__ w1, const float* __restrict__ b1,
    const float* __restrict__ w2, const float* __restrict__ b2,
    const int* __restrict__ agp)
{
    __shared__ float X[4 * K4];
    __shared__ float HD[4 * H];
    __shared__ float RED[2 * 4 * H];
    const int row0 = blockIdx.x * 4, b = row0 >> 6, t = threadIdx.x;
    const int g = *agp;
    for (int i = t; i < 4 * 2 * H; i += 256) {
        int j = i >> 8, h2 = i & 255;
        X[j * K4 + h2] = g_ragent[(size_t)(row0 + j) * (2 * H) + h2];
    }
    for (int i = t; i < 4 * H; i += 256) {
        int j = i >> 7, h2 = i & 127;
        X[j * K4 + 2 * H + h2] = g_s2[(size_t)(row0 + j) * H + h2];
        X[j * K4 + 3 * H + h2] = g_s2[((size_t)b * A + g) * H + h2];
    }
    __syncthreads();
    const int h = t & 127, kh = t >> 7;
    {
        float acc[4] = {0.f, 0.f, 0.f, 0.f};
        const float4* X4 = (const float4*)X;
        const int k0 = kh * 256;
#pragma unroll 4
        for (int k = k0; k < k0 + 256; k += 4) {
            float w0 = w1[k * H + h], wA = w1[(k + 1) * H + h], wB = w1[(k + 2) * H + h], wC = w1[(k + 3) * H + h];
#pragma unroll
            for (int j = 0; j < 4; j++) {
                float4 x = X4[j * (K4 / 4) + (k >> 2)];
                acc[j] = fmaf(x.x, w0, acc[j]); acc[j] = fmaf(x.y, wA, acc[j]);
                acc[j] = fmaf(x.z, wB, acc[j]); acc[j] = fmaf(x.w, wC, acc[j]);
            }
        }
#pragma unroll
        for (int j = 0; j < 4; j++) RED[(kh * 4 + j) * H + h] = acc[j];
    }
    __syncthreads();
    for (int idx = t; idx < 4 * H; idx += 256)
        HD[idx] = fmaxf(RED[idx] + RED[4 * H + idx] + b1[idx & 127], 0.f);
    __syncthreads();
    {
        const int c = t;
        float acc2[4];
        const float bb = b2[c];
#pragma unroll
        for (int j = 0; j < 4; j++) acc2[j] = bb;
        const float4* H4 = (const float4*)HD;
#pragma unroll 4
        for (int k = 0; k < H; k += 4) {
            float w0 = w2[k * 256 + c], wA = w2[(k + 1) * 256 + c], wB = w2[(k + 2) * 256 + c], wC = w2[(k + 3) * 256 + c];
#pragma unroll
            for (int j = 0; j < 4; j++) {
                float4 x = H4[j * (H / 4) + (k >> 2)];
                acc2[j] = fmaf(x.x, w0, acc2[j]); acc2[j] = fmaf(x.y, wA, acc2[j]);
                acc2[j] = fmaf(x.z, wB, acc2[j]); acc2[j] = fmaf(x.w, wC, acc2[j]);
            }
        }
#pragma unroll
        for (int j = 0; j < 4; j++)
            g_ae[(size_t)(row0 + j) * (2 * H) + c] = fmaxf(acc2[j], 0.f);
    }
}

// ---------------- k_final: block 256 ----------------
__global__ __launch_bounds__(256) void k_final(
    const float* __restrict__ action_embed, const int* __restrict__ action,
    const int* __restrict__ agp, float* __restrict__ out)
{
    const int b = blockIdx.x, t = threadIdx.x;
    const int h = t & 127, jp = t >> 7;
    const int a = action[b], g = *agp;
    const float sel = (a < E) ? action_embed[a * H + h]
                              : g_ae[((size_t)b * A + (a - E)) * (2 * H) + h];
    float* out_state = out;
    float* out_sel = out + (size_t)B * A * H;
    float* out_ps = out_sel + (size_t)B * H;
    if (jp == 0) out_sel[b * H + h] = sel;
    for (int j = jp; j < A; j += 2) {
        float st = g_s2[((size_t)b * A + j) * H + h];
        float ps = 0.f;
        if (a == E + j) ps = g_ae[((size_t)b * A + j) * (2 * H) + H + h];
        if (j == g) st += sel;
        out_ps[((size_t)b * A + j) * H + h] = ps;
        out_state[((size_t)b * A + j) * H + h] = st + ps;
    }
}

// ---------------- launcher ----------------
extern "C" void kernel_launch(void* const* d_in, const int* in_sizes, int n_in,
                              void* d_out, int out_size)
{
    const float* states       = (const float*)d_in[0];
    const float* relations    = (const float*)d_in[1];
    const float* alive_mask   = (const float*)d_in[2];
    const float* se_w1        = (const float*)d_in[3];
    const float* se_b1        = (const float*)d_in[4];
    const float* se_w2        = (const float*)d_in[5];
    const float* se_b2        = (const float*)d_in[6];
    const float* re_w1        = (const float*)d_in[7];
    const float* re_b1        = (const float*)d_in[8];
    const float* re_w2        = (const float*)d_in[9];
    const float* re_b2        = (const float*)d_in[10];
    const float* ra_w         = (const float*)d_in[11];
    const float* ra_b         = (const float*)d_in[12];
    const float* ae_w1        = (const float*)d_in[13];
    const float* ae_b1        = (const float*)d_in[14];
    const float* ae_w2        = (const float*)d_in[15];
    const float* ae_b2        = (const float*)d_in[16];
    const float* action_embed = (const float*)d_in[17];
    const int*   action       = (const int*)d_in[19];
    const int*   agent_id     = (const int*)d_in[20];
    float* out = (float*)d_out;

    static bool attr = false;
    if (!attr) {
        cudaFuncSetAttribute(k_rel, cudaFuncAttributeMaxDynamicSharedMemorySize, SM_REL);
        attr = true;
    }

    k_enc_prep<<<532, 256>>>(states, se_w1, se_b1, se_w2, se_b2, re_w1, re_w2);
    k_smm<<<128, 256>>>(re_w1);
    k_rel<<<B * A, 256, SM_REL>>>(relations, alive_mask, re_b1, re_b2, agent_id);
    k_ra<<<(B * A) / 4, 256>>>(ra_w, ra_b);
    k_ae<<<(B * A) / 4, 256>>>(ae_w1, ae_b1, ae_w2, ae_b2, agent_id);
    k_final<<<B, 256>>>(action_embed, action, agent_id, out);
}

// round 10
// speedup vs baseline: 3.8830x; 1.0002x over previous
#include <cuda_runtime.h>
#include <cuda_bf16.h>
#include <cstdint>

#define B 32
#define A 64
#define SLEN 256
#define H 128
#define RLEN 64
#define E 16
#define K3 (3 * H)
#define K4 (4 * H)

__device__ float g_s1[B * A * H];
__device__ float g_Cs[B * H * A];          // [b][c][j]
__device__ float g_pooled[B * A * 2 * H];
__device__ float g_ragent[B * A * 2 * H];
__device__ float g_s2[B * A * H];
__device__ float g_ae[B * A * 2 * H];
__device__ __align__(16) uint4 g_w1fh[8 * 4 * 32];
__device__ __align__(16) uint4 g_w1fl[8 * 4 * 32];
__device__ __align__(16) uint4 g_w2fh[16 * 8 * 32];
__device__ __align__(16) uint4 g_w2fl[16 * 8 * 32];

#define MMA4(d, a, b0, b1) asm volatile( \
    "mma.sync.aligned.m16n8k16.row.col.f32.bf16.bf16.f32 " \
    "{%0,%1,%2,%3},{%4,%5,%6,%7},{%8,%9},{%0,%1,%2,%3};" \
    : "+f"((d)[0]), "+f"((d)[1]), "+f"((d)[2]), "+f"((d)[3]) \
    : "r"((a)[0]), "r"((a)[1]), "r"((a)[2]), "r"((a)[3]), "r"(b0), "r"(b1))

#define LDSM4(r, a) asm volatile( \
    "ldmatrix.sync.aligned.m8n8.x4.shared.b16 {%0,%1,%2,%3}, [%4];" \
    : "=r"((r)[0]), "=r"((r)[1]), "=r"((r)[2]), "=r"((r)[3]) : "r"(a))
#define LDSM4T(r, a) asm volatile( \
    "ldmatrix.sync.aligned.m8n8.x4.trans.shared.b16 {%0,%1,%2,%3}, [%4];" \
    : "=r"((r)[0]), "=r"((r)[1]), "=r"((r)[2]), "=r"((r)[3]) : "r"(a))

__device__ __forceinline__ uint32_t s2u(const void* p) {
    uint32_t a;
    asm("{ .reg .u64 t; cvta.to.shared.u64 t, %1; cvt.u32.u64 %0, t; }" : "=r"(a) : "l"(p));
    return a;
}
__device__ __forceinline__ uint32_t pkhi(float a, float b) {
    __nv_bfloat162 t = __halves2bfloat162(__float2bfloat16(a), __float2bfloat16(b));
    return *reinterpret_cast<uint32_t*>(&t);
}
__device__ __forceinline__ uint32_t pklo(float a, float b) {
    float ra = a - __bfloat162float(__float2bfloat16(a));
    float rb = b - __bfloat162float(__float2bfloat16(b));
    __nv_bfloat162 t = __halves2bfloat162(__float2bfloat16(ra), __float2bfloat16(rb));
    return *reinterpret_cast<uint32_t*>(&t);
}

// ---------------- k_enc_prep: state encoder (blocks <512) + weight prep (>=512) ----------------
__global__ __launch_bounds__(256) void k_enc_prep(
    const float* __restrict__ st, const float* __restrict__ w1, const float* __restrict__ b1,
    const float* __restrict__ w2, const float* __restrict__ b2,
    const float* __restrict__ rw1, const float* __restrict__ rw2)
{
    __shared__ float X[4 * SLEN];
    __shared__ float HD[4 * H];
    __shared__ float RED[2 * 4 * H];
    const int t = threadIdx.x;

    if (blockIdx.x >= 512) {
        const int it = (blockIdx.x - 512) * 256 + t;
        if (it < 1024) {
            const int i = it, lane = i & 31, ks = (i >> 5) & 3, slot = i >> 7;
            const int r0 = slot * 16 + (lane >> 2), ka = ks * 16 + 2 * (lane & 3);
            float v00 = rw1[ka * 128 + r0],       v01 = rw1[(ka + 1) * 128 + r0];
            float v10 = rw1[ka * 128 + r0 + 8],   v11 = rw1[(ka + 1) * 128 + r0 + 8];
            float v20 = rw1[(ka + 8) * 128 + r0], v21 = rw1[(ka + 9) * 128 + r0];
            float v30 = rw1[(ka + 8) * 128 + r0 + 8], v31 = rw1[(ka + 9) * 128 + r0 + 8];
            g_w1fh[i] = make_uint4(pkhi(v00, v01), pkhi(v10, v11), pkhi(v20, v21), pkhi(v30, v31));
            g_w1fl[i] = make_uint4(pklo(v00, v01), pklo(v10, v11), pklo(v20, v21), pklo(v30, v31));
        } else {
            const int i = it - 1024, lane = i & 31, ks = (i >> 5) & 7, slot = i >> 8;
            const int rr = slot * 16 + (lane >> 2), ka = ks * 16 + 2 * (lane & 3);
            float v00 = rw2[ka * 256 + rr],       v01 = rw2[(ka + 1) * 256 + rr];
            float v10 = rw2[ka * 256 + rr + 8],   v11 = rw2[(ka + 1) * 256 + rr + 8];
            float v20 = rw2[(ka + 8) * 256 + rr], v21 = rw2[(ka + 9) * 256 + rr];
            float v30 = rw2[(ka + 8) * 256 + rr + 8], v31 = rw2[(ka + 9) * 256 + rr + 8];
            g_w2fh[i] = make_uint4(pkhi(v00, v01), pkhi(v10, v11), pkhi(v20, v21), pkhi(v30, v31));
            g_w2fl[i] = make_uint4(pklo(v00, v01), pklo(v10, v11), pklo(v20, v21), pklo(v30, v31));
        }
        return;
    }

    const int row0 = blockIdx.x * 4;
    for (int i = t; i < 4 * SLEN; i += 256) X[i] = st[(size_t)row0 * SLEN + i];
    __syncthreads();
    const int h = t & 127, kh = t >> 7;
    {
        float acc[4] = {0.f, 0.f, 0.f, 0.f};
        const float4* X4 = (const float4*)X;
        const int k0 = kh * 128;
#pragma unroll 4
        for (int k = k0; k < k0 + 128; k += 4) {
            float w0 = w1[k * H + h], wA = w1[(k + 1) * H + h], wB = w1[(k + 2) * H + h], wC = w1[(k + 3) * H + h];
#pragma unroll
            for (int j = 0; j < 4; j++) {
                float4 x = X4[j * (SLEN / 4) + (k >> 2)];
                acc[j] = fmaf(x.x, w0, acc[j]); acc[j] = fmaf(x.y, wA, acc[j]);
                acc[j] = fmaf(x.z, wB, acc[j]); acc[j] = fmaf(x.w, wC, acc[j]);
            }
        }
#pragma unroll
        for (int j = 0; j < 4; j++) RED[(kh * 4 + j) * H + h] = acc[j];
    }
    __syncthreads();
    for (int idx = t; idx < 4 * H; idx += 256)
        HD[idx] = fmaxf(RED[idx] + RED[4 * H + idx] + b1[idx & 127], 0.f);
    __syncthreads();
    {
        const int rb = kh * 2;
        float acc[2];
        const float bb = b2[h];
        acc[0] = bb; acc[1] = bb;
        const float4* H4 = (const float4*)HD;
#pragma unroll 4
        for (int k = 0; k < H; k += 4) {
            float w0 = w2[k * H + h], wA = w2[(k + 1) * H + h], wB = w2[(k + 2) * H + h], wC = w2[(k + 3) * H + h];
#pragma unroll
            for (int j = 0; j < 2; j++) {
                float4 x = H4[(rb + j) * (H / 4) + (k >> 2)];
                acc[j] = fmaf(x.x, w0, acc[j]); acc[j] = fmaf(x.y, wA, acc[j]);
                acc[j] = fmaf(x.z, wB, acc[j]); acc[j] = fmaf(x.w, wC, acc[j]);
            }
        }
#pragma unroll
        for (int j = 0; j < 2; j++) g_s1[(size_t)(row0 + rb + j) * H + h] = fmaxf(acc[j], 0.f);
    }
}

// ---------------- k_smm: grid 128 (4 j-chunks per b) ----------------
__global__ __launch_bounds__(256) void k_smm(const float* __restrict__ w1)
{
    __shared__ float S[16 * 128];
    const int b = blockIdx.x >> 2, j0 = (blockIdx.x & 3) * 16, t = threadIdx.x;
    for (int i = t; i < 16 * 128; i += 256)
        S[i] = g_s1[(size_t)b * 8192 + (size_t)j0 * 128 + i];
    __syncthreads();
    const int c = t & 127, jh = t >> 7;
    float acc[8];
#pragma unroll
    for (int j = 0; j < 8; j++) acc[j] = 0.f;
    const float4* S4 = (const float4*)S;
#pragma unroll 2
    for (int k4 = 0; k4 < 32; k4++) {
        const int k = 4 * k4;
        float w0 = w1[(64 + k) * 128 + c], wA = w1[(65 + k) * 128 + c];
        float wB = w1[(66 + k) * 128 + c], wC = w1[(67 + k) * 128 + c];
#pragma unroll
        for (int j = 0; j < 8; j++) {
            float4 s = S4[(jh * 8 + j) * 32 + k4];
            acc[j] = fmaf(s.x, w0, acc[j]); acc[j] = fmaf(s.y, wA, acc[j]);
            acc[j] = fmaf(s.z, wB, acc[j]); acc[j] = fmaf(s.w, wC, acc[j]);
        }
    }
#pragma unroll
    for (int j = 0; j < 8; j++)
        g_Cs[(size_t)b * 8192 + c * 64 + j0 + jh * 8 + j] = acc[j];
}

// ---------------- k_rel ----------------
#define XS 72
#define HTS 72
#define SM_REL 55552

#define DO6(q, BH, BL) \
    MMA4(ac[q], ah, BH[0], BH[1]); MMA4(ac[q], ah, BL[0], BL[1]); MMA4(ac[q], alr, BH[0], BH[1]); \
    MMA4(ac[q + 1], ah, BH[2], BH[3]); MMA4(ac[q + 1], ah, BL[2], BL[3]); MMA4(ac[q + 1], alr, BH[2], BH[3]);

#define DO12(q, BH, BL) \
    MMA4(acM[q], aha, BH[0], BH[1]); MMA4(acM[q], aha, BL[0], BL[1]); MMA4(acM[q], ala, BH[0], BH[1]); \
    MMA4(acX[q], ahb, BH[0], BH[1]); MMA4(acX[q], ahb, BL[0], BL[1]); MMA4(acX[q], alb, BH[0], BH[1]); \
    MMA4(acM[q + 1], aha, BH[2], BH[3]); MMA4(acM[q + 1], aha, BL[2], BL[3]); MMA4(acM[q + 1], ala, BH[2], BH[3]); \
    MMA4(acX[q + 1], ahb, BH[2], BH[3]); MMA4(acX[q + 1], ahb, BL[2], BL[3]); MMA4(acX[q + 1], alb, BH[2], BH[3]);

__global__ __launch_bounds__(256, 2) void k_rel(
    const float* __restrict__ rel, const float* __restrict__ alive,
    const float* __restrict__ b1, const float* __restrict__ b2,
    const int* __restrict__ agp)
{
    extern __shared__ unsigned char smem[];
    __nv_bfloat16* XH = (__nv_bfloat16*)smem;
    __nv_bfloat16* XL = (__nv_bfloat16*)(smem + 9216);
    __nv_bfloat16* HTh = (__nv_bfloat16*)(smem + 18432);
    __nv_bfloat16* HTl = (__nv_bfloat16*)(smem + 36864);
    float* sal = (float*)(smem + 55296);

    const int tid = threadIdx.x, w = tid >> 5, l = tid & 31, g = l >> 2, t4 = l & 3;
    const int bi = blockIdx.x, b = bi >> 6, i = bi & 63;
    if (tid < 64) sal[tid] = alive[b * 64 + tid];

    const int sel = l >> 3, lr = l & 7;
    const uint32_t xrow = (uint32_t)(((lr + ((sel >> 1) << 3)) * XS + ((sel & 1) << 3)) * 2);
    const uint32_t hrow = (uint32_t)(((lr + ((sel & 1) << 3)) * HTS + ((sel >> 1) << 3)) * 2);
    const uint32_t xh_b = s2u(XH), xl_b = s2u(XL), hh_b = s2u(HTh), hl_b = s2u(HTl);

    {
        const float4* rr4 = (const float4*)(rel + (size_t)bi * 4096);
        for (int idx = tid; idx < 1024; idx += 256) {
            const int j = idx >> 4, k4 = idx & 15;
            float4 v = rr4[idx];
            *(uint2*)(XH + j * XS + k4 * 4) = make_uint2(pkhi(v.x, v.y), pkhi(v.z, v.w));
            *(uint2*)(XL + j * XS + k4 * 4) = make_uint2(pklo(v.x, v.y), pklo(v.z, v.w));
        }
    }

    const int r0 = w * 16 + g;
    float2 csA[8], csB[8];
    {
        const float* pA = g_Cs + (size_t)b * 8192 + r0 * 64;
        const float* pB = pA + 8 * 64;
#pragma unroll
        for (int n = 0; n < 8; n++) {
            csA[n] = *(const float2*)(pA + n * 8 + 2 * t4);
            csB[n] = *(const float2*)(pB + n * 8 + 2 * t4);
        }
    }
    __syncthreads();

    float ac[8][4];
#pragma unroll
    for (int n = 0; n < 8; n++) { ac[n][0] = 0.f; ac[n][1] = 0.f; ac[n][2] = 0.f; ac[n][3] = 0.f; }

    // layer 1: K=64, 4 ksteps
#pragma unroll
    for (int ks = 0; ks < 4; ks++) {
        const uint4 AH = g_w1fh[(w * 4 + ks) * 32 + l];
        const uint4 AL = g_w1fl[(w * 4 + ks) * 32 + l];
        const uint32_t ah[4] = {AH.x, AH.y, AH.z, AH.w};
        const uint32_t alr[4] = {AL.x, AL.y, AL.z, AL.w};
        const uint32_t kb = (uint32_t)(ks * 32);
        uint32_t bh0[4], bl0[4], bh1[4], bl1[4];
        LDSM4(bh0, xh_b + kb + xrow);
        LDSM4(bl0, xl_b + kb + xrow);
        LDSM4(bh1, xh_b + (uint32_t)(16 * XS * 2) + kb + xrow);
        LDSM4(bl1, xl_b + (uint32_t)(16 * XS * 2) + kb + xrow);
        DO6(0, bh0, bl0)
        DO6(2, bh1, bl1)
        LDSM4(bh0, xh_b + (uint32_t)(32 * XS * 2) + kb + xrow);
        LDSM4(bl0, xl_b + (uint32_t)(32 * XS * 2) + kb + xrow);
        LDSM4(bh1, xh_b + (uint32_t)(48 * XS * 2) + kb + xrow);
        LDSM4(bl1, xl_b + (uint32_t)(48 * XS * 2) + kb + xrow);
        DO6(4, bh0, bl0)
        DO6(6, bh1, bl1)
    }
    {
        const float bA = b1[r0], bB = b1[r0 + 8];
#pragma unroll
        for (int n = 0; n < 8; n++) {
            const int j0 = n * 8 + 2 * t4;
            float v0 = fmaxf(ac[n][0] + csA[n].x + bA, 0.f);
            float v1 = fmaxf(ac[n][1] + csA[n].y + bA, 0.f);
            float v2 = fmaxf(ac[n][2] + csB[n].x + bB, 0.f);
            float v3 = fmaxf(ac[n][3] + csB[n].y + bB, 0.f);
            *(uint32_t*)(HTh + r0 * HTS + j0) = pkhi(v0, v1);
            *(uint32_t*)(HTl + r0 * HTS + j0) = pklo(v0, v1);
            *(uint32_t*)(HTh + (r0 + 8) * HTS + j0) = pkhi(v2, v3);
            *(uint32_t*)(HTl + (r0 + 8) * HTS + j0) = pklo(v2, v3);
        }
    }
    __syncthreads();

    float acM[8][4], acX[8][4];
#pragma unroll
    for (int n = 0; n < 8; n++) {
        acM[n][0] = 0.f; acM[n][1] = 0.f; acM[n][2] = 0.f; acM[n][3] = 0.f;
        acX[n][0] = 0.f; acX[n][1] = 0.f; acX[n][2] = 0.f; acX[n][3] = 0.f;
    }
#pragma unroll 1
    for (int ks = 0; ks < 8; ks++) {
        const uint4 AHa = g_w2fh[(w * 8 + ks) * 32 + l];
        const uint4 ALa = g_w2fl[(w * 8 + ks) * 32 + l];
        const uint4 AHb = g_w2fh[((8 + w) * 8 + ks) * 32 + l];
        const uint4 ALb = g_w2fl[((8 + w) * 8 + ks) * 32 + l];
        const uint32_t aha[4] = {AHa.x, AHa.y, AHa.z, AHa.w};
        const uint32_t ala[4] = {ALa.x, ALa.y, ALa.z, ALa.w};
        const uint32_t ahb[4] = {AHb.x, AHb.y, AHb.z, AHb.w};
        const uint32_t alb[4] = {ALb.x, ALb.y, ALb.z, ALb.w};
        const uint32_t kb = (uint32_t)(ks * 16 * HTS * 2);
        uint32_t bh0[4], bl0[4], bh1[4], bl1[4];
        LDSM4T(bh0, hh_b + kb + hrow);
        LDSM4T(bl0, hl_b + kb + hrow);
        LDSM4T(bh1, hh_b + kb + 32 + hrow);
        LDSM4T(bl1, hl_b + kb + 32 + hrow);
        DO12(0, bh0, bl0)
        DO12(2, bh1, bl1)
        LDSM4T(bh0, hh_b + kb + 64 + hrow);
        LDSM4T(bl0, hl_b + kb + 64 + hrow);
        LDSM4T(bh1, hh_b + kb + 96 + hrow);
        LDSM4T(bl1, hl_b + kb + 96 + hrow);
        DO12(4, bh0, bl0)
        DO12(6, bh1, bl1)
    }
    {
        const int rrA = w * 16 + g;
        const int rrB = 128 + w * 16 + g;
        const int gag = *agp;
        const bool isag = (i == gag);
        const float bMA = b2[rrA], bMB = b2[rrA + 8];
        const float bXA = b2[rrB], bXB = b2[rrB + 8];
        float s0 = 0.f, s1 = 0.f, t0 = 0.f, t1 = 0.f;
        float* rg = g_ragent + (size_t)(b * 64) * 256;
#pragma unroll
        for (int n = 0; n < 8; n++) {
            const int j0 = n * 8 + 2 * t4;
            const float al0 = sal[j0], al1 = sal[j0 + 1];
            float m0 = fmaxf(acM[n][0] + bMA, 0.f), m1 = fmaxf(acM[n][1] + bMA, 0.f);
            float m2 = fmaxf(acM[n][2] + bMB, 0.f), m3 = fmaxf(acM[n][3] + bMB, 0.f);
            float x0 = fmaxf(acX[n][0] + bXA, 0.f), x1 = fmaxf(acX[n][1] + bXA, 0.f);
            float x2 = fmaxf(acX[n][2] + bXB, 0.f), x3 = fmaxf(acX[n][3] + bXB, 0.f);
            if (isag) {
                rg[(size_t)j0 * 256 + rrA] = m0;
                rg[(size_t)(j0 + 1) * 256 + rrA] = m1;
                rg[(size_t)j0 * 256 + rrA + 8] = m2;
                rg[(size_t)(j0 + 1) * 256 + rrA + 8] = m3;
                rg[(size_t)j0 * 256 + rrB] = x0;
                rg[(size_t)(j0 + 1) * 256 + rrB] = x1;
                rg[(size_t)j0 * 256 + rrB + 8] = x2;
                rg[(size_t)(j0 + 1) * 256 + rrB + 8] = x3;
            }
            s0 += m0 * al0 + m1 * al1;
            s1 += m2 * al0 + m3 * al1;
            t0 = fmaxf(t0, fmaxf(x0 * al0, x1 * al1));
            t1 = fmaxf(t1, fmaxf(x2 * al0, x3 * al1));
        }
        s0 += __shfl_xor_sync(0xffffffffu, s0, 1); s0 += __shfl_xor_sync(0xffffffffu, s0, 2);
        s1 += __shfl_xor_sync(0xffffffffu, s1, 1); s1 += __shfl_xor_sync(0xffffffffu, s1, 2);
        t0 = fmaxf(t0, __shfl_xor_sync(0xffffffffu, t0, 1)); t0 = fmaxf(t0, __shfl_xor_sync(0xffffffffu, t0, 2));
        t1 = fmaxf(t1, __shfl_xor_sync(0xffffffffu, t1, 1)); t1 = fmaxf(t1, __shfl_xor_sync(0xffffffffu, t1, 2));
        if (t4 == 0) {
            g_pooled[(size_t)bi * 256 + rrA] = s0 * (1.f / 64.f);
            g_pooled[(size_t)bi * 256 + rrA + 8] = s1 * (1.f / 64.f);
            g_pooled[(size_t)bi * 256 + rrB] = t0;
            g_pooled[(size_t)bi * 256 + rrB + 8] = t1;
        }
    }
}

// ---------------- k_ra_ae: fused ra + ae (agent s2 row recomputed per block) ----------------
__global__ __launch_bounds__(256) void k_ra_ae(
    const float* __restrict__ raw, const float* __restrict__ rab,
    const float* __restrict__ w1, const float* __restrict__ b1,
    const float* __restrict__ w2, const float* __restrict__ b2,
    const int* __restrict__ agp)
{
    __shared__ float X[5 * K3];     // rows 0..3 = block rows, row 4 = agent
    __shared__ float RED[2 * 5 * H];
    __shared__ float S2[5 * H];
    __shared__ float XA[4 * K4];
    __shared__ float HD[4 * H];
    const int row0 = blockIdx.x * 4, b = row0 >> 6, t = threadIdx.x;
    const int g = *agp;
    const int agrow = b * A + g;

    // ---- stage [s1 | pooled] for 4 rows + agent row ----
    for (int i = t; i < 4 * H; i += 256) {
        int j = i >> 7, h2 = i & 127;
        X[j * K3 + h2] = g_s1[(size_t)(row0 + j) * H + h2];
    }
    for (int i = t; i < 4 * 2 * H; i += 256) {
        int j = i >> 8, h2 = i & 255;
        X[j * K3 + H + h2] = g_pooled[(size_t)(row0 + j) * (2 * H) + h2];
    }
    if (t < H) X[4 * K3 + t] = g_s1[(size_t)agrow * H + t];
    for (int i = t; i < 2 * H; i += 256)
        X[4 * K3 + H + i] = g_pooled[(size_t)agrow * (2 * H) + i];
    __syncthreads();

    const int h = t & 127, kh = t >> 7;

    // ---- ra layer (s2) for 5 rows, split-K 192 ----
    {
        float acc[5] = {0.f, 0.f, 0.f, 0.f, 0.f};
        const float4* X4 = (const float4*)X;
        const int k0 = kh * 192;
#pragma unroll 4
        for (int k = k0; k < k0 + 192; k += 4) {
            float w0 = raw[k * H + h], wA = raw[(k + 1) * H + h], wB = raw[(k + 2) * H + h], wC = raw[(k + 3) * H + h];
#pragma unroll
            for (int j = 0; j < 5; j++) {
                float4 x = X4[j * (K3 / 4) + (k >> 2)];
                acc[j] = fmaf(x.x, w0, acc[j]); acc[j] = fmaf(x.y, wA, acc[j]);
                acc[j] = fmaf(x.z, wB, acc[j]); acc[j] = fmaf(x.w, wC, acc[j]);
            }
        }
#pragma unroll
        for (int j = 0; j < 5; j++) RED[(kh * 5 + j) * H + h] = acc[j];
    }
    __syncthreads();
    for (int idx = t; idx < 5 * H; idx += 256) {
        const int j = idx >> 7;
        float v = fmaxf(RED[idx] + RED[5 * H + idx] + rab[idx & 127], 0.f);
        S2[idx] = v;
        if (j < 4) g_s2[(size_t)(row0 + j) * H + (idx & 127)] = v;
    }
    __syncthreads();

    // ---- build ae input: [ragent(256) | s2_row(128) | s2_agent(128)] ----
    for (int i = t; i < 4 * 2 * H; i += 256) {
        int j = i >> 8, h2 = i & 255;
        XA[j * K4 + h2] = g_ragent[(size_t)(row0 + j) * (2 * H) + h2];
    }
    for (int i = t; i < 4 * H; i += 256) {
        int j = i >> 7, h2 = i & 127;
        XA[j * K4 + 2 * H + h2] = S2[j * H + h2];
        XA[j * K4 + 3 * H + h2] = S2[4 * H + h2];
    }
    __syncthreads();

    // ---- ae layer 1, split-K 512 ----
    {
        float acc[4] = {0.f, 0.f, 0.f, 0.f};
        const float4* X4 = (const float4*)XA;
        const int k0 = kh * 256;
#pragma unroll 4
        for (int k = k0; k < k0 + 256; k += 4) {
            float w0 = w1[k * H + h], wA = w1[(k + 1) * H + h], wB = w1[(k + 2) * H + h], wC = w1[(k + 3) * H + h];
#pragma unroll
            for (int j = 0; j < 4; j++) {
                float4 x = X4[j * (K4 / 4) + (k >> 2)];
                acc[j] = fmaf(x.x, w0, acc[j]); acc[j] = fmaf(x.y, wA, acc[j]);
                acc[j] = fmaf(x.z, wB, acc[j]); acc[j] = fmaf(x.w, wC, acc[j]);
            }
        }
#pragma unroll
        for (int j = 0; j < 4; j++) RED[(kh * 4 + j) * H + h] = acc[j];
    }
    __syncthreads();
    for (int idx = t; idx < 4 * H; idx += 256)
        HD[idx] = fmaxf(RED[idx] + RED[4 * H + idx] + b1[idx & 127], 0.f);
    __syncthreads();

    // ---- ae layer 2 ----
    {
        const int c = t;
        float acc2[4];
        const float bb = b2[c];
#pragma unroll
        for (int j = 0; j < 4; j++) acc2[j] = bb;
        const float4* H4 = (const float4*)HD;
#pragma unroll 4
        for (int k = 0; k < H; k += 4) {
            float w0 = w2[k * 256 + c], wA = w2[(k + 1) * 256 + c], wB = w2[(k + 2) * 256 + c], wC = w2[(k + 3) * 256 + c];
#pragma unroll
            for (int j = 0; j < 4; j++) {
                float4 x = H4[j * (H / 4) + (k >> 2)];
                acc2[j] = fmaf(x.x, w0, acc2[j]); acc2[j] = fmaf(x.y, wA, acc2[j]);
                acc2[j] = fmaf(x.z, wB, acc2[j]); acc2[j] = fmaf(x.w, wC, acc2[j]);
            }
        }
#pragma unroll
        for (int j = 0; j < 4; j++)
            g_ae[(size_t)(row0 + j) * (2 * H) + c] = fmaxf(acc2[j], 0.f);
    }
}

// ---------------- k_final ----------------
__global__ __launch_bounds__(256) void k_final(
    const float* __restrict__ action_embed, const int* __restrict__ action,
    const int* __restrict__ agp, float* __restrict__ out)
{
    const int b = blockIdx.x, t = threadIdx.x;
    const int h = t & 127, jp = t >> 7;
    const int a = action[b], g = *agp;
    const float sel = (a < E) ? action_embed[a * H + h]
                              : g_ae[((size_t)b * A + (a - E)) * (2 * H) + h];
    float* out_state = out;
    float* out_sel = out + (size_t)B * A * H;
    float* out_ps = out_sel + (size_t)B * H;
    if (jp == 0) out_sel[b * H + h] = sel;
    for (int j = jp; j < A; j += 2) {
        float st = g_s2[((size_t)b * A + j) * H + h];
        float ps = 0.f;
        if (a == E + j) ps = g_ae[((size_t)b * A + j) * (2 * H) + H + h];
        if (j == g) st += sel;
        out_ps[((size_t)b * A + j) * H + h] = ps;
        out_state[((size_t)b * A + j) * H + h] = st + ps;
    }
}

// ---------------- launcher ----------------
extern "C" void kernel_launch(void* const* d_in, const int* in_sizes, int n_in,
                              void* d_out, int out_size)
{
    const float* states       = (const float*)d_in[0];
    const float* relations    = (const float*)d_in[1];
    const float* alive_mask   = (const float*)d_in[2];
    const float* se_w1        = (const float*)d_in[3];
    const float* se_b1        = (const float*)d_in[4];
    const float* se_w2        = (const float*)d_in[5];
    const float* se_b2        = (const float*)d_in[6];
    const float* re_w1        = (const float*)d_in[7];
    const float* re_b1        = (const float*)d_in[8];
    const float* re_w2        = (const float*)d_in[9];
    const float* re_b2        = (const float*)d_in[10];
    const float* ra_w         = (const float*)d_in[11];
    const float* ra_b         = (const float*)d_in[12];
    const float* ae_w1        = (const float*)d_in[13];
    const float* ae_b1        = (const float*)d_in[14];
    const float* ae_w2        = (const float*)d_in[15];
    const float* ae_b2        = (const float*)d_in[16];
    const float* action_embed = (const float*)d_in[17];
    const int*   action       = (const int*)d_in[19];
    const int*   agent_id     = (const int*)d_in[20];
    float* out = (float*)d_out;

    static bool attr = false;
    if (!attr) {
        cudaFuncSetAttribute(k_rel, cudaFuncAttributeMaxDynamicSharedMemorySize, SM_REL);
        attr = true;
    }

    k_enc_prep<<<532, 256>>>(states, se_w1, se_b1, se_w2, se_b2, re_w1, re_w2);
    k_smm<<<128, 256>>>(re_w1);
    k_rel<<<B * A, 256, SM_REL>>>(relations, alive_mask, re_b1, re_b2, agent_id);
    k_ra_ae<<<(B * A) / 4, 256>>>(ra_w, ra_b, ae_w1, ae_b1, ae_w2, ae_b2, agent_id);
    k_final<<<B, 256>>>(action_embed, action, agent_id, out);
}